// round 10
// baseline (speedup 1.0000x reference)
#include <cuda_runtime.h>
#include <cuda_bf16.h>
#include <cuda_fp16.h>
#include <cstdint>

// Problem constants
#define B_ 2
#define S_ 2048
#define D_ 768
#define H_ 12
#define DH_ 64
#define L_ 2
#define DFF_ 3072
#define MROWS (B_ * S_)   // 4096
#define NQKV 2304
#define KSPLIT 3

// ---------------------------------------------------------------------------
// Scratch (static device globals — no allocation allowed)
// ---------------------------------------------------------------------------
__device__ float g_x  [MROWS * D_];
__device__ float g_tmp[KSPLIT * MROWS * D_];   // split-K partials
__device__ float g_bqkv[NQKV];
__device__ __half g_xf [MROWS * D_];
__device__ __half g_of [MROWS * D_];
__device__ __half g_fff[MROWS * DFF_];   // also holds packed QKV (M x 2304)
__device__ __half g_wf [DFF_ * D_];

// ---------------------------------------------------------------------------
// Baseline-PTX tensor-core helpers
// ---------------------------------------------------------------------------
__device__ __forceinline__ uint32_t smem_u32(const void* p) {
    uint32_t a;
    asm("{ .reg .u64 t; cvta.to.shared.u64 t, %1; cvt.u32.u64 %0, t; }"
        : "=r"(a) : "l"(p));
    return a;
}
__device__ __forceinline__ void ldsm_x4(uint32_t& r0, uint32_t& r1,
                                        uint32_t& r2, uint32_t& r3, uint32_t a) {
    asm volatile("ldmatrix.sync.aligned.m8n8.x4.shared.b16 {%0,%1,%2,%3}, [%4];"
                 : "=r"(r0), "=r"(r1), "=r"(r2), "=r"(r3) : "r"(a));
}
__device__ __forceinline__ void ldsm_x2(uint32_t& r0, uint32_t& r1, uint32_t a) {
    asm volatile("ldmatrix.sync.aligned.m8n8.x2.shared.b16 {%0,%1}, [%2];"
                 : "=r"(r0), "=r"(r1) : "r"(a));
}
__device__ __forceinline__ void ldsm_x2t(uint32_t& r0, uint32_t& r1, uint32_t a) {
    asm volatile("ldmatrix.sync.aligned.m8n8.x2.trans.shared.b16 {%0,%1}, [%2];"
                 : "=r"(r0), "=r"(r1) : "r"(a));
}
__device__ __forceinline__ void mma_f16(float* d, const uint32_t* a, const uint32_t* b) {
    asm volatile(
        "mma.sync.aligned.m16n8k16.row.col.f32.f16.f16.f32 "
        "{%0,%1,%2,%3}, {%4,%5,%6,%7}, {%8,%9}, {%0,%1,%2,%3};"
        : "+f"(d[0]), "+f"(d[1]), "+f"(d[2]), "+f"(d[3])
        : "r"(a[0]), "r"(a[1]), "r"(a[2]), "r"(a[3]), "r"(b[0]), "r"(b[1]));
}
#define CP16(dst, src) \
    asm volatile("cp.async.cg.shared.global [%0], [%1], 16;" :: "r"(dst), "l"(src))
#define CP_COMMIT() asm volatile("cp.async.commit_group;" ::: "memory")
#define CP_WAIT0()  asm volatile("cp.async.wait_group 0;" ::: "memory")
#define CP_WAIT1()  asm volatile("cp.async.wait_group 1;" ::: "memory")

__device__ __forceinline__ uint32_t packh(float a, float b) {
    __half2 t = __floats2half2_rn(a, b);
    return *(uint32_t*)&t;
}

// ---------------------------------------------------------------------------
// Convert fp32 -> fp16 (single source)
// ---------------------------------------------------------------------------
__global__ __launch_bounds__(256) void cvt_kernel(
    const float* __restrict__ in, __half* __restrict__ out, int n4)
{
    int i = blockIdx.x * blockDim.x + threadIdx.x;
    if (i >= n4) return;
    float4 x = ((const float4*)in)[i];
    __half2* op = (__half2*)out;
    op[2 * i + 0] = __floats2half2_rn(x.x, x.y);
    op[2 * i + 1] = __floats2half2_rn(x.z, x.w);
}

// Convert 3 equal-size fp32 sources into one contiguous fp16 buffer
__global__ __launch_bounds__(256) void cvt3_kernel(
    const float* __restrict__ a, const float* __restrict__ b,
    const float* __restrict__ c, __half* __restrict__ out)
{
    const int R = (D_ * D_) >> 2;
    int i = blockIdx.x * blockDim.x + threadIdx.x;
    if (i >= 3 * R) return;
    const float* src; int j;
    if (i < R)          { src = a; j = i; }
    else if (i < 2 * R) { src = b; j = i - R; }
    else                { src = c; j = i - 2 * R; }
    float4 x = ((const float4*)src)[j];
    __half2* op = (__half2*)out;
    op[2 * i + 0] = __floats2half2_rn(x.x, x.y);
    op[2 * i + 1] = __floats2half2_rn(x.z, x.w);
}

// Pack [qb; kb; vb] into one 2304-float bias vector
__global__ __launch_bounds__(256) void pack_bias_kernel(
    const float* __restrict__ qb, const float* __restrict__ kb,
    const float* __restrict__ vb, float* __restrict__ out)
{
    int i = blockIdx.x * blockDim.x + threadIdx.x;
    if (i >= NQKV) return;
    float v;
    if (i < D_)          v = qb[i];
    else if (i < 2 * D_) v = kb[i - D_];
    else                 v = vb[i - 2 * D_];
    out[i] = v;
}

// ---------------------------------------------------------------------------
// fp16 mma.sync GEMM: C = A[M,Kfull] @ W[N,Kfull]^T (+bias)
// 256x128 CTA tile, BK=64, 8 warps (4x2), warp tile 64x64.
// 2-stage cp.async pipeline, 1 barrier per chunk. 1 CTA/SM.
// Split-K via blockIdx.z.
// EPI: 1 = fp16 out (+bias, x0.125 for n<768); 2 = relu + fp16 out (+bias);
//      3 = raw fp32 partial (no bias), at C + z*M*N
// ---------------------------------------------------------------------------
#define RS_B 144               // smem row stride bytes (64 halves = 128B + 16 pad)
#define ATILE_B (256 * RS_B)   // 36864
#define BTILE_B (128 * RS_B)   // 18432
#define STAGE_B (ATILE_B + BTILE_B)  // 55296
#define GEMM_SMEM (2 * STAGE_B)      // 110592

template <int EPI>
__global__ __launch_bounds__(256, 1) void gemm_mma_kernel(
    const __half* __restrict__ A, const __half* __restrict__ W,
    const float* __restrict__ bias, float* __restrict__ C,
    __half* __restrict__ Hf, int M, int N, int K, int klen)
{
    extern __shared__ char smem[];
    const uint32_t sb = smem_u32(smem);

    const int tid = threadIdx.x;
    const int wid = tid >> 5;
    const int lane = tid & 31;
    const int warp_m = wid >> 1;   // 0..3
    const int warp_n = wid & 1;    // 0..1
    const int bm = blockIdx.y * 256;
    const int bn = blockIdx.x * 128;
    const int kstart = blockIdx.z * klen;

    float acc[4][8][4];
#pragma unroll
    for (int mi = 0; mi < 4; mi++)
#pragma unroll
        for (int ni = 0; ni < 8; ni++)
#pragma unroll
            for (int r = 0; r < 4; r++) acc[mi][ni][r] = 0.f;

    auto load_chunk = [&](int kc, int stage) {
        const uint32_t base = sb + stage * STAGE_B;
#pragma unroll
        for (int t = 0; t < 8; t++) {
            const int idx = tid + t * 256;
            const int lr = idx >> 3, ls = idx & 7;
            CP16(base + lr * RS_B + ls * 16,
                 A + (size_t)(bm + lr) * K + kstart + kc + ls * 8);
        }
#pragma unroll
        for (int t = 0; t < 4; t++) {
            const int idx = tid + t * 256;
            const int lr = idx >> 3, ls = idx & 7;
            CP16(base + ATILE_B + lr * RS_B + ls * 16,
                 W + (size_t)(bn + lr) * K + kstart + kc + ls * 8);
        }
    };

    const int arow = warp_m * 64 + (lane & 15);
    const int akb  = (lane >> 4) * 8;
    const int bg_ni = (lane >> 4);
    const int bg_kh = ((lane >> 3) & 1) * 8;
    const int brow_l = lane & 7;

    auto compute = [&](int stage) {
        const uint32_t base = sb + stage * STAGE_B;
        const uint32_t pA = base;
        const uint32_t pB = base + ATILE_B;
#pragma unroll
        for (int ks = 0; ks < 4; ks++) {
            const int k0 = ks * 16;
            uint32_t af[4][4], bf[8][2];
#pragma unroll
            for (int mi = 0; mi < 4; mi++) {
                const uint32_t ro = (uint32_t)(arow + mi * 16) * RS_B + (k0 + akb) * 2;
                ldsm_x4(af[mi][0], af[mi][1], af[mi][2], af[mi][3], pA + ro);
            }
#pragma unroll
            for (int np = 0; np < 4; np++) {    // ni pairs {0,1},{2,3},{4,5},{6,7}
                const int nrow = warp_n * 64 + (np * 2 + bg_ni) * 8 + brow_l;
                const uint32_t ro = (uint32_t)nrow * RS_B + (k0 + bg_kh) * 2;
                ldsm_x4(bf[np * 2][0], bf[np * 2][1], bf[np * 2 + 1][0], bf[np * 2 + 1][1], pB + ro);
            }
#pragma unroll
            for (int mi = 0; mi < 4; mi++)
#pragma unroll
                for (int ni = 0; ni < 8; ni++)
                    mma_f16(acc[mi][ni], af[mi], bf[ni]);
        }
    };

    const int nchunks = klen >> 6;
    load_chunk(0, 0);
    CP_COMMIT();

    for (int c = 0; c < nchunks; c++) {
        CP_WAIT0();
        __syncthreads();
        if (c + 1 < nchunks) {
            load_chunk((c + 1) << 6, (c + 1) & 1);
            CP_COMMIT();
        }
        compute(c & 1);
    }

    // epilogue
    float* Cz = (EPI == 3) ? (C + (size_t)blockIdx.z * M * N) : C;
#pragma unroll
    for (int mi = 0; mi < 4; mi++) {
        const int m0 = bm + warp_m * 64 + mi * 16 + (lane >> 2);
#pragma unroll
        for (int ni = 0; ni < 8; ni++) {
            const int n0 = bn + warp_n * 64 + ni * 8 + (lane & 3) * 2;
            float v00 = acc[mi][ni][0], v01 = acc[mi][ni][1];
            float v10 = acc[mi][ni][2], v11 = acc[mi][ni][3];
            if (EPI != 3) {
                const float bx = bias[n0], by = bias[n0 + 1];
                v00 += bx; v01 += by; v10 += bx; v11 += by;
            }
            if (EPI == 1) {
                const float sc = (n0 < 768) ? 0.125f : 1.0f;  // Q pre-scale (exact 2^-3)
                v00 *= sc; v01 *= sc; v10 *= sc; v11 *= sc;
            }
            if (EPI == 2) {
                v00 = fmaxf(v00, 0.f); v01 = fmaxf(v01, 0.f);
                v10 = fmaxf(v10, 0.f); v11 = fmaxf(v11, 0.f);
            }
            if (EPI == 3) {
                *(float2*)(Cz + (size_t)m0 * N + n0) = make_float2(v00, v01);
                *(float2*)(Cz + (size_t)(m0 + 8) * N + n0) = make_float2(v10, v11);
            } else {
                *(uint32_t*)(Hf + (size_t)m0 * N + n0) = packh(v00, v01);
                *(uint32_t*)(Hf + (size_t)(m0 + 8) * N + n0) = packh(v10, v11);
            }
        }
    }
}

// ---------------------------------------------------------------------------
// Tensor-core banded flash attention, fp16, band-aware MMA skipping.
// ---------------------------------------------------------------------------
#define ATT_RSB 144
#define ATT_TILE_B (128 * ATT_RSB)        // 18432
#define ATT_SMEM (5 * ATT_TILE_B)         // Q + 2 stages x (K,V) = 92160

__global__ __launch_bounds__(256) void attn_mma_kernel(
    const __half* __restrict__ Qf, const __half* __restrict__ Kf,
    const __half* __restrict__ Vf, int ldq, __half* __restrict__ Of)
{
    extern __shared__ char smem[];
    const uint32_t sb = smem_u32(smem);
    const int b = blockIdx.z;
    const int h = blockIdx.y;
    const int qt = blockIdx.x;
    const int q0 = qt * 128;
    const int tid = threadIdx.x;
    const int wid = tid >> 5;
    const int lane = tid & 31;
    const int g = lane >> 2;
    const int tq = lane & 3;

    const uint32_t sQ = sb;
    const uint32_t sKV0 = sb + ATT_TILE_B;

    {
        const int row = tid >> 1, seg = tid & 1;
#pragma unroll
        for (int t = 0; t < 4; t++) {
            const size_t go = (size_t)(b * S_ + q0 + row) * ldq + h * 64 + (seg * 4 + t) * 8;
            CP16(sQ + (uint32_t)row * ATT_RSB + (seg * 4 + t) * 16, Qf + go);
        }
    }
    CP_COMMIT();

    const int kt_lo = (qt - 2 < 0) ? 0 : qt - 2;
    const int kt_hi = (qt + 2 > S_ / 128 - 1) ? S_ / 128 - 1 : qt + 2;

    auto load_kv = [&](int kt, int stg) {
        const uint32_t base = sKV0 + stg * 2 * ATT_TILE_B;
        const int row = tid >> 1, seg = tid & 1;
#pragma unroll
        for (int t = 0; t < 4; t++) {
            const size_t go = (size_t)(b * S_ + kt * 128 + row) * ldq + h * 64 + (seg * 4 + t) * 8;
            const uint32_t so = (uint32_t)row * ATT_RSB + (seg * 4 + t) * 16;
            CP16(base + so,              Kf + go);
            CP16(base + ATT_TILE_B + so, Vf + go);
        }
    };
    load_kv(kt_lo, 0);
    CP_COMMIT();

    CP_WAIT1();
    __syncthreads();

    uint32_t qf[4][4];
    {
        const int arow = wid * 16 + (lane & 15);
        const int akb = (lane >> 4) * 8;
#pragma unroll
        for (int ks = 0; ks < 4; ks++) {
            const uint32_t ro = (uint32_t)arow * ATT_RSB + (ks * 16 + akb) * 2;
            ldsm_x4(qf[ks][0], qf[ks][1], qf[ks][2], qf[ks][3], sQ + ro);
        }
    }

    float m0 = -1e30f, m1 = -1e30f, l0 = 0.f, l1 = 0.f;
    float o[8][4];
#pragma unroll
    for (int nd = 0; nd < 8; nd++)
#pragma unroll
        for (int r = 0; r < 4; r++) o[nd][r] = 0.f;

    const int rlo = q0 + wid * 16;
    const int row0 = rlo + g;
    const int brow0 = lane & 7;
    const int bkb = ((lane >> 3) & 1) * 8;
    const int vrow = lane & 15;

    for (int kt = kt_lo; kt <= kt_hi; kt++) {
        const int stg = (kt - kt_lo) & 1;
        if (kt < kt_hi) {
            load_kv(kt + 1, stg ^ 1);
            CP_COMMIT();
            CP_WAIT1();
        } else {
            CP_WAIT0();
        }
        __syncthreads();

        const uint32_t base = sKV0 + stg * 2 * ATT_TILE_B;
        const uint32_t pK = base, pV = base + ATT_TILE_B;

        const int cbase = kt * 128;
        const int T1 = rlo - 256 - cbase;
        const int T2 = rlo + 15 + 256 - cbase;
        int ntlo = (T1 > 0) ? (T1 >> 3) : 0;
        int nthi = (T2 < 0) ? -1 : (T2 >> 3);
        if (nthi > 15) nthi = 15;

        float s[16][4];
#pragma unroll
        for (int nt = 0; nt < 16; nt++)
#pragma unroll
            for (int r = 0; r < 4; r++) s[nt][r] = 0.f;
#pragma unroll
        for (int ks = 0; ks < 4; ks++) {
#pragma unroll
            for (int nt = 0; nt < 16; nt++) {
                if (nt < ntlo || nt > nthi) continue;
                uint32_t bk[2];
                const uint32_t ro = (uint32_t)(nt * 8 + brow0) * ATT_RSB + (ks * 16 + bkb) * 2;
                ldsm_x2(bk[0], bk[1], pK + ro);
                mma_f16(s[nt], qf[ks], bk);
            }
        }

        float rmax0 = -1e30f, rmax1 = -1e30f;
#pragma unroll
        for (int nt = 0; nt < 16; nt++) {
            if (nt < ntlo || nt > nthi) continue;
            const int col = cbase + nt * 8 + tq * 2;
            const bool i00 = (unsigned)(row0 - col + 256) <= 512u;
            const bool i01 = (unsigned)(row0 - col - 1 + 256) <= 512u;
            const bool i10 = (unsigned)(row0 + 8 - col + 256) <= 512u;
            const bool i11 = (unsigned)(row0 + 8 - col - 1 + 256) <= 512u;
            s[nt][0] = i00 ? s[nt][0] : -1e30f;
            s[nt][1] = i01 ? s[nt][1] : -1e30f;
            s[nt][2] = i10 ? s[nt][2] : -1e30f;
            s[nt][3] = i11 ? s[nt][3] : -1e30f;
            rmax0 = fmaxf(rmax0, fmaxf(s[nt][0], s[nt][1]));
            rmax1 = fmaxf(rmax1, fmaxf(s[nt][2], s[nt][3]));
        }
        rmax0 = fmaxf(rmax0, __shfl_xor_sync(0xffffffffu, rmax0, 1));
        rmax0 = fmaxf(rmax0, __shfl_xor_sync(0xffffffffu, rmax0, 2));
        rmax1 = fmaxf(rmax1, __shfl_xor_sync(0xffffffffu, rmax1, 1));
        rmax1 = fmaxf(rmax1, __shfl_xor_sync(0xffffffffu, rmax1, 2));

        const float nm0 = fmaxf(m0, rmax0);
        const float nm1 = fmaxf(m1, rmax1);
        const float c0 = __expf(m0 - nm0);
        const float c1 = __expf(m1 - nm1);
        m0 = nm0; m1 = nm1;

        float add0 = 0.f, add1 = 0.f;
        uint32_t p[16][2];
#pragma unroll
        for (int nt = 0; nt < 16; nt++) {
            if (nt < ntlo || nt > nthi) { p[nt][0] = 0; p[nt][1] = 0; continue; }
            const float p00 = __expf(s[nt][0] - nm0);
            const float p01 = __expf(s[nt][1] - nm0);
            const float p10 = __expf(s[nt][2] - nm1);
            const float p11 = __expf(s[nt][3] - nm1);
            add0 += p00 + p01;
            add1 += p10 + p11;
            p[nt][0] = packh(p00, p01);
            p[nt][1] = packh(p10, p11);
        }
        add0 += __shfl_xor_sync(0xffffffffu, add0, 1);
        add0 += __shfl_xor_sync(0xffffffffu, add0, 2);
        add1 += __shfl_xor_sync(0xffffffffu, add1, 1);
        add1 += __shfl_xor_sync(0xffffffffu, add1, 2);
        l0 = l0 * c0 + add0;
        l1 = l1 * c1 + add1;
#pragma unroll
        for (int nd = 0; nd < 8; nd++) {
            o[nd][0] *= c0; o[nd][1] *= c0;
            o[nd][2] *= c1; o[nd][3] *= c1;
        }

#pragma unroll
        for (int ks = 0; ks < 8; ks++) {
            if (2 * ks + 1 < ntlo || 2 * ks > nthi) continue;
            uint32_t a[4] = {p[2 * ks][0], p[2 * ks][1], p[2 * ks + 1][0], p[2 * ks + 1][1]};
#pragma unroll
            for (int nd = 0; nd < 8; nd++) {
                uint32_t bv[2];
                const uint32_t ro = (uint32_t)(ks * 16 + vrow) * ATT_RSB + nd * 16;
                ldsm_x2t(bv[0], bv[1], pV + ro);
                mma_f16(o[nd], a, bv);
            }
        }
        __syncthreads();
    }

    const float inv0 = 1.f / l0;
    const float inv1 = 1.f / l1;
#pragma unroll
    for (int nd = 0; nd < 8; nd++) {
        const int d = nd * 8 + tq * 2;
        const size_t o0 = (size_t)(b * S_ + row0) * D_ + h * 64 + d;
        const size_t o1 = (size_t)(b * S_ + row0 + 8) * D_ + h * 64 + d;
        *(uint32_t*)(Of + o0) = packh(o[nd][0] * inv0, o[nd][1] * inv0);
        *(uint32_t*)(Of + o1) = packh(o[nd][2] * inv1, o[nd][3] * inv1);
    }
}

// ---------------------------------------------------------------------------
// Fused split-K reduce + bias + residual add + LayerNorm.
// val = x + (p0 + p1 + p2) + bias;  then LN -> xout fp32 + xf fp16
// ---------------------------------------------------------------------------
__global__ __launch_bounds__(256) void add_ln3_kernel(
    const float* __restrict__ x, const float* __restrict__ parts,
    const float* __restrict__ bias,
    const float* __restrict__ g, const float* __restrict__ be,
    float* __restrict__ xout, __half* __restrict__ xf)
{
    const int row = blockIdx.x;
    const int tid = threadIdx.x;
    const float* xp = x + (size_t)row * D_;
    const float* p0 = parts + (size_t)row * D_;
    const float* p1 = parts + (size_t)MROWS * D_ + (size_t)row * D_;
    const float* p2 = parts + 2 * (size_t)MROWS * D_ + (size_t)row * D_;

    float v[3];
    float s1 = 0.f, s2 = 0.f;
#pragma unroll
    for (int i = 0; i < 3; i++) {
        const int c = tid + 256 * i;
        v[i] = xp[c] + ((p0[c] + p1[c]) + p2[c]) + bias[c];
        s1 += v[i];
        s2 += v[i] * v[i];
    }
#pragma unroll
    for (int off = 16; off; off >>= 1) {
        s1 += __shfl_xor_sync(0xffffffffu, s1, off);
        s2 += __shfl_xor_sync(0xffffffffu, s2, off);
    }
    __shared__ float r1[8], r2[8];
    if ((tid & 31) == 0) { r1[tid >> 5] = s1; r2[tid >> 5] = s2; }
    __syncthreads();
    s1 = 0.f; s2 = 0.f;
#pragma unroll
    for (int i = 0; i < 8; i++) { s1 += r1[i]; s2 += r2[i]; }

    const float mean = s1 * (1.f / 768.f);
    const float var  = s2 * (1.f / 768.f) - mean * mean;
    const float rstd = rsqrtf(var + 1e-5f);
#pragma unroll
    for (int i = 0; i < 3; i++) {
        const int c = tid + 256 * i;
        const float val = (v[i] - mean) * rstd * g[c] + be[c];
        xout[(size_t)row * D_ + c] = val;
        xf[(size_t)row * D_ + c] = __float2half_rn(val);
    }
}

// ---------------------------------------------------------------------------
// Host orchestration
// ---------------------------------------------------------------------------
static void run_cvt(const float* in, __half* out, int n)
{
    int n4 = n >> 2;
    cvt_kernel<<<(n4 + 255) / 256, 256>>>(in, out, n4);
}

template <int EPI>
static void run_gemm(const __half* A, const __half* W, const float* bias,
                     __half* Hf, int M, int N, int K)
{
    dim3 grid(N / 128, M / 256, 1);
    gemm_mma_kernel<EPI><<<grid, 256, GEMM_SMEM>>>(A, W, bias, nullptr, Hf, M, N, K, K);
}

// split-K=3 raw-partial GEMM (EPI=3)
static void run_gemm_sk(const __half* A, const __half* W, float* Cparts,
                        int M, int N, int K)
{
    dim3 grid(N / 128, M / 256, KSPLIT);
    gemm_mma_kernel<3><<<grid, 256, GEMM_SMEM>>>(A, W, nullptr, Cparts, nullptr,
                                                 M, N, K, K / KSPLIT);
}

extern "C" void kernel_launch(void* const* d_in, const int* in_sizes, int n_in,
                              void* d_out, int out_size)
{
    const float* src = (const float*)d_in[0];
    const float* qw  = (const float*)d_in[1];
    const float* qb  = (const float*)d_in[2];
    const float* kw  = (const float*)d_in[3];
    const float* kb  = (const float*)d_in[4];
    const float* vw  = (const float*)d_in[5];
    const float* vb  = (const float*)d_in[6];
    const float* ow  = (const float*)d_in[7];
    const float* ob  = (const float*)d_in[8];
    const float* w1  = (const float*)d_in[9];
    const float* b1  = (const float*)d_in[10];
    const float* w2  = (const float*)d_in[11];
    const float* b2  = (const float*)d_in[12];
    const float* g1  = (const float*)d_in[13];
    const float* be1 = (const float*)d_in[14];
    const float* g2  = (const float*)d_in[15];
    const float* be2 = (const float*)d_in[16];

    cudaFuncSetAttribute((const void*)gemm_mma_kernel<1>, cudaFuncAttributeMaxDynamicSharedMemorySize, GEMM_SMEM);
    cudaFuncSetAttribute((const void*)gemm_mma_kernel<2>, cudaFuncAttributeMaxDynamicSharedMemorySize, GEMM_SMEM);
    cudaFuncSetAttribute((const void*)gemm_mma_kernel<3>, cudaFuncAttributeMaxDynamicSharedMemorySize, GEMM_SMEM);
    cudaFuncSetAttribute((const void*)attn_mma_kernel, cudaFuncAttributeMaxDynamicSharedMemorySize, ATT_SMEM);

    float *x, *tmp, *bqkv;
    __half *xf, *of, *fff, *wf;
    cudaGetSymbolAddress((void**)&x,    g_x);
    cudaGetSymbolAddress((void**)&tmp,  g_tmp);
    cudaGetSymbolAddress((void**)&bqkv, g_bqkv);
    cudaGetSymbolAddress((void**)&xf,   g_xf);
    cudaGetSymbolAddress((void**)&of,   g_of);
    cudaGetSymbolAddress((void**)&fff,  g_fff);
    cudaGetSymbolAddress((void**)&wf,   g_wf);

    const size_t xbytes = (size_t)MROWS * D_ * sizeof(float);
    cudaMemcpyAsync(x, src, xbytes, cudaMemcpyDeviceToDevice, 0);
    run_cvt(src, xf, MROWS * D_);

    for (int l = 0; l < L_; l++) {
        const float* qwl = qw + (size_t)l * D_ * D_;
        const float* kwl = kw + (size_t)l * D_ * D_;
        const float* vwl = vw + (size_t)l * D_ * D_;
        const float* owl = ow + (size_t)l * D_ * D_;
        const float* w1l = w1 + (size_t)l * DFF_ * D_;
        const float* w2l = w2 + (size_t)l * D_ * DFF_;

        // fused QKV projection: W = [qw; kw; vw] (2304 x 768), Q pre-scaled
        {
            const int R3 = 3 * ((D_ * D_) >> 2);
            cvt3_kernel<<<(R3 + 255) / 256, 256>>>(qwl, kwl, vwl, wf);
        }
        pack_bias_kernel<<<(NQKV + 255) / 256, 256>>>(qb + l * D_, kb + l * D_, vb + l * D_, bqkv);
        run_gemm<1>(xf, wf, bqkv, fff, MROWS, NQKV, D_);

        // banded attention on packed QKV
        {
            dim3 grid(S_ / 128, H_, B_);
            attn_mma_kernel<<<grid, 256, ATT_SMEM>>>(
                fff, fff + D_, fff + 2 * D_, NQKV, of);
        }

        // output projection: split-K=3 partials, reduced inside add_ln3
        run_cvt(owl, wf, D_ * D_);
        run_gemm_sk(of, wf, tmp, MROWS, D_, D_);
        add_ln3_kernel<<<MROWS, 256>>>(x, tmp, ob + l * D_, g1 + l * D_, be1 + l * D_, x, xf);

        // FFN
        run_cvt(w1l, wf, DFF_ * D_);
        run_gemm<2>(xf, wf, b1 + l * DFF_, fff, MROWS, DFF_, D_);
        run_cvt(w2l, wf, D_ * DFF_);
        run_gemm_sk(fff, wf, tmp, MROWS, D_, DFF_);
        // last LN writes the final output directly to d_out
        float* xout = (l == L_ - 1) ? (float*)d_out : x;
        add_ln3_kernel<<<MROWS, 256>>>(x, tmp, b2 + l * D_, g2 + l * D_, be2 + l * D_, xout, xf);
    }
}

// round 11
// speedup vs baseline: 1.0164x; 1.0164x over previous
#include <cuda_runtime.h>
#include <cuda_bf16.h>
#include <cuda_fp16.h>
#include <cstdint>

// Problem constants
#define B_ 2
#define S_ 2048
#define D_ 768
#define H_ 12
#define DH_ 64
#define L_ 2
#define DFF_ 3072
#define MROWS (B_ * S_)   // 4096
#define NQKV 2304
#define KSPLIT 3

// ---------------------------------------------------------------------------
// Scratch (static device globals — no allocation allowed)
// ---------------------------------------------------------------------------
__device__ float g_x  [MROWS * D_];
__device__ float g_tmp[KSPLIT * MROWS * D_];   // split-K partials
__device__ float g_bqkv[NQKV];
__device__ __half g_xf [MROWS * D_];
__device__ __half g_of [MROWS * D_];
__device__ __half g_fff[MROWS * DFF_];   // also holds packed QKV (M x 2304)
__device__ __half g_wf [DFF_ * D_];

// ---------------------------------------------------------------------------
// Baseline-PTX tensor-core helpers
// ---------------------------------------------------------------------------
__device__ __forceinline__ uint32_t smem_u32(const void* p) {
    uint32_t a;
    asm("{ .reg .u64 t; cvta.to.shared.u64 t, %1; cvt.u32.u64 %0, t; }"
        : "=r"(a) : "l"(p));
    return a;
}
__device__ __forceinline__ void ldsm_x4(uint32_t& r0, uint32_t& r1,
                                        uint32_t& r2, uint32_t& r3, uint32_t a) {
    asm volatile("ldmatrix.sync.aligned.m8n8.x4.shared.b16 {%0,%1,%2,%3}, [%4];"
                 : "=r"(r0), "=r"(r1), "=r"(r2), "=r"(r3) : "r"(a));
}
__device__ __forceinline__ void ldsm_x2(uint32_t& r0, uint32_t& r1, uint32_t a) {
    asm volatile("ldmatrix.sync.aligned.m8n8.x2.shared.b16 {%0,%1}, [%2];"
                 : "=r"(r0), "=r"(r1) : "r"(a));
}
__device__ __forceinline__ void ldsm_x2t(uint32_t& r0, uint32_t& r1, uint32_t a) {
    asm volatile("ldmatrix.sync.aligned.m8n8.x2.trans.shared.b16 {%0,%1}, [%2];"
                 : "=r"(r0), "=r"(r1) : "r"(a));
}
__device__ __forceinline__ void mma_f16(float* d, const uint32_t* a, const uint32_t* b) {
    asm volatile(
        "mma.sync.aligned.m16n8k16.row.col.f32.f16.f16.f32 "
        "{%0,%1,%2,%3}, {%4,%5,%6,%7}, {%8,%9}, {%0,%1,%2,%3};"
        : "+f"(d[0]), "+f"(d[1]), "+f"(d[2]), "+f"(d[3])
        : "r"(a[0]), "r"(a[1]), "r"(a[2]), "r"(a[3]), "r"(b[0]), "r"(b[1]));
}
#define CP16(dst, src) \
    asm volatile("cp.async.cg.shared.global [%0], [%1], 16;" :: "r"(dst), "l"(src))
#define CP_COMMIT() asm volatile("cp.async.commit_group;" ::: "memory")
#define CP_WAIT0()  asm volatile("cp.async.wait_group 0;" ::: "memory")
#define CP_WAIT1()  asm volatile("cp.async.wait_group 1;" ::: "memory")

__device__ __forceinline__ uint32_t packh(float a, float b) {
    __half2 t = __floats2half2_rn(a, b);
    return *(uint32_t*)&t;
}

// ---------------------------------------------------------------------------
// Convert fp32 -> fp16 (single source)
// ---------------------------------------------------------------------------
__global__ __launch_bounds__(256) void cvt_kernel(
    const float* __restrict__ in, __half* __restrict__ out, int n4)
{
    int i = blockIdx.x * blockDim.x + threadIdx.x;
    if (i >= n4) return;
    float4 x = ((const float4*)in)[i];
    __half2* op = (__half2*)out;
    op[2 * i + 0] = __floats2half2_rn(x.x, x.y);
    op[2 * i + 1] = __floats2half2_rn(x.z, x.w);
}

// Convert 3 equal-size fp32 sources into one contiguous fp16 buffer
__global__ __launch_bounds__(256) void cvt3_kernel(
    const float* __restrict__ a, const float* __restrict__ b,
    const float* __restrict__ c, __half* __restrict__ out)
{
    const int R = (D_ * D_) >> 2;
    int i = blockIdx.x * blockDim.x + threadIdx.x;
    if (i >= 3 * R) return;
    const float* src; int j;
    if (i < R)          { src = a; j = i; }
    else if (i < 2 * R) { src = b; j = i - R; }
    else                { src = c; j = i - 2 * R; }
    float4 x = ((const float4*)src)[j];
    __half2* op = (__half2*)out;
    op[2 * i + 0] = __floats2half2_rn(x.x, x.y);
    op[2 * i + 1] = __floats2half2_rn(x.z, x.w);
}

// Pack [qb; kb; vb] into one 2304-float bias vector
__global__ __launch_bounds__(256) void pack_bias_kernel(
    const float* __restrict__ qb, const float* __restrict__ kb,
    const float* __restrict__ vb, float* __restrict__ out)
{
    int i = blockIdx.x * blockDim.x + threadIdx.x;
    if (i >= NQKV) return;
    float v;
    if (i < D_)          v = qb[i];
    else if (i < 2 * D_) v = kb[i - D_];
    else                 v = vb[i - 2 * D_];
    out[i] = v;
}

// ---------------------------------------------------------------------------
// fp16 mma.sync GEMM: C = A[M,Kfull] @ W[N,Kfull]^T (+bias)
// 128x128 CTA tile, BK=64, 4 warps (2x2), warp tile 64x64, 128 threads.
// 2 CTAs/SM for cross-CTA latency hiding; 2-stage cp.async pipeline.
// Split-K via blockIdx.z.
// EPI: 1 = fp16 out (+bias, x0.125 for n<768); 2 = relu + fp16 out (+bias);
//      3 = raw fp32 partial (no bias), at C + z*M*N
// ---------------------------------------------------------------------------
#define RS_B 144               // smem row stride bytes (64 halves = 128B + 16 pad)
#define TILE_B (128 * RS_B)    // 18432
#define STAGE_B (2 * TILE_B)   // A + B
#define GEMM_SMEM (2 * STAGE_B)  // 73728

template <int EPI>
__global__ __launch_bounds__(128, 2) void gemm_mma_kernel(
    const __half* __restrict__ A, const __half* __restrict__ W,
    const float* __restrict__ bias, float* __restrict__ C,
    __half* __restrict__ Hf, int M, int N, int K, int klen)
{
    extern __shared__ char smem[];
    const uint32_t sb = smem_u32(smem);

    const int tid = threadIdx.x;
    const int wid = tid >> 5;
    const int lane = tid & 31;
    const int warp_m = wid >> 1;   // 0..1
    const int warp_n = wid & 1;    // 0..1
    const int bm = blockIdx.y * 128;
    const int bn = blockIdx.x * 128;
    const int kstart = blockIdx.z * klen;

    float acc[4][8][4];
#pragma unroll
    for (int mi = 0; mi < 4; mi++)
#pragma unroll
        for (int ni = 0; ni < 8; ni++)
#pragma unroll
            for (int r = 0; r < 4; r++) acc[mi][ni][r] = 0.f;

    auto load_chunk = [&](int kc, int stage) {
        const uint32_t base = sb + stage * STAGE_B;
#pragma unroll
        for (int t = 0; t < 8; t++) {
            const int idx = tid + t * 128;
            const int lr = idx >> 3, ls = idx & 7;
            CP16(base + lr * RS_B + ls * 16,
                 A + (size_t)(bm + lr) * K + kstart + kc + ls * 8);
        }
#pragma unroll
        for (int t = 0; t < 8; t++) {
            const int idx = tid + t * 128;
            const int lr = idx >> 3, ls = idx & 7;
            CP16(base + TILE_B + lr * RS_B + ls * 16,
                 W + (size_t)(bn + lr) * K + kstart + kc + ls * 8);
        }
    };

    const int arow = warp_m * 64 + (lane & 15);
    const int akb  = (lane >> 4) * 8;
    const int bg_ni = (lane >> 4);
    const int bg_kh = ((lane >> 3) & 1) * 8;
    const int brow_l = lane & 7;

    auto compute = [&](int stage) {
        const uint32_t base = sb + stage * STAGE_B;
        const uint32_t pA = base;
        const uint32_t pB = base + TILE_B;
#pragma unroll
        for (int ks = 0; ks < 4; ks++) {
            const int k0 = ks * 16;
            uint32_t af[4][4], bf[8][2];
#pragma unroll
            for (int mi = 0; mi < 4; mi++) {
                const uint32_t ro = (uint32_t)(arow + mi * 16) * RS_B + (k0 + akb) * 2;
                ldsm_x4(af[mi][0], af[mi][1], af[mi][2], af[mi][3], pA + ro);
            }
#pragma unroll
            for (int np = 0; np < 4; np++) {    // ni pairs {0,1},{2,3},{4,5},{6,7}
                const int nrow = warp_n * 64 + (np * 2 + bg_ni) * 8 + brow_l;
                const uint32_t ro = (uint32_t)nrow * RS_B + (k0 + bg_kh) * 2;
                ldsm_x4(bf[np * 2][0], bf[np * 2][1], bf[np * 2 + 1][0], bf[np * 2 + 1][1], pB + ro);
            }
#pragma unroll
            for (int mi = 0; mi < 4; mi++)
#pragma unroll
                for (int ni = 0; ni < 8; ni++)
                    mma_f16(acc[mi][ni], af[mi], bf[ni]);
        }
    };

    const int nchunks = klen >> 6;
    load_chunk(0, 0);
    CP_COMMIT();

    for (int c = 0; c < nchunks; c++) {
        CP_WAIT0();
        __syncthreads();
        if (c + 1 < nchunks) {
            load_chunk((c + 1) << 6, (c + 1) & 1);
            CP_COMMIT();
        }
        compute(c & 1);
    }

    // epilogue
    float* Cz = (EPI == 3) ? (C + (size_t)blockIdx.z * M * N) : C;
#pragma unroll
    for (int mi = 0; mi < 4; mi++) {
        const int m0 = bm + warp_m * 64 + mi * 16 + (lane >> 2);
#pragma unroll
        for (int ni = 0; ni < 8; ni++) {
            const int n0 = bn + warp_n * 64 + ni * 8 + (lane & 3) * 2;
            float v00 = acc[mi][ni][0], v01 = acc[mi][ni][1];
            float v10 = acc[mi][ni][2], v11 = acc[mi][ni][3];
            if (EPI != 3) {
                const float bx = bias[n0], by = bias[n0 + 1];
                v00 += bx; v01 += by; v10 += bx; v11 += by;
            }
            if (EPI == 1) {
                const float sc = (n0 < 768) ? 0.125f : 1.0f;  // Q pre-scale (exact 2^-3)
                v00 *= sc; v01 *= sc; v10 *= sc; v11 *= sc;
            }
            if (EPI == 2) {
                v00 = fmaxf(v00, 0.f); v01 = fmaxf(v01, 0.f);
                v10 = fmaxf(v10, 0.f); v11 = fmaxf(v11, 0.f);
            }
            if (EPI == 3) {
                *(float2*)(Cz + (size_t)m0 * N + n0) = make_float2(v00, v01);
                *(float2*)(Cz + (size_t)(m0 + 8) * N + n0) = make_float2(v10, v11);
            } else {
                *(uint32_t*)(Hf + (size_t)m0 * N + n0) = packh(v00, v01);
                *(uint32_t*)(Hf + (size_t)(m0 + 8) * N + n0) = packh(v10, v11);
            }
        }
    }
}

// ---------------------------------------------------------------------------
// Tensor-core banded flash attention, fp16, band-aware MMA skipping.
// ---------------------------------------------------------------------------
#define ATT_RSB 144
#define ATT_TILE_B (128 * ATT_RSB)        // 18432
#define ATT_SMEM (5 * ATT_TILE_B)         // Q + 2 stages x (K,V) = 92160

__global__ __launch_bounds__(256) void attn_mma_kernel(
    const __half* __restrict__ Qf, const __half* __restrict__ Kf,
    const __half* __restrict__ Vf, int ldq, __half* __restrict__ Of)
{
    extern __shared__ char smem[];
    const uint32_t sb = smem_u32(smem);
    const int b = blockIdx.z;
    const int h = blockIdx.y;
    const int qt = blockIdx.x;
    const int q0 = qt * 128;
    const int tid = threadIdx.x;
    const int wid = tid >> 5;
    const int lane = tid & 31;
    const int g = lane >> 2;
    const int tq = lane & 3;

    const uint32_t sQ = sb;
    const uint32_t sKV0 = sb + ATT_TILE_B;

    {
        const int row = tid >> 1, seg = tid & 1;
#pragma unroll
        for (int t = 0; t < 4; t++) {
            const size_t go = (size_t)(b * S_ + q0 + row) * ldq + h * 64 + (seg * 4 + t) * 8;
            CP16(sQ + (uint32_t)row * ATT_RSB + (seg * 4 + t) * 16, Qf + go);
        }
    }
    CP_COMMIT();

    const int kt_lo = (qt - 2 < 0) ? 0 : qt - 2;
    const int kt_hi = (qt + 2 > S_ / 128 - 1) ? S_ / 128 - 1 : qt + 2;

    auto load_kv = [&](int kt, int stg) {
        const uint32_t base = sKV0 + stg * 2 * ATT_TILE_B;
        const int row = tid >> 1, seg = tid & 1;
#pragma unroll
        for (int t = 0; t < 4; t++) {
            const size_t go = (size_t)(b * S_ + kt * 128 + row) * ldq + h * 64 + (seg * 4 + t) * 8;
            const uint32_t so = (uint32_t)row * ATT_RSB + (seg * 4 + t) * 16;
            CP16(base + so,              Kf + go);
            CP16(base + ATT_TILE_B + so, Vf + go);
        }
    };
    load_kv(kt_lo, 0);
    CP_COMMIT();

    CP_WAIT1();
    __syncthreads();

    uint32_t qf[4][4];
    {
        const int arow = wid * 16 + (lane & 15);
        const int akb = (lane >> 4) * 8;
#pragma unroll
        for (int ks = 0; ks < 4; ks++) {
            const uint32_t ro = (uint32_t)arow * ATT_RSB + (ks * 16 + akb) * 2;
            ldsm_x4(qf[ks][0], qf[ks][1], qf[ks][2], qf[ks][3], sQ + ro);
        }
    }

    float m0 = -1e30f, m1 = -1e30f, l0 = 0.f, l1 = 0.f;
    float o[8][4];
#pragma unroll
    for (int nd = 0; nd < 8; nd++)
#pragma unroll
        for (int r = 0; r < 4; r++) o[nd][r] = 0.f;

    const int rlo = q0 + wid * 16;
    const int row0 = rlo + g;
    const int brow0 = lane & 7;
    const int bkb = ((lane >> 3) & 1) * 8;
    const int vrow = lane & 15;

    for (int kt = kt_lo; kt <= kt_hi; kt++) {
        const int stg = (kt - kt_lo) & 1;
        if (kt < kt_hi) {
            load_kv(kt + 1, stg ^ 1);
            CP_COMMIT();
            CP_WAIT1();
        } else {
            CP_WAIT0();
        }
        __syncthreads();

        const uint32_t base = sKV0 + stg * 2 * ATT_TILE_B;
        const uint32_t pK = base, pV = base + ATT_TILE_B;

        const int cbase = kt * 128;
        const int T1 = rlo - 256 - cbase;
        const int T2 = rlo + 15 + 256 - cbase;
        int ntlo = (T1 > 0) ? (T1 >> 3) : 0;
        int nthi = (T2 < 0) ? -1 : (T2 >> 3);
        if (nthi > 15) nthi = 15;

        float s[16][4];
#pragma unroll
        for (int nt = 0; nt < 16; nt++)
#pragma unroll
            for (int r = 0; r < 4; r++) s[nt][r] = 0.f;
#pragma unroll
        for (int ks = 0; ks < 4; ks++) {
#pragma unroll
            for (int nt = 0; nt < 16; nt++) {
                if (nt < ntlo || nt > nthi) continue;
                uint32_t bk[2];
                const uint32_t ro = (uint32_t)(nt * 8 + brow0) * ATT_RSB + (ks * 16 + bkb) * 2;
                ldsm_x2(bk[0], bk[1], pK + ro);
                mma_f16(s[nt], qf[ks], bk);
            }
        }

        float rmax0 = -1e30f, rmax1 = -1e30f;
#pragma unroll
        for (int nt = 0; nt < 16; nt++) {
            if (nt < ntlo || nt > nthi) continue;
            const int col = cbase + nt * 8 + tq * 2;
            const bool i00 = (unsigned)(row0 - col + 256) <= 512u;
            const bool i01 = (unsigned)(row0 - col - 1 + 256) <= 512u;
            const bool i10 = (unsigned)(row0 + 8 - col + 256) <= 512u;
            const bool i11 = (unsigned)(row0 + 8 - col - 1 + 256) <= 512u;
            s[nt][0] = i00 ? s[nt][0] : -1e30f;
            s[nt][1] = i01 ? s[nt][1] : -1e30f;
            s[nt][2] = i10 ? s[nt][2] : -1e30f;
            s[nt][3] = i11 ? s[nt][3] : -1e30f;
            rmax0 = fmaxf(rmax0, fmaxf(s[nt][0], s[nt][1]));
            rmax1 = fmaxf(rmax1, fmaxf(s[nt][2], s[nt][3]));
        }
        rmax0 = fmaxf(rmax0, __shfl_xor_sync(0xffffffffu, rmax0, 1));
        rmax0 = fmaxf(rmax0, __shfl_xor_sync(0xffffffffu, rmax0, 2));
        rmax1 = fmaxf(rmax1, __shfl_xor_sync(0xffffffffu, rmax1, 1));
        rmax1 = fmaxf(rmax1, __shfl_xor_sync(0xffffffffu, rmax1, 2));

        const float nm0 = fmaxf(m0, rmax0);
        const float nm1 = fmaxf(m1, rmax1);
        const float c0 = __expf(m0 - nm0);
        const float c1 = __expf(m1 - nm1);
        m0 = nm0; m1 = nm1;

        float add0 = 0.f, add1 = 0.f;
        uint32_t p[16][2];
#pragma unroll
        for (int nt = 0; nt < 16; nt++) {
            if (nt < ntlo || nt > nthi) { p[nt][0] = 0; p[nt][1] = 0; continue; }
            const float p00 = __expf(s[nt][0] - nm0);
            const float p01 = __expf(s[nt][1] - nm0);
            const float p10 = __expf(s[nt][2] - nm1);
            const float p11 = __expf(s[nt][3] - nm1);
            add0 += p00 + p01;
            add1 += p10 + p11;
            p[nt][0] = packh(p00, p01);
            p[nt][1] = packh(p10, p11);
        }
        add0 += __shfl_xor_sync(0xffffffffu, add0, 1);
        add0 += __shfl_xor_sync(0xffffffffu, add0, 2);
        add1 += __shfl_xor_sync(0xffffffffu, add1, 1);
        add1 += __shfl_xor_sync(0xffffffffu, add1, 2);
        l0 = l0 * c0 + add0;
        l1 = l1 * c1 + add1;
#pragma unroll
        for (int nd = 0; nd < 8; nd++) {
            o[nd][0] *= c0; o[nd][1] *= c0;
            o[nd][2] *= c1; o[nd][3] *= c1;
        }

#pragma unroll
        for (int ks = 0; ks < 8; ks++) {
            if (2 * ks + 1 < ntlo || 2 * ks > nthi) continue;
            uint32_t a[4] = {p[2 * ks][0], p[2 * ks][1], p[2 * ks + 1][0], p[2 * ks + 1][1]};
#pragma unroll
            for (int nd = 0; nd < 8; nd++) {
                uint32_t bv[2];
                const uint32_t ro = (uint32_t)(ks * 16 + vrow) * ATT_RSB + nd * 16;
                ldsm_x2t(bv[0], bv[1], pV + ro);
                mma_f16(o[nd], a, bv);
            }
        }
        __syncthreads();
    }

    const float inv0 = 1.f / l0;
    const float inv1 = 1.f / l1;
#pragma unroll
    for (int nd = 0; nd < 8; nd++) {
        const int d = nd * 8 + tq * 2;
        const size_t o0 = (size_t)(b * S_ + row0) * D_ + h * 64 + d;
        const size_t o1 = (size_t)(b * S_ + row0 + 8) * D_ + h * 64 + d;
        *(uint32_t*)(Of + o0) = packh(o[nd][0] * inv0, o[nd][1] * inv0);
        *(uint32_t*)(Of + o1) = packh(o[nd][2] * inv1, o[nd][3] * inv1);
    }
}

// ---------------------------------------------------------------------------
// Fused split-K reduce + bias + residual add + LayerNorm.
// val = x + (p0 + p1 + p2) + bias;  then LN -> xout fp32 + xf fp16
// ---------------------------------------------------------------------------
__global__ __launch_bounds__(256) void add_ln3_kernel(
    const float* __restrict__ x, const float* __restrict__ parts,
    const float* __restrict__ bias,
    const float* __restrict__ g, const float* __restrict__ be,
    float* __restrict__ xout, __half* __restrict__ xf)
{
    const int row = blockIdx.x;
    const int tid = threadIdx.x;
    const float* xp = x + (size_t)row * D_;
    const float* p0 = parts + (size_t)row * D_;
    const float* p1 = parts + (size_t)MROWS * D_ + (size_t)row * D_;
    const float* p2 = parts + 2 * (size_t)MROWS * D_ + (size_t)row * D_;

    float v[3];
    float s1 = 0.f, s2 = 0.f;
#pragma unroll
    for (int i = 0; i < 3; i++) {
        const int c = tid + 256 * i;
        v[i] = xp[c] + ((p0[c] + p1[c]) + p2[c]) + bias[c];
        s1 += v[i];
        s2 += v[i] * v[i];
    }
#pragma unroll
    for (int off = 16; off; off >>= 1) {
        s1 += __shfl_xor_sync(0xffffffffu, s1, off);
        s2 += __shfl_xor_sync(0xffffffffu, s2, off);
    }
    __shared__ float r1[8], r2[8];
    if ((tid & 31) == 0) { r1[tid >> 5] = s1; r2[tid >> 5] = s2; }
    __syncthreads();
    s1 = 0.f; s2 = 0.f;
#pragma unroll
    for (int i = 0; i < 8; i++) { s1 += r1[i]; s2 += r2[i]; }

    const float mean = s1 * (1.f / 768.f);
    const float var  = s2 * (1.f / 768.f) - mean * mean;
    const float rstd = rsqrtf(var + 1e-5f);
#pragma unroll
    for (int i = 0; i < 3; i++) {
        const int c = tid + 256 * i;
        const float val = (v[i] - mean) * rstd * g[c] + be[c];
        xout[(size_t)row * D_ + c] = val;
        xf[(size_t)row * D_ + c] = __float2half_rn(val);
    }
}

// ---------------------------------------------------------------------------
// Host orchestration
// ---------------------------------------------------------------------------
static void run_cvt(const float* in, __half* out, int n)
{
    int n4 = n >> 2;
    cvt_kernel<<<(n4 + 255) / 256, 256>>>(in, out, n4);
}

template <int EPI>
static void run_gemm(const __half* A, const __half* W, const float* bias,
                     __half* Hf, int M, int N, int K)
{
    dim3 grid(N / 128, M / 128, 1);
    gemm_mma_kernel<EPI><<<grid, 128, GEMM_SMEM>>>(A, W, bias, nullptr, Hf, M, N, K, K);
}

// split-K=3 raw-partial GEMM (EPI=3)
static void run_gemm_sk(const __half* A, const __half* W, float* Cparts,
                        int M, int N, int K)
{
    dim3 grid(N / 128, M / 128, KSPLIT);
    gemm_mma_kernel<3><<<grid, 128, GEMM_SMEM>>>(A, W, nullptr, Cparts, nullptr,
                                                 M, N, K, K / KSPLIT);
}

extern "C" void kernel_launch(void* const* d_in, const int* in_sizes, int n_in,
                              void* d_out, int out_size)
{
    const float* src = (const float*)d_in[0];
    const float* qw  = (const float*)d_in[1];
    const float* qb  = (const float*)d_in[2];
    const float* kw  = (const float*)d_in[3];
    const float* kb  = (const float*)d_in[4];
    const float* vw  = (const float*)d_in[5];
    const float* vb  = (const float*)d_in[6];
    const float* ow  = (const float*)d_in[7];
    const float* ob  = (const float*)d_in[8];
    const float* w1  = (const float*)d_in[9];
    const float* b1  = (const float*)d_in[10];
    const float* w2  = (const float*)d_in[11];
    const float* b2  = (const float*)d_in[12];
    const float* g1  = (const float*)d_in[13];
    const float* be1 = (const float*)d_in[14];
    const float* g2  = (const float*)d_in[15];
    const float* be2 = (const float*)d_in[16];

    cudaFuncSetAttribute((const void*)gemm_mma_kernel<1>, cudaFuncAttributeMaxDynamicSharedMemorySize, GEMM_SMEM);
    cudaFuncSetAttribute((const void*)gemm_mma_kernel<2>, cudaFuncAttributeMaxDynamicSharedMemorySize, GEMM_SMEM);
    cudaFuncSetAttribute((const void*)gemm_mma_kernel<3>, cudaFuncAttributeMaxDynamicSharedMemorySize, GEMM_SMEM);
    cudaFuncSetAttribute((const void*)attn_mma_kernel, cudaFuncAttributeMaxDynamicSharedMemorySize, ATT_SMEM);

    float *x, *tmp, *bqkv;
    __half *xf, *of, *fff, *wf;
    cudaGetSymbolAddress((void**)&x,    g_x);
    cudaGetSymbolAddress((void**)&tmp,  g_tmp);
    cudaGetSymbolAddress((void**)&bqkv, g_bqkv);
    cudaGetSymbolAddress((void**)&xf,   g_xf);
    cudaGetSymbolAddress((void**)&of,   g_of);
    cudaGetSymbolAddress((void**)&fff,  g_fff);
    cudaGetSymbolAddress((void**)&wf,   g_wf);

    const size_t xbytes = (size_t)MROWS * D_ * sizeof(float);
    cudaMemcpyAsync(x, src, xbytes, cudaMemcpyDeviceToDevice, 0);
    run_cvt(src, xf, MROWS * D_);

    for (int l = 0; l < L_; l++) {
        const float* qwl = qw + (size_t)l * D_ * D_;
        const float* kwl = kw + (size_t)l * D_ * D_;
        const float* vwl = vw + (size_t)l * D_ * D_;
        const float* owl = ow + (size_t)l * D_ * D_;
        const float* w1l = w1 + (size_t)l * DFF_ * D_;
        const float* w2l = w2 + (size_t)l * D_ * DFF_;

        // fused QKV projection: W = [qw; kw; vw] (2304 x 768), Q pre-scaled
        {
            const int R3 = 3 * ((D_ * D_) >> 2);
            cvt3_kernel<<<(R3 + 255) / 256, 256>>>(qwl, kwl, vwl, wf);
        }
        pack_bias_kernel<<<(NQKV + 255) / 256, 256>>>(qb + l * D_, kb + l * D_, vb + l * D_, bqkv);
        run_gemm<1>(xf, wf, bqkv, fff, MROWS, NQKV, D_);

        // banded attention on packed QKV
        {
            dim3 grid(S_ / 128, H_, B_);
            attn_mma_kernel<<<grid, 256, ATT_SMEM>>>(
                fff, fff + D_, fff + 2 * D_, NQKV, of);
        }

        // output projection: split-K=3 partials, reduced inside add_ln3
        run_cvt(owl, wf, D_ * D_);
        run_gemm_sk(of, wf, tmp, MROWS, D_, D_);
        add_ln3_kernel<<<MROWS, 256>>>(x, tmp, ob + l * D_, g1 + l * D_, be1 + l * D_, x, xf);

        // FFN
        run_cvt(w1l, wf, DFF_ * D_);
        run_gemm<2>(xf, wf, b1 + l * DFF_, fff, MROWS, DFF_, D_);
        run_cvt(w2l, wf, D_ * DFF_);
        run_gemm_sk(fff, wf, tmp, MROWS, D_, DFF_);
        // last LN writes the final output directly to d_out
        float* xout = (l == L_ - 1) ? (float*)d_out : x;
        add_ln3_kernel<<<MROWS, 256>>>(x, tmp, b2 + l * D_, g2 + l * D_, be2 + l * D_, xout, xf);
    }
}

// round 12
// speedup vs baseline: 1.0503x; 1.0334x over previous
#include <cuda_runtime.h>
#include <cuda_bf16.h>
#include <cuda_fp16.h>
#include <cstdint>

// Problem constants
#define B_ 2
#define S_ 2048
#define D_ 768
#define H_ 12
#define DH_ 64
#define L_ 2
#define DFF_ 3072
#define MROWS (B_ * S_)   // 4096
#define NQKV 2304
#define KSPLIT 3

// ---------------------------------------------------------------------------
// Scratch (static device globals — no allocation allowed)
// ---------------------------------------------------------------------------
__device__ float g_x  [MROWS * D_];
__device__ float g_tmp[KSPLIT * MROWS * D_];   // split-K partials
__device__ float g_bq2[L_ * NQKV];
__device__ __half g_xf [MROWS * D_];
__device__ __half g_of [MROWS * D_];
__device__ __half g_fff[MROWS * DFF_];         // QKV (M x 2304) / FFN1 (M x 3072)
__device__ __half g_wqkv[L_ * NQKV * D_];
__device__ __half g_wo  [L_ * D_ * D_];
__device__ __half g_w1c [L_ * DFF_ * D_];
__device__ __half g_w2c [L_ * D_ * DFF_];

// ---------------------------------------------------------------------------
// Baseline-PTX tensor-core helpers
// ---------------------------------------------------------------------------
__device__ __forceinline__ uint32_t smem_u32(const void* p) {
    uint32_t a;
    asm("{ .reg .u64 t; cvta.to.shared.u64 t, %1; cvt.u32.u64 %0, t; }"
        : "=r"(a) : "l"(p));
    return a;
}
__device__ __forceinline__ void ldsm_x4(uint32_t& r0, uint32_t& r1,
                                        uint32_t& r2, uint32_t& r3, uint32_t a) {
    asm volatile("ldmatrix.sync.aligned.m8n8.x4.shared.b16 {%0,%1,%2,%3}, [%4];"
                 : "=r"(r0), "=r"(r1), "=r"(r2), "=r"(r3) : "r"(a));
}
__device__ __forceinline__ void ldsm_x2(uint32_t& r0, uint32_t& r1, uint32_t a) {
    asm volatile("ldmatrix.sync.aligned.m8n8.x2.shared.b16 {%0,%1}, [%2];"
                 : "=r"(r0), "=r"(r1) : "r"(a));
}
__device__ __forceinline__ void ldsm_x2t(uint32_t& r0, uint32_t& r1, uint32_t a) {
    asm volatile("ldmatrix.sync.aligned.m8n8.x2.trans.shared.b16 {%0,%1}, [%2];"
                 : "=r"(r0), "=r"(r1) : "r"(a));
}
__device__ __forceinline__ void mma_f16(float* d, const uint32_t* a, const uint32_t* b) {
    asm volatile(
        "mma.sync.aligned.m16n8k16.row.col.f32.f16.f16.f32 "
        "{%0,%1,%2,%3}, {%4,%5,%6,%7}, {%8,%9}, {%0,%1,%2,%3};"
        : "+f"(d[0]), "+f"(d[1]), "+f"(d[2]), "+f"(d[3])
        : "r"(a[0]), "r"(a[1]), "r"(a[2]), "r"(a[3]), "r"(b[0]), "r"(b[1]));
}
#define CP16(dst, src) \
    asm volatile("cp.async.cg.shared.global [%0], [%1], 16;" :: "r"(dst), "l"(src))
#define CP_COMMIT() asm volatile("cp.async.commit_group;" ::: "memory")
#define CP_WAIT0()  asm volatile("cp.async.wait_group 0;" ::: "memory")
#define CP_WAIT1()  asm volatile("cp.async.wait_group 1;" ::: "memory")

__device__ __forceinline__ uint32_t packh(float a, float b) {
    __half2 t = __floats2half2_rn(a, b);
    return *(uint32_t*)&t;
}

// ---------------------------------------------------------------------------
// Convert fp32 -> fp16 (single source)
// ---------------------------------------------------------------------------
__global__ __launch_bounds__(256) void cvt_kernel(
    const float* __restrict__ in, __half* __restrict__ out, int n4)
{
    int i = blockIdx.x * blockDim.x + threadIdx.x;
    if (i >= n4) return;
    float4 x = ((const float4*)in)[i];
    __half2* op = (__half2*)out;
    op[2 * i + 0] = __floats2half2_rn(x.x, x.y);
    op[2 * i + 1] = __floats2half2_rn(x.z, x.w);
}

// ---------------------------------------------------------------------------
// Per-layer weight prep: converts qw|kw|vw -> wqkv, ow -> wo, w1 -> w1c,
// w2 -> w2c (all fp32->fp16, float4 granularity) and packs qkv bias.
// All region sizes are compile-time constants.
// ---------------------------------------------------------------------------
#define RQ ((D_ * D_) >> 2)          // 147456 f4 units per D*D matrix
#define RW ((DFF_ * D_) >> 2)        // 589824 f4 units per DFF*D matrix
#define PREP_B0 (3 * RQ)             // end of wqkv
#define PREP_B1 (PREP_B0 + RQ)       // end of wo
#define PREP_B2 (PREP_B1 + RW)       // end of w1
#define PREP_B3 (PREP_B2 + RW)       // end of w2
#define PREP_TOTAL (PREP_B3 + NQKV)  // + bias elements

__global__ __launch_bounds__(256) void prep_kernel(
    const float* __restrict__ qw, const float* __restrict__ kw,
    const float* __restrict__ vw, const float* __restrict__ qb,
    const float* __restrict__ kb, const float* __restrict__ vb,
    const float* __restrict__ ow, const float* __restrict__ w1,
    const float* __restrict__ w2,
    __half* __restrict__ wqkv, float* __restrict__ bq,
    __half* __restrict__ wo, __half* __restrict__ w1c, __half* __restrict__ w2c)
{
    const int i = blockIdx.x * 256 + threadIdx.x;
    if (i >= PREP_TOTAL) return;
    if (i >= PREP_B3) {   // bias pack
        const int j = i - PREP_B3;
        float v;
        if (j < D_)          v = qb[j];
        else if (j < 2 * D_) v = kb[j - D_];
        else                 v = vb[j - 2 * D_];
        bq[j] = v;
        return;
    }
    const float* src;
    __half* dst;
    int j;
    if (i < PREP_B0) {
        j = i;
        if (j < RQ)          src = qw;
        else if (j < 2 * RQ) { src = kw; }
        else                 { src = vw; }
        dst = wqkv;
        // j stays the flat index into the concatenated [qw;kw;vw] fp16 buffer
        const float* s = (j < RQ) ? qw : (j < 2 * RQ) ? kw : vw;
        const int jj = (j < RQ) ? j : (j < 2 * RQ) ? j - RQ : j - 2 * RQ;
        float4 x = ((const float4*)s)[jj];
        __half2* op = (__half2*)dst;
        op[2 * j + 0] = __floats2half2_rn(x.x, x.y);
        op[2 * j + 1] = __floats2half2_rn(x.z, x.w);
        return;
    } else if (i < PREP_B1) {
        j = i - PREP_B0; src = ow; dst = wo;
    } else if (i < PREP_B2) {
        j = i - PREP_B1; src = w1; dst = w1c;
    } else {
        j = i - PREP_B2; src = w2; dst = w2c;
    }
    float4 x = ((const float4*)src)[j];
    __half2* op = (__half2*)dst;
    op[2 * j + 0] = __floats2half2_rn(x.x, x.y);
    op[2 * j + 1] = __floats2half2_rn(x.z, x.w);
}

// ---------------------------------------------------------------------------
// fp16 mma.sync GEMM (R9 champion config): C = A[M,K] @ W[N,K]^T (+bias)
// 128x128 CTA tile, BK=64, 8 warps (2x4), warp tile 64x32, 256 threads,
// 2 CTAs/SM. 2-stage cp.async pipeline, 1 barrier per chunk.
// Split-K via blockIdx.z.
// EPI: 1 = fp16 out (+bias, x0.125 for n<768); 2 = relu + fp16 out (+bias);
//      3 = raw fp32 partial (no bias), at C + z*M*N
// ---------------------------------------------------------------------------
#define RS_B 144             // smem row stride bytes (64 halves = 128B + 16 pad)
#define TILE_B (128 * RS_B)  // 18432
#define STAGE_B (2 * TILE_B) // A + B
#define GEMM_SMEM (2 * STAGE_B)  // 73728

template <int EPI>
__global__ __launch_bounds__(256, 2) void gemm_mma_kernel(
    const __half* __restrict__ A, const __half* __restrict__ W,
    const float* __restrict__ bias, float* __restrict__ C,
    __half* __restrict__ Hf, int M, int N, int K, int klen)
{
    extern __shared__ char smem[];
    const uint32_t sb = smem_u32(smem);

    const int tid = threadIdx.x;
    const int wid = tid >> 5;
    const int lane = tid & 31;
    const int warp_m = wid >> 2;
    const int warp_n = wid & 3;
    const int bm = blockIdx.y * 128;
    const int bn = blockIdx.x * 128;
    const int kstart = blockIdx.z * klen;

    float acc[4][4][4];
#pragma unroll
    for (int mi = 0; mi < 4; mi++)
#pragma unroll
        for (int ni = 0; ni < 4; ni++)
#pragma unroll
            for (int r = 0; r < 4; r++) acc[mi][ni][r] = 0.f;

    auto load_chunk = [&](int kc, int stage) {
        const uint32_t base = sb + stage * STAGE_B;
#pragma unroll
        for (int t = 0; t < 4; t++) {
            const int idx = tid + t * 256;
            const int lr = idx >> 3, ls = idx & 7;
            CP16(base + lr * RS_B + ls * 16,
                 A + (size_t)(bm + lr) * K + kstart + kc + ls * 8);
        }
#pragma unroll
        for (int t = 0; t < 4; t++) {
            const int idx = tid + t * 256;
            const int lr = idx >> 3, ls = idx & 7;
            CP16(base + TILE_B + lr * RS_B + ls * 16,
                 W + (size_t)(bn + lr) * K + kstart + kc + ls * 8);
        }
    };

    const int arow = warp_m * 64 + (lane & 15);
    const int akb  = (lane >> 4) * 8;
    const int bg_ni = (lane >> 4);
    const int bg_kh = ((lane >> 3) & 1) * 8;
    const int brow_l = lane & 7;

    auto compute = [&](int stage) {
        const uint32_t base = sb + stage * STAGE_B;
        const uint32_t pA = base;
        const uint32_t pB = base + TILE_B;
#pragma unroll
        for (int ks = 0; ks < 4; ks++) {
            const int k0 = ks * 16;
            uint32_t af[4][4], bf[4][2];
#pragma unroll
            for (int mi = 0; mi < 4; mi++) {
                const uint32_t ro = (uint32_t)(arow + mi * 16) * RS_B + (k0 + akb) * 2;
                ldsm_x4(af[mi][0], af[mi][1], af[mi][2], af[mi][3], pA + ro);
            }
#pragma unroll
            for (int np = 0; np < 2; np++) {
                const int nrow = warp_n * 32 + (np * 2 + bg_ni) * 8 + brow_l;
                const uint32_t ro = (uint32_t)nrow * RS_B + (k0 + bg_kh) * 2;
                ldsm_x4(bf[np * 2][0], bf[np * 2][1], bf[np * 2 + 1][0], bf[np * 2 + 1][1], pB + ro);
            }
#pragma unroll
            for (int mi = 0; mi < 4; mi++)
#pragma unroll
                for (int ni = 0; ni < 4; ni++)
                    mma_f16(acc[mi][ni], af[mi], bf[ni]);
        }
    };

    const int nchunks = klen >> 6;
    load_chunk(0, 0);
    CP_COMMIT();

    for (int c = 0; c < nchunks; c++) {
        CP_WAIT0();
        __syncthreads();
        if (c + 1 < nchunks) {
            load_chunk((c + 1) << 6, (c + 1) & 1);
            CP_COMMIT();
        }
        compute(c & 1);
    }

    // epilogue
    float* Cz = (EPI == 3) ? (C + (size_t)blockIdx.z * M * N) : C;
#pragma unroll
    for (int mi = 0; mi < 4; mi++) {
        const int m0 = bm + warp_m * 64 + mi * 16 + (lane >> 2);
#pragma unroll
        for (int ni = 0; ni < 4; ni++) {
            const int n0 = bn + warp_n * 32 + ni * 8 + (lane & 3) * 2;
            float v00 = acc[mi][ni][0], v01 = acc[mi][ni][1];
            float v10 = acc[mi][ni][2], v11 = acc[mi][ni][3];
            if (EPI != 3) {
                const float bx = bias[n0], by = bias[n0 + 1];
                v00 += bx; v01 += by; v10 += bx; v11 += by;
            }
            if (EPI == 1) {
                const float sc = (n0 < 768) ? 0.125f : 1.0f;  // Q pre-scale (exact 2^-3)
                v00 *= sc; v01 *= sc; v10 *= sc; v11 *= sc;
            }
            if (EPI == 2) {
                v00 = fmaxf(v00, 0.f); v01 = fmaxf(v01, 0.f);
                v10 = fmaxf(v10, 0.f); v11 = fmaxf(v11, 0.f);
            }
            if (EPI == 3) {
                *(float2*)(Cz + (size_t)m0 * N + n0) = make_float2(v00, v01);
                *(float2*)(Cz + (size_t)(m0 + 8) * N + n0) = make_float2(v10, v11);
            } else {
                *(uint32_t*)(Hf + (size_t)m0 * N + n0) = packh(v00, v01);
                *(uint32_t*)(Hf + (size_t)(m0 + 8) * N + n0) = packh(v10, v11);
            }
        }
    }
}

// ---------------------------------------------------------------------------
// Tensor-core banded flash attention, fp16, band-aware MMA skipping.
// ---------------------------------------------------------------------------
#define ATT_RSB 144
#define ATT_TILE_B (128 * ATT_RSB)        // 18432
#define ATT_SMEM (5 * ATT_TILE_B)         // Q + 2 stages x (K,V) = 92160

__global__ __launch_bounds__(256) void attn_mma_kernel(
    const __half* __restrict__ Qf, const __half* __restrict__ Kf,
    const __half* __restrict__ Vf, int ldq, __half* __restrict__ Of)
{
    extern __shared__ char smem[];
    const uint32_t sb = smem_u32(smem);
    const int b = blockIdx.z;
    const int h = blockIdx.y;
    const int qt = blockIdx.x;
    const int q0 = qt * 128;
    const int tid = threadIdx.x;
    const int wid = tid >> 5;
    const int lane = tid & 31;
    const int g = lane >> 2;
    const int tq = lane & 3;

    const uint32_t sQ = sb;
    const uint32_t sKV0 = sb + ATT_TILE_B;

    {
        const int row = tid >> 1, seg = tid & 1;
#pragma unroll
        for (int t = 0; t < 4; t++) {
            const size_t go = (size_t)(b * S_ + q0 + row) * ldq + h * 64 + (seg * 4 + t) * 8;
            CP16(sQ + (uint32_t)row * ATT_RSB + (seg * 4 + t) * 16, Qf + go);
        }
    }
    CP_COMMIT();

    const int kt_lo = (qt - 2 < 0) ? 0 : qt - 2;
    const int kt_hi = (qt + 2 > S_ / 128 - 1) ? S_ / 128 - 1 : qt + 2;

    auto load_kv = [&](int kt, int stg) {
        const uint32_t base = sKV0 + stg * 2 * ATT_TILE_B;
        const int row = tid >> 1, seg = tid & 1;
#pragma unroll
        for (int t = 0; t < 4; t++) {
            const size_t go = (size_t)(b * S_ + kt * 128 + row) * ldq + h * 64 + (seg * 4 + t) * 8;
            const uint32_t so = (uint32_t)row * ATT_RSB + (seg * 4 + t) * 16;
            CP16(base + so,              Kf + go);
            CP16(base + ATT_TILE_B + so, Vf + go);
        }
    };
    load_kv(kt_lo, 0);
    CP_COMMIT();

    CP_WAIT1();
    __syncthreads();

    uint32_t qf[4][4];
    {
        const int arow = wid * 16 + (lane & 15);
        const int akb = (lane >> 4) * 8;
#pragma unroll
        for (int ks = 0; ks < 4; ks++) {
            const uint32_t ro = (uint32_t)arow * ATT_RSB + (ks * 16 + akb) * 2;
            ldsm_x4(qf[ks][0], qf[ks][1], qf[ks][2], qf[ks][3], sQ + ro);
        }
    }

    float m0 = -1e30f, m1 = -1e30f, l0 = 0.f, l1 = 0.f;
    float o[8][4];
#pragma unroll
    for (int nd = 0; nd < 8; nd++)
#pragma unroll
        for (int r = 0; r < 4; r++) o[nd][r] = 0.f;

    const int rlo = q0 + wid * 16;
    const int row0 = rlo + g;
    const int brow0 = lane & 7;
    const int bkb = ((lane >> 3) & 1) * 8;
    const int vrow = lane & 15;

    for (int kt = kt_lo; kt <= kt_hi; kt++) {
        const int stg = (kt - kt_lo) & 1;
        if (kt < kt_hi) {
            load_kv(kt + 1, stg ^ 1);
            CP_COMMIT();
            CP_WAIT1();
        } else {
            CP_WAIT0();
        }
        __syncthreads();

        const uint32_t base = sKV0 + stg * 2 * ATT_TILE_B;
        const uint32_t pK = base, pV = base + ATT_TILE_B;

        const int cbase = kt * 128;
        const int T1 = rlo - 256 - cbase;
        const int T2 = rlo + 15 + 256 - cbase;
        int ntlo = (T1 > 0) ? (T1 >> 3) : 0;
        int nthi = (T2 < 0) ? -1 : (T2 >> 3);
        if (nthi > 15) nthi = 15;

        float s[16][4];
#pragma unroll
        for (int nt = 0; nt < 16; nt++)
#pragma unroll
            for (int r = 0; r < 4; r++) s[nt][r] = 0.f;
#pragma unroll
        for (int ks = 0; ks < 4; ks++) {
#pragma unroll
            for (int nt = 0; nt < 16; nt++) {
                if (nt < ntlo || nt > nthi) continue;
                uint32_t bk[2];
                const uint32_t ro = (uint32_t)(nt * 8 + brow0) * ATT_RSB + (ks * 16 + bkb) * 2;
                ldsm_x2(bk[0], bk[1], pK + ro);
                mma_f16(s[nt], qf[ks], bk);
            }
        }

        float rmax0 = -1e30f, rmax1 = -1e30f;
#pragma unroll
        for (int nt = 0; nt < 16; nt++) {
            if (nt < ntlo || nt > nthi) continue;
            const int col = cbase + nt * 8 + tq * 2;
            const bool i00 = (unsigned)(row0 - col + 256) <= 512u;
            const bool i01 = (unsigned)(row0 - col - 1 + 256) <= 512u;
            const bool i10 = (unsigned)(row0 + 8 - col + 256) <= 512u;
            const bool i11 = (unsigned)(row0 + 8 - col - 1 + 256) <= 512u;
            s[nt][0] = i00 ? s[nt][0] : -1e30f;
            s[nt][1] = i01 ? s[nt][1] : -1e30f;
            s[nt][2] = i10 ? s[nt][2] : -1e30f;
            s[nt][3] = i11 ? s[nt][3] : -1e30f;
            rmax0 = fmaxf(rmax0, fmaxf(s[nt][0], s[nt][1]));
            rmax1 = fmaxf(rmax1, fmaxf(s[nt][2], s[nt][3]));
        }
        rmax0 = fmaxf(rmax0, __shfl_xor_sync(0xffffffffu, rmax0, 1));
        rmax0 = fmaxf(rmax0, __shfl_xor_sync(0xffffffffu, rmax0, 2));
        rmax1 = fmaxf(rmax1, __shfl_xor_sync(0xffffffffu, rmax1, 1));
        rmax1 = fmaxf(rmax1, __shfl_xor_sync(0xffffffffu, rmax1, 2));

        const float nm0 = fmaxf(m0, rmax0);
        const float nm1 = fmaxf(m1, rmax1);
        const float c0 = __expf(m0 - nm0);
        const float c1 = __expf(m1 - nm1);
        m0 = nm0; m1 = nm1;

        float add0 = 0.f, add1 = 0.f;
        uint32_t p[16][2];
#pragma unroll
        for (int nt = 0; nt < 16; nt++) {
            if (nt < ntlo || nt > nthi) { p[nt][0] = 0; p[nt][1] = 0; continue; }
            const float p00 = __expf(s[nt][0] - nm0);
            const float p01 = __expf(s[nt][1] - nm0);
            const float p10 = __expf(s[nt][2] - nm1);
            const float p11 = __expf(s[nt][3] - nm1);
            add0 += p00 + p01;
            add1 += p10 + p11;
            p[nt][0] = packh(p00, p01);
            p[nt][1] = packh(p10, p11);
        }
        add0 += __shfl_xor_sync(0xffffffffu, add0, 1);
        add0 += __shfl_xor_sync(0xffffffffu, add0, 2);
        add1 += __shfl_xor_sync(0xffffffffu, add1, 1);
        add1 += __shfl_xor_sync(0xffffffffu, add1, 2);
        l0 = l0 * c0 + add0;
        l1 = l1 * c1 + add1;
#pragma unroll
        for (int nd = 0; nd < 8; nd++) {
            o[nd][0] *= c0; o[nd][1] *= c0;
            o[nd][2] *= c1; o[nd][3] *= c1;
        }

#pragma unroll
        for (int ks = 0; ks < 8; ks++) {
            if (2 * ks + 1 < ntlo || 2 * ks > nthi) continue;
            uint32_t a[4] = {p[2 * ks][0], p[2 * ks][1], p[2 * ks + 1][0], p[2 * ks + 1][1]};
#pragma unroll
            for (int nd = 0; nd < 8; nd++) {
                uint32_t bv[2];
                const uint32_t ro = (uint32_t)(ks * 16 + vrow) * ATT_RSB + nd * 16;
                ldsm_x2t(bv[0], bv[1], pV + ro);
                mma_f16(o[nd], a, bv);
            }
        }
        __syncthreads();
    }

    const float inv0 = 1.f / l0;
    const float inv1 = 1.f / l1;
#pragma unroll
    for (int nd = 0; nd < 8; nd++) {
        const int d = nd * 8 + tq * 2;
        const size_t o0 = (size_t)(b * S_ + row0) * D_ + h * 64 + d;
        const size_t o1 = (size_t)(b * S_ + row0 + 8) * D_ + h * 64 + d;
        *(uint32_t*)(Of + o0) = packh(o[nd][0] * inv0, o[nd][1] * inv0);
        *(uint32_t*)(Of + o1) = packh(o[nd][2] * inv1, o[nd][3] * inv1);
    }
}

// ---------------------------------------------------------------------------
// Fused split-K reduce + bias + residual add + LayerNorm.
// val = res + (p0 + p1 + p2) + bias;  then LN -> xout fp32 + xf fp16
// ---------------------------------------------------------------------------
__global__ __launch_bounds__(256) void add_ln3_kernel(
    const float* __restrict__ res, const float* __restrict__ parts,
    const float* __restrict__ bias,
    const float* __restrict__ g, const float* __restrict__ be,
    float* __restrict__ xout, __half* __restrict__ xf)
{
    const int row = blockIdx.x;
    const int tid = threadIdx.x;
    const float* xp = res + (size_t)row * D_;
    const float* p0 = parts + (size_t)row * D_;
    const float* p1 = parts + (size_t)MROWS * D_ + (size_t)row * D_;
    const float* p2 = parts + 2 * (size_t)MROWS * D_ + (size_t)row * D_;

    float v[3];
    float s1 = 0.f, s2 = 0.f;
#pragma unroll
    for (int i = 0; i < 3; i++) {
        const int c = tid + 256 * i;
        v[i] = xp[c] + ((p0[c] + p1[c]) + p2[c]) + bias[c];
        s1 += v[i];
        s2 += v[i] * v[i];
    }
#pragma unroll
    for (int off = 16; off; off >>= 1) {
        s1 += __shfl_xor_sync(0xffffffffu, s1, off);
        s2 += __shfl_xor_sync(0xffffffffu, s2, off);
    }
    __shared__ float r1[8], r2[8];
    if ((tid & 31) == 0) { r1[tid >> 5] = s1; r2[tid >> 5] = s2; }
    __syncthreads();
    s1 = 0.f; s2 = 0.f;
#pragma unroll
    for (int i = 0; i < 8; i++) { s1 += r1[i]; s2 += r2[i]; }

    const float mean = s1 * (1.f / 768.f);
    const float var  = s2 * (1.f / 768.f) - mean * mean;
    const float rstd = rsqrtf(var + 1e-5f);
#pragma unroll
    for (int i = 0; i < 3; i++) {
        const int c = tid + 256 * i;
        const float val = (v[i] - mean) * rstd * g[c] + be[c];
        xout[(size_t)row * D_ + c] = val;
        xf[(size_t)row * D_ + c] = __float2half_rn(val);
    }
}

// ---------------------------------------------------------------------------
// Host orchestration
// ---------------------------------------------------------------------------
template <int EPI>
static void run_gemm(const __half* A, const __half* W, const float* bias,
                     __half* Hf, int M, int N, int K)
{
    dim3 grid(N / 128, M / 128, 1);
    gemm_mma_kernel<EPI><<<grid, 256, GEMM_SMEM>>>(A, W, bias, nullptr, Hf, M, N, K, K);
}

// split-K=3 raw-partial GEMM (EPI=3)
static void run_gemm_sk(const __half* A, const __half* W, float* Cparts,
                        int M, int N, int K)
{
    dim3 grid(N / 128, M / 128, KSPLIT);
    gemm_mma_kernel<3><<<grid, 256, GEMM_SMEM>>>(A, W, nullptr, Cparts, nullptr,
                                                 M, N, K, K / KSPLIT);
}

extern "C" void kernel_launch(void* const* d_in, const int* in_sizes, int n_in,
                              void* d_out, int out_size)
{
    const float* src = (const float*)d_in[0];
    const float* qw  = (const float*)d_in[1];
    const float* qb  = (const float*)d_in[2];
    const float* kw  = (const float*)d_in[3];
    const float* kb  = (const float*)d_in[4];
    const float* vw  = (const float*)d_in[5];
    const float* vb  = (const float*)d_in[6];
    const float* ow  = (const float*)d_in[7];
    const float* ob  = (const float*)d_in[8];
    const float* w1  = (const float*)d_in[9];
    const float* b1  = (const float*)d_in[10];
    const float* w2  = (const float*)d_in[11];
    const float* b2  = (const float*)d_in[12];
    const float* g1  = (const float*)d_in[13];
    const float* be1 = (const float*)d_in[14];
    const float* g2  = (const float*)d_in[15];
    const float* be2 = (const float*)d_in[16];

    cudaFuncSetAttribute((const void*)gemm_mma_kernel<1>, cudaFuncAttributeMaxDynamicSharedMemorySize, GEMM_SMEM);
    cudaFuncSetAttribute((const void*)gemm_mma_kernel<2>, cudaFuncAttributeMaxDynamicSharedMemorySize, GEMM_SMEM);
    cudaFuncSetAttribute((const void*)gemm_mma_kernel<3>, cudaFuncAttributeMaxDynamicSharedMemorySize, GEMM_SMEM);
    cudaFuncSetAttribute((const void*)attn_mma_kernel, cudaFuncAttributeMaxDynamicSharedMemorySize, ATT_SMEM);

    float *x, *tmp, *bq2;
    __half *xf, *of, *fff, *wqkv, *wo, *w1c, *w2c;
    cudaGetSymbolAddress((void**)&x,    g_x);
    cudaGetSymbolAddress((void**)&tmp,  g_tmp);
    cudaGetSymbolAddress((void**)&bq2,  g_bq2);
    cudaGetSymbolAddress((void**)&xf,   g_xf);
    cudaGetSymbolAddress((void**)&of,   g_of);
    cudaGetSymbolAddress((void**)&fff,  g_fff);
    cudaGetSymbolAddress((void**)&wqkv, g_wqkv);
    cudaGetSymbolAddress((void**)&wo,   g_wo);
    cudaGetSymbolAddress((void**)&w1c,  g_w1c);
    cudaGetSymbolAddress((void**)&w2c,  g_w2c);

    // all weight conversions + bias packs up front (one launch per layer)
    const int prep_blocks = (PREP_TOTAL + 255) / 256;
    for (int l = 0; l < L_; l++) {
        prep_kernel<<<prep_blocks, 256>>>(
            qw + (size_t)l * D_ * D_, kw + (size_t)l * D_ * D_,
            vw + (size_t)l * D_ * D_,
            qb + l * D_, kb + l * D_, vb + l * D_,
            ow + (size_t)l * D_ * D_,
            w1 + (size_t)l * DFF_ * D_, w2 + (size_t)l * D_ * DFF_,
            wqkv + (size_t)l * NQKV * D_, bq2 + l * NQKV,
            wo + (size_t)l * D_ * D_,
            w1c + (size_t)l * DFF_ * D_, w2c + (size_t)l * D_ * DFF_);
    }

    // src -> fp16 activations
    {
        const int n4 = (MROWS * D_) >> 2;
        cvt_kernel<<<(n4 + 255) / 256, 256>>>(src, xf, n4);
    }

    for (int l = 0; l < L_; l++) {
        const __half* wqkv_l = wqkv + (size_t)l * NQKV * D_;
        const __half* wo_l   = wo   + (size_t)l * D_ * D_;
        const __half* w1_l   = w1c  + (size_t)l * DFF_ * D_;
        const __half* w2_l   = w2c  + (size_t)l * D_ * DFF_;

        // fused QKV projection (Q pre-scaled in epilogue)
        run_gemm<1>(xf, wqkv_l, bq2 + l * NQKV, fff, MROWS, NQKV, D_);

        // banded attention on packed QKV
        {
            dim3 grid(S_ / 128, H_, B_);
            attn_mma_kernel<<<grid, 256, ATT_SMEM>>>(
                fff, fff + D_, fff + 2 * D_, NQKV, of);
        }

        // output projection: split-K=3 partials, reduced inside add_ln3.
        // residual source is src for layer 0 (saves the initial memcpy).
        run_gemm_sk(of, wo_l, tmp, MROWS, D_, D_);
        const float* res0 = (l == 0) ? src : x;
        add_ln3_kernel<<<MROWS, 256>>>(res0, tmp, ob + l * D_, g1 + l * D_, be1 + l * D_, x, xf);

        // FFN
        run_gemm<2>(xf, w1_l, b1 + l * DFF_, fff, MROWS, DFF_, D_);
        run_gemm_sk(fff, w2_l, tmp, MROWS, D_, DFF_);
        // last LN writes the final output directly to d_out
        float* xout = (l == L_ - 1) ? (float*)d_out : x;
        add_ln3_kernel<<<MROWS, 256>>>(x, tmp, b2 + l * D_, g2 + l * D_, be2 + l * D_, xout, xf);
    }
}

// round 13
// speedup vs baseline: 1.0609x; 1.0101x over previous
#include <cuda_runtime.h>
#include <cuda_bf16.h>
#include <cuda_fp16.h>
#include <cstdint>

// Problem constants
#define B_ 2
#define S_ 2048
#define D_ 768
#define H_ 12
#define DH_ 64
#define L_ 2
#define DFF_ 3072
#define MROWS (B_ * S_)   // 4096
#define NQKV 2304
#define KSPLIT 3

// ---------------------------------------------------------------------------
// Scratch (static device globals — no allocation allowed)
// ---------------------------------------------------------------------------
__device__ float g_x  [MROWS * D_];
__device__ float g_bq2[L_ * NQKV];
__device__ __half g_pf [KSPLIT * MROWS * D_];  // split-K fp16 partials
__device__ __half g_xf [MROWS * D_];
__device__ __half g_of [MROWS * D_];
__device__ __half g_fff[MROWS * DFF_];         // QKV (M x 2304) / FFN1 (M x 3072)
__device__ __half g_wqkv[L_ * NQKV * D_];
__device__ __half g_wo  [L_ * D_ * D_];
__device__ __half g_w1c [L_ * DFF_ * D_];
__device__ __half g_w2c [L_ * D_ * DFF_];

// ---------------------------------------------------------------------------
// Baseline-PTX tensor-core helpers
// ---------------------------------------------------------------------------
__device__ __forceinline__ uint32_t smem_u32(const void* p) {
    uint32_t a;
    asm("{ .reg .u64 t; cvta.to.shared.u64 t, %1; cvt.u32.u64 %0, t; }"
        : "=r"(a) : "l"(p));
    return a;
}
__device__ __forceinline__ void ldsm_x4(uint32_t& r0, uint32_t& r1,
                                        uint32_t& r2, uint32_t& r3, uint32_t a) {
    asm volatile("ldmatrix.sync.aligned.m8n8.x4.shared.b16 {%0,%1,%2,%3}, [%4];"
                 : "=r"(r0), "=r"(r1), "=r"(r2), "=r"(r3) : "r"(a));
}
__device__ __forceinline__ void ldsm_x2(uint32_t& r0, uint32_t& r1, uint32_t a) {
    asm volatile("ldmatrix.sync.aligned.m8n8.x2.shared.b16 {%0,%1}, [%2];"
                 : "=r"(r0), "=r"(r1) : "r"(a));
}
__device__ __forceinline__ void ldsm_x2t(uint32_t& r0, uint32_t& r1, uint32_t a) {
    asm volatile("ldmatrix.sync.aligned.m8n8.x2.trans.shared.b16 {%0,%1}, [%2];"
                 : "=r"(r0), "=r"(r1) : "r"(a));
}
__device__ __forceinline__ void mma_f16(float* d, const uint32_t* a, const uint32_t* b) {
    asm volatile(
        "mma.sync.aligned.m16n8k16.row.col.f32.f16.f16.f32 "
        "{%0,%1,%2,%3}, {%4,%5,%6,%7}, {%8,%9}, {%0,%1,%2,%3};"
        : "+f"(d[0]), "+f"(d[1]), "+f"(d[2]), "+f"(d[3])
        : "r"(a[0]), "r"(a[1]), "r"(a[2]), "r"(a[3]), "r"(b[0]), "r"(b[1]));
}
#define CP16(dst, src) \
    asm volatile("cp.async.cg.shared.global [%0], [%1], 16;" :: "r"(dst), "l"(src))
#define CP_COMMIT() asm volatile("cp.async.commit_group;" ::: "memory")
#define CP_WAIT0()  asm volatile("cp.async.wait_group 0;" ::: "memory")
#define CP_WAIT1()  asm volatile("cp.async.wait_group 1;" ::: "memory")

__device__ __forceinline__ uint32_t packh(float a, float b) {
    __half2 t = __floats2half2_rn(a, b);
    return *(uint32_t*)&t;
}

// ---------------------------------------------------------------------------
// Convert fp32 -> fp16 (single source)
// ---------------------------------------------------------------------------
__global__ __launch_bounds__(256) void cvt_kernel(
    const float* __restrict__ in, __half* __restrict__ out, int n4)
{
    int i = blockIdx.x * blockDim.x + threadIdx.x;
    if (i >= n4) return;
    float4 x = ((const float4*)in)[i];
    __half2* op = (__half2*)out;
    op[2 * i + 0] = __floats2half2_rn(x.x, x.y);
    op[2 * i + 1] = __floats2half2_rn(x.z, x.w);
}

// ---------------------------------------------------------------------------
// Weight prep for ALL layers in one launch (blockIdx.y = layer):
// qw|kw|vw -> wqkv, ow -> wo, w1 -> w1c, w2 -> w2c, and packs qkv bias.
// ---------------------------------------------------------------------------
#define RQ ((D_ * D_) >> 2)          // f4 units per D*D matrix
#define RW ((DFF_ * D_) >> 2)        // f4 units per DFF*D matrix
#define PREP_B0 (3 * RQ)
#define PREP_B1 (PREP_B0 + RQ)
#define PREP_B2 (PREP_B1 + RW)
#define PREP_B3 (PREP_B2 + RW)
#define PREP_TOTAL (PREP_B3 + NQKV)

__global__ __launch_bounds__(256) void prep_kernel(
    const float* __restrict__ qw, const float* __restrict__ kw,
    const float* __restrict__ vw, const float* __restrict__ qb,
    const float* __restrict__ kb, const float* __restrict__ vb,
    const float* __restrict__ ow, const float* __restrict__ w1,
    const float* __restrict__ w2,
    __half* __restrict__ wqkv, float* __restrict__ bq,
    __half* __restrict__ wo, __half* __restrict__ w1c, __half* __restrict__ w2c)
{
    const int l = blockIdx.y;
    const int i = blockIdx.x * 256 + threadIdx.x;
    if (i >= PREP_TOTAL) return;

    // per-layer source/dest bases
    const float* qwl = qw + (size_t)l * D_ * D_;
    const float* kwl = kw + (size_t)l * D_ * D_;
    const float* vwl = vw + (size_t)l * D_ * D_;
    const float* owl = ow + (size_t)l * D_ * D_;
    const float* w1l = w1 + (size_t)l * DFF_ * D_;
    const float* w2l = w2 + (size_t)l * D_ * DFF_;
    __half* wqkvl = wqkv + (size_t)l * NQKV * D_;
    __half* wol   = wo   + (size_t)l * D_ * D_;
    __half* w1cl  = w1c  + (size_t)l * DFF_ * D_;
    __half* w2cl  = w2c  + (size_t)l * D_ * DFF_;

    if (i >= PREP_B3) {   // bias pack
        const int j = i - PREP_B3;
        float v;
        if (j < D_)          v = qb[l * D_ + j];
        else if (j < 2 * D_) v = kb[l * D_ + j - D_];
        else                 v = vb[l * D_ + j - 2 * D_];
        bq[l * NQKV + j] = v;
        return;
    }
    const float* src;
    __half* dst;
    int j, oj;
    if (i < PREP_B0) {
        oj = i;
        src = (i < RQ) ? qwl : (i < 2 * RQ) ? kwl : vwl;
        j = (i < RQ) ? i : (i < 2 * RQ) ? i - RQ : i - 2 * RQ;
        dst = wqkvl;
    } else if (i < PREP_B1) {
        j = i - PREP_B0; oj = j; src = owl; dst = wol;
    } else if (i < PREP_B2) {
        j = i - PREP_B1; oj = j; src = w1l; dst = w1cl;
    } else {
        j = i - PREP_B2; oj = j; src = w2l; dst = w2cl;
    }
    float4 x = ((const float4*)src)[j];
    __half2* op = (__half2*)dst;
    op[2 * oj + 0] = __floats2half2_rn(x.x, x.y);
    op[2 * oj + 1] = __floats2half2_rn(x.z, x.w);
}

// ---------------------------------------------------------------------------
// fp16 mma.sync GEMM (R9 champion config): C = A[M,K] @ W[N,K]^T (+bias)
// 128x128 CTA tile, BK=64, 8 warps (2x4), warp tile 64x32, 256 threads,
// 2 CTAs/SM. 2-stage cp.async pipeline, 1 barrier per chunk.
// Split-K via blockIdx.z.
// EPI: 1 = fp16 out (+bias, x0.125 for n<768); 2 = relu + fp16 out (+bias);
//      3 = raw fp16 partial (no bias), at Hf + z*M*N
// ---------------------------------------------------------------------------
#define RS_B 144             // smem row stride bytes (64 halves = 128B + 16 pad)
#define TILE_B (128 * RS_B)  // 18432
#define STAGE_B (2 * TILE_B) // A + B
#define GEMM_SMEM (2 * STAGE_B)  // 73728

template <int EPI>
__global__ __launch_bounds__(256, 2) void gemm_mma_kernel(
    const __half* __restrict__ A, const __half* __restrict__ W,
    const float* __restrict__ bias,
    __half* __restrict__ Hf, int M, int N, int K, int klen)
{
    extern __shared__ char smem[];
    const uint32_t sb = smem_u32(smem);

    const int tid = threadIdx.x;
    const int wid = tid >> 5;
    const int lane = tid & 31;
    const int warp_m = wid >> 2;
    const int warp_n = wid & 3;
    const int bm = blockIdx.y * 128;
    const int bn = blockIdx.x * 128;
    const int kstart = blockIdx.z * klen;

    float acc[4][4][4];
#pragma unroll
    for (int mi = 0; mi < 4; mi++)
#pragma unroll
        for (int ni = 0; ni < 4; ni++)
#pragma unroll
            for (int r = 0; r < 4; r++) acc[mi][ni][r] = 0.f;

    auto load_chunk = [&](int kc, int stage) {
        const uint32_t base = sb + stage * STAGE_B;
#pragma unroll
        for (int t = 0; t < 4; t++) {
            const int idx = tid + t * 256;
            const int lr = idx >> 3, ls = idx & 7;
            CP16(base + lr * RS_B + ls * 16,
                 A + (size_t)(bm + lr) * K + kstart + kc + ls * 8);
        }
#pragma unroll
        for (int t = 0; t < 4; t++) {
            const int idx = tid + t * 256;
            const int lr = idx >> 3, ls = idx & 7;
            CP16(base + TILE_B + lr * RS_B + ls * 16,
                 W + (size_t)(bn + lr) * K + kstart + kc + ls * 8);
        }
    };

    const int arow = warp_m * 64 + (lane & 15);
    const int akb  = (lane >> 4) * 8;
    const int bg_ni = (lane >> 4);
    const int bg_kh = ((lane >> 3) & 1) * 8;
    const int brow_l = lane & 7;

    auto compute = [&](int stage) {
        const uint32_t base = sb + stage * STAGE_B;
        const uint32_t pA = base;
        const uint32_t pB = base + TILE_B;
#pragma unroll
        for (int ks = 0; ks < 4; ks++) {
            const int k0 = ks * 16;
            uint32_t af[4][4], bf[4][2];
#pragma unroll
            for (int mi = 0; mi < 4; mi++) {
                const uint32_t ro = (uint32_t)(arow + mi * 16) * RS_B + (k0 + akb) * 2;
                ldsm_x4(af[mi][0], af[mi][1], af[mi][2], af[mi][3], pA + ro);
            }
#pragma unroll
            for (int np = 0; np < 2; np++) {
                const int nrow = warp_n * 32 + (np * 2 + bg_ni) * 8 + brow_l;
                const uint32_t ro = (uint32_t)nrow * RS_B + (k0 + bg_kh) * 2;
                ldsm_x4(bf[np * 2][0], bf[np * 2][1], bf[np * 2 + 1][0], bf[np * 2 + 1][1], pB + ro);
            }
#pragma unroll
            for (int mi = 0; mi < 4; mi++)
#pragma unroll
                for (int ni = 0; ni < 4; ni++)
                    mma_f16(acc[mi][ni], af[mi], bf[ni]);
        }
    };

    const int nchunks = klen >> 6;
    load_chunk(0, 0);
    CP_COMMIT();

    for (int c = 0; c < nchunks; c++) {
        CP_WAIT0();
        __syncthreads();
        if (c + 1 < nchunks) {
            load_chunk((c + 1) << 6, (c + 1) & 1);
            CP_COMMIT();
        }
        compute(c & 1);
    }

    // epilogue
    __half* Hz = (EPI == 3) ? (Hf + (size_t)blockIdx.z * M * N) : Hf;
#pragma unroll
    for (int mi = 0; mi < 4; mi++) {
        const int m0 = bm + warp_m * 64 + mi * 16 + (lane >> 2);
#pragma unroll
        for (int ni = 0; ni < 4; ni++) {
            const int n0 = bn + warp_n * 32 + ni * 8 + (lane & 3) * 2;
            float v00 = acc[mi][ni][0], v01 = acc[mi][ni][1];
            float v10 = acc[mi][ni][2], v11 = acc[mi][ni][3];
            if (EPI != 3) {
                const float bx = bias[n0], by = bias[n0 + 1];
                v00 += bx; v01 += by; v10 += bx; v11 += by;
            }
            if (EPI == 1) {
                const float sc = (n0 < 768) ? 0.125f : 1.0f;  // Q pre-scale (exact 2^-3)
                v00 *= sc; v01 *= sc; v10 *= sc; v11 *= sc;
            }
            if (EPI == 2) {
                v00 = fmaxf(v00, 0.f); v01 = fmaxf(v01, 0.f);
                v10 = fmaxf(v10, 0.f); v11 = fmaxf(v11, 0.f);
            }
            *(uint32_t*)(Hz + (size_t)m0 * N + n0) = packh(v00, v01);
            *(uint32_t*)(Hz + (size_t)(m0 + 8) * N + n0) = packh(v10, v11);
        }
    }
}

// ---------------------------------------------------------------------------
// Tensor-core banded flash attention, fp16, band-aware MMA skipping.
// ---------------------------------------------------------------------------
#define ATT_RSB 144
#define ATT_TILE_B (128 * ATT_RSB)        // 18432
#define ATT_SMEM (5 * ATT_TILE_B)         // Q + 2 stages x (K,V) = 92160

__global__ __launch_bounds__(256) void attn_mma_kernel(
    const __half* __restrict__ Qf, const __half* __restrict__ Kf,
    const __half* __restrict__ Vf, int ldq, __half* __restrict__ Of)
{
    extern __shared__ char smem[];
    const uint32_t sb = smem_u32(smem);
    const int b = blockIdx.z;
    const int h = blockIdx.y;
    const int qt = blockIdx.x;
    const int q0 = qt * 128;
    const int tid = threadIdx.x;
    const int wid = tid >> 5;
    const int lane = tid & 31;
    const int g = lane >> 2;
    const int tq = lane & 3;

    const uint32_t sQ = sb;
    const uint32_t sKV0 = sb + ATT_TILE_B;

    {
        const int row = tid >> 1, seg = tid & 1;
#pragma unroll
        for (int t = 0; t < 4; t++) {
            const size_t go = (size_t)(b * S_ + q0 + row) * ldq + h * 64 + (seg * 4 + t) * 8;
            CP16(sQ + (uint32_t)row * ATT_RSB + (seg * 4 + t) * 16, Qf + go);
        }
    }
    CP_COMMIT();

    const int kt_lo = (qt - 2 < 0) ? 0 : qt - 2;
    const int kt_hi = (qt + 2 > S_ / 128 - 1) ? S_ / 128 - 1 : qt + 2;

    auto load_kv = [&](int kt, int stg) {
        const uint32_t base = sKV0 + stg * 2 * ATT_TILE_B;
        const int row = tid >> 1, seg = tid & 1;
#pragma unroll
        for (int t = 0; t < 4; t++) {
            const size_t go = (size_t)(b * S_ + kt * 128 + row) * ldq + h * 64 + (seg * 4 + t) * 8;
            const uint32_t so = (uint32_t)row * ATT_RSB + (seg * 4 + t) * 16;
            CP16(base + so,              Kf + go);
            CP16(base + ATT_TILE_B + so, Vf + go);
        }
    };
    load_kv(kt_lo, 0);
    CP_COMMIT();

    CP_WAIT1();
    __syncthreads();

    uint32_t qf[4][4];
    {
        const int arow = wid * 16 + (lane & 15);
        const int akb = (lane >> 4) * 8;
#pragma unroll
        for (int ks = 0; ks < 4; ks++) {
            const uint32_t ro = (uint32_t)arow * ATT_RSB + (ks * 16 + akb) * 2;
            ldsm_x4(qf[ks][0], qf[ks][1], qf[ks][2], qf[ks][3], sQ + ro);
        }
    }

    float m0 = -1e30f, m1 = -1e30f, l0 = 0.f, l1 = 0.f;
    float o[8][4];
#pragma unroll
    for (int nd = 0; nd < 8; nd++)
#pragma unroll
        for (int r = 0; r < 4; r++) o[nd][r] = 0.f;

    const int rlo = q0 + wid * 16;
    const int row0 = rlo + g;
    const int brow0 = lane & 7;
    const int bkb = ((lane >> 3) & 1) * 8;
    const int vrow = lane & 15;

    for (int kt = kt_lo; kt <= kt_hi; kt++) {
        const int stg = (kt - kt_lo) & 1;
        if (kt < kt_hi) {
            load_kv(kt + 1, stg ^ 1);
            CP_COMMIT();
            CP_WAIT1();
        } else {
            CP_WAIT0();
        }
        __syncthreads();

        const uint32_t base = sKV0 + stg * 2 * ATT_TILE_B;
        const uint32_t pK = base, pV = base + ATT_TILE_B;

        const int cbase = kt * 128;
        const int T1 = rlo - 256 - cbase;
        const int T2 = rlo + 15 + 256 - cbase;
        int ntlo = (T1 > 0) ? (T1 >> 3) : 0;
        int nthi = (T2 < 0) ? -1 : (T2 >> 3);
        if (nthi > 15) nthi = 15;

        float s[16][4];
#pragma unroll
        for (int nt = 0; nt < 16; nt++)
#pragma unroll
            for (int r = 0; r < 4; r++) s[nt][r] = 0.f;
#pragma unroll
        for (int ks = 0; ks < 4; ks++) {
#pragma unroll
            for (int nt = 0; nt < 16; nt++) {
                if (nt < ntlo || nt > nthi) continue;
                uint32_t bk[2];
                const uint32_t ro = (uint32_t)(nt * 8 + brow0) * ATT_RSB + (ks * 16 + bkb) * 2;
                ldsm_x2(bk[0], bk[1], pK + ro);
                mma_f16(s[nt], qf[ks], bk);
            }
        }

        float rmax0 = -1e30f, rmax1 = -1e30f;
#pragma unroll
        for (int nt = 0; nt < 16; nt++) {
            if (nt < ntlo || nt > nthi) continue;
            const int col = cbase + nt * 8 + tq * 2;
            const bool i00 = (unsigned)(row0 - col + 256) <= 512u;
            const bool i01 = (unsigned)(row0 - col - 1 + 256) <= 512u;
            const bool i10 = (unsigned)(row0 + 8 - col + 256) <= 512u;
            const bool i11 = (unsigned)(row0 + 8 - col - 1 + 256) <= 512u;
            s[nt][0] = i00 ? s[nt][0] : -1e30f;
            s[nt][1] = i01 ? s[nt][1] : -1e30f;
            s[nt][2] = i10 ? s[nt][2] : -1e30f;
            s[nt][3] = i11 ? s[nt][3] : -1e30f;
            rmax0 = fmaxf(rmax0, fmaxf(s[nt][0], s[nt][1]));
            rmax1 = fmaxf(rmax1, fmaxf(s[nt][2], s[nt][3]));
        }
        rmax0 = fmaxf(rmax0, __shfl_xor_sync(0xffffffffu, rmax0, 1));
        rmax0 = fmaxf(rmax0, __shfl_xor_sync(0xffffffffu, rmax0, 2));
        rmax1 = fmaxf(rmax1, __shfl_xor_sync(0xffffffffu, rmax1, 1));
        rmax1 = fmaxf(rmax1, __shfl_xor_sync(0xffffffffu, rmax1, 2));

        const float nm0 = fmaxf(m0, rmax0);
        const float nm1 = fmaxf(m1, rmax1);
        const float c0 = __expf(m0 - nm0);
        const float c1 = __expf(m1 - nm1);
        m0 = nm0; m1 = nm1;

        float add0 = 0.f, add1 = 0.f;
        uint32_t p[16][2];
#pragma unroll
        for (int nt = 0; nt < 16; nt++) {
            if (nt < ntlo || nt > nthi) { p[nt][0] = 0; p[nt][1] = 0; continue; }
            const float p00 = __expf(s[nt][0] - nm0);
            const float p01 = __expf(s[nt][1] - nm0);
            const float p10 = __expf(s[nt][2] - nm1);
            const float p11 = __expf(s[nt][3] - nm1);
            add0 += p00 + p01;
            add1 += p10 + p11;
            p[nt][0] = packh(p00, p01);
            p[nt][1] = packh(p10, p11);
        }
        add0 += __shfl_xor_sync(0xffffffffu, add0, 1);
        add0 += __shfl_xor_sync(0xffffffffu, add0, 2);
        add1 += __shfl_xor_sync(0xffffffffu, add1, 1);
        add1 += __shfl_xor_sync(0xffffffffu, add1, 2);
        l0 = l0 * c0 + add0;
        l1 = l1 * c1 + add1;
#pragma unroll
        for (int nd = 0; nd < 8; nd++) {
            o[nd][0] *= c0; o[nd][1] *= c0;
            o[nd][2] *= c1; o[nd][3] *= c1;
        }

#pragma unroll
        for (int ks = 0; ks < 8; ks++) {
            if (2 * ks + 1 < ntlo || 2 * ks > nthi) continue;
            uint32_t a[4] = {p[2 * ks][0], p[2 * ks][1], p[2 * ks + 1][0], p[2 * ks + 1][1]};
#pragma unroll
            for (int nd = 0; nd < 8; nd++) {
                uint32_t bv[2];
                const uint32_t ro = (uint32_t)(ks * 16 + vrow) * ATT_RSB + nd * 16;
                ldsm_x2t(bv[0], bv[1], pV + ro);
                mma_f16(o[nd], a, bv);
            }
        }
        __syncthreads();
    }

    const float inv0 = 1.f / l0;
    const float inv1 = 1.f / l1;
#pragma unroll
    for (int nd = 0; nd < 8; nd++) {
        const int d = nd * 8 + tq * 2;
        const size_t o0 = (size_t)(b * S_ + row0) * D_ + h * 64 + d;
        const size_t o1 = (size_t)(b * S_ + row0 + 8) * D_ + h * 64 + d;
        *(uint32_t*)(Of + o0) = packh(o[nd][0] * inv0, o[nd][1] * inv0);
        *(uint32_t*)(Of + o1) = packh(o[nd][2] * inv1, o[nd][3] * inv1);
    }
}

// ---------------------------------------------------------------------------
// Fused split-K reduce (fp16 partials) + bias + residual add + LayerNorm.
// val = res + (p0 + p1 + p2) + bias;  then LN -> xout fp32 + xf fp16
// ---------------------------------------------------------------------------
__global__ __launch_bounds__(256) void add_ln3_kernel(
    const float* __restrict__ res, const __half* __restrict__ parts,
    const float* __restrict__ bias,
    const float* __restrict__ g, const float* __restrict__ be,
    float* __restrict__ xout, __half* __restrict__ xf)
{
    const int row = blockIdx.x;
    const int tid = threadIdx.x;
    const float* xp = res + (size_t)row * D_;
    const __half* p0 = parts + (size_t)row * D_;
    const __half* p1 = parts + (size_t)MROWS * D_ + (size_t)row * D_;
    const __half* p2 = parts + 2 * (size_t)MROWS * D_ + (size_t)row * D_;

    float v[3];
    float s1 = 0.f, s2 = 0.f;
#pragma unroll
    for (int i = 0; i < 3; i++) {
        const int c = tid + 256 * i;
        const float ps = (__half2float(p0[c]) + __half2float(p1[c])) + __half2float(p2[c]);
        v[i] = xp[c] + ps + bias[c];
        s1 += v[i];
        s2 += v[i] * v[i];
    }
#pragma unroll
    for (int off = 16; off; off >>= 1) {
        s1 += __shfl_xor_sync(0xffffffffu, s1, off);
        s2 += __shfl_xor_sync(0xffffffffu, s2, off);
    }
    __shared__ float r1[8], r2[8];
    if ((tid & 31) == 0) { r1[tid >> 5] = s1; r2[tid >> 5] = s2; }
    __syncthreads();
    s1 = 0.f; s2 = 0.f;
#pragma unroll
    for (int i = 0; i < 8; i++) { s1 += r1[i]; s2 += r2[i]; }

    const float mean = s1 * (1.f / 768.f);
    const float var  = s2 * (1.f / 768.f) - mean * mean;
    const float rstd = rsqrtf(var + 1e-5f);
#pragma unroll
    for (int i = 0; i < 3; i++) {
        const int c = tid + 256 * i;
        const float val = (v[i] - mean) * rstd * g[c] + be[c];
        xout[(size_t)row * D_ + c] = val;
        xf[(size_t)row * D_ + c] = __float2half_rn(val);
    }
}

// ---------------------------------------------------------------------------
// Host orchestration
// ---------------------------------------------------------------------------
template <int EPI>
static void run_gemm(const __half* A, const __half* W, const float* bias,
                     __half* Hf, int M, int N, int K)
{
    dim3 grid(N / 128, M / 128, 1);
    gemm_mma_kernel<EPI><<<grid, 256, GEMM_SMEM>>>(A, W, bias, Hf, M, N, K, K);
}

// split-K=3 raw fp16-partial GEMM (EPI=3)
static void run_gemm_sk(const __half* A, const __half* W, __half* Pf,
                        int M, int N, int K)
{
    dim3 grid(N / 128, M / 128, KSPLIT);
    gemm_mma_kernel<3><<<grid, 256, GEMM_SMEM>>>(A, W, nullptr, Pf,
                                                 M, N, K, K / KSPLIT);
}

extern "C" void kernel_launch(void* const* d_in, const int* in_sizes, int n_in,
                              void* d_out, int out_size)
{
    const float* src = (const float*)d_in[0];
    const float* qw  = (const float*)d_in[1];
    const float* qb  = (const float*)d_in[2];
    const float* kw  = (const float*)d_in[3];
    const float* kb  = (const float*)d_in[4];
    const float* vw  = (const float*)d_in[5];
    const float* vb  = (const float*)d_in[6];
    const float* ow  = (const float*)d_in[7];
    const float* ob  = (const float*)d_in[8];
    const float* w1  = (const float*)d_in[9];
    const float* b1  = (const float*)d_in[10];
    const float* w2  = (const float*)d_in[11];
    const float* b2  = (const float*)d_in[12];
    const float* g1  = (const float*)d_in[13];
    const float* be1 = (const float*)d_in[14];
    const float* g2  = (const float*)d_in[15];
    const float* be2 = (const float*)d_in[16];

    cudaFuncSetAttribute((const void*)gemm_mma_kernel<1>, cudaFuncAttributeMaxDynamicSharedMemorySize, GEMM_SMEM);
    cudaFuncSetAttribute((const void*)gemm_mma_kernel<2>, cudaFuncAttributeMaxDynamicSharedMemorySize, GEMM_SMEM);
    cudaFuncSetAttribute((const void*)gemm_mma_kernel<3>, cudaFuncAttributeMaxDynamicSharedMemorySize, GEMM_SMEM);
    cudaFuncSetAttribute((const void*)attn_mma_kernel, cudaFuncAttributeMaxDynamicSharedMemorySize, ATT_SMEM);

    float *x, *bq2;
    __half *pf, *xf, *of, *fff, *wqkv, *wo, *w1c, *w2c;
    cudaGetSymbolAddress((void**)&x,    g_x);
    cudaGetSymbolAddress((void**)&bq2,  g_bq2);
    cudaGetSymbolAddress((void**)&pf,   g_pf);
    cudaGetSymbolAddress((void**)&xf,   g_xf);
    cudaGetSymbolAddress((void**)&of,   g_of);
    cudaGetSymbolAddress((void**)&fff,  g_fff);
    cudaGetSymbolAddress((void**)&wqkv, g_wqkv);
    cudaGetSymbolAddress((void**)&wo,   g_wo);
    cudaGetSymbolAddress((void**)&w1c,  g_w1c);
    cudaGetSymbolAddress((void**)&w2c,  g_w2c);

    // all weight conversions + bias packs in ONE launch (grid.y = layer)
    {
        dim3 grid((PREP_TOTAL + 255) / 256, L_);
        prep_kernel<<<grid, 256>>>(qw, kw, vw, qb, kb, vb, ow, w1, w2,
                                   wqkv, bq2, wo, w1c, w2c);
    }

    // src -> fp16 activations
    {
        const int n4 = (MROWS * D_) >> 2;
        cvt_kernel<<<(n4 + 255) / 256, 256>>>(src, xf, n4);
    }

    for (int l = 0; l < L_; l++) {
        const __half* wqkv_l = wqkv + (size_t)l * NQKV * D_;
        const __half* wo_l   = wo   + (size_t)l * D_ * D_;
        const __half* w1_l   = w1c  + (size_t)l * DFF_ * D_;
        const __half* w2_l   = w2c  + (size_t)l * D_ * DFF_;

        // fused QKV projection (Q pre-scaled in epilogue)
        run_gemm<1>(xf, wqkv_l, bq2 + l * NQKV, fff, MROWS, NQKV, D_);

        // banded attention on packed QKV
        {
            dim3 grid(S_ / 128, H_, B_);
            attn_mma_kernel<<<grid, 256, ATT_SMEM>>>(
                fff, fff + D_, fff + 2 * D_, NQKV, of);
        }

        // output projection: split-K=3 fp16 partials, reduced inside add_ln3.
        // residual source is src for layer 0 (saves the initial memcpy).
        run_gemm_sk(of, wo_l, pf, MROWS, D_, D_);
        const float* res0 = (l == 0) ? src : x;
        add_ln3_kernel<<<MROWS, 256>>>(res0, pf, ob + l * D_, g1 + l * D_, be1 + l * D_, x, xf);

        // FFN
        run_gemm<2>(xf, w1_l, b1 + l * DFF_, fff, MROWS, DFF_, D_);
        run_gemm_sk(fff, w2_l, pf, MROWS, D_, DFF_);
        // last LN writes the final output directly to d_out
        float* xout = (l == L_ - 1) ? (float*)d_out : x;
        add_ln3_kernel<<<MROWS, 256>>>(x, pf, b2 + l * D_, g2 + l * D_, be2 + l * D_, xout, xf);
    }
}

// round 14
// speedup vs baseline: 1.1374x; 1.0721x over previous
#include <cuda_runtime.h>
#include <cuda_bf16.h>
#include <cuda_fp16.h>
#include <cstdint>

// Problem constants
#define B_ 2
#define S_ 2048
#define D_ 768
#define H_ 12
#define DH_ 64
#define L_ 2
#define DFF_ 3072
#define MROWS (B_ * S_)   // 4096
#define NQKV 2304
#define KSPLIT 3

// ---------------------------------------------------------------------------
// Scratch (static device globals — no allocation allowed)
// ---------------------------------------------------------------------------
__device__ float g_x  [MROWS * D_];
__device__ float g_bq2[L_ * NQKV];
__device__ __half g_pf [KSPLIT * MROWS * D_];  // split-K fp16 partials
__device__ __half g_xf [MROWS * D_];
__device__ __half g_of [MROWS * D_];
__device__ __half g_fff[MROWS * DFF_];         // QKV (M x 2304) / FFN1 (M x 3072)
__device__ __half g_wqkv[L_ * NQKV * D_];
__device__ __half g_wo  [L_ * D_ * D_];
__device__ __half g_w1c [L_ * DFF_ * D_];
__device__ __half g_w2c [L_ * D_ * DFF_];

// ---------------------------------------------------------------------------
// Baseline-PTX tensor-core helpers
// ---------------------------------------------------------------------------
__device__ __forceinline__ uint32_t smem_u32(const void* p) {
    uint32_t a;
    asm("{ .reg .u64 t; cvta.to.shared.u64 t, %1; cvt.u32.u64 %0, t; }"
        : "=r"(a) : "l"(p));
    return a;
}
__device__ __forceinline__ void ldsm_x4(uint32_t& r0, uint32_t& r1,
                                        uint32_t& r2, uint32_t& r3, uint32_t a) {
    asm volatile("ldmatrix.sync.aligned.m8n8.x4.shared.b16 {%0,%1,%2,%3}, [%4];"
                 : "=r"(r0), "=r"(r1), "=r"(r2), "=r"(r3) : "r"(a));
}
__device__ __forceinline__ void ldsm_x2(uint32_t& r0, uint32_t& r1, uint32_t a) {
    asm volatile("ldmatrix.sync.aligned.m8n8.x2.shared.b16 {%0,%1}, [%2];"
                 : "=r"(r0), "=r"(r1) : "r"(a));
}
__device__ __forceinline__ void ldsm_x2t(uint32_t& r0, uint32_t& r1, uint32_t a) {
    asm volatile("ldmatrix.sync.aligned.m8n8.x2.trans.shared.b16 {%0,%1}, [%2];"
                 : "=r"(r0), "=r"(r1) : "r"(a));
}
__device__ __forceinline__ void mma_f16(float* d, const uint32_t* a, const uint32_t* b) {
    asm volatile(
        "mma.sync.aligned.m16n8k16.row.col.f32.f16.f16.f32 "
        "{%0,%1,%2,%3}, {%4,%5,%6,%7}, {%8,%9}, {%0,%1,%2,%3};"
        : "+f"(d[0]), "+f"(d[1]), "+f"(d[2]), "+f"(d[3])
        : "r"(a[0]), "r"(a[1]), "r"(a[2]), "r"(a[3]), "r"(b[0]), "r"(b[1]));
}
#define CP16(dst, src) \
    asm volatile("cp.async.cg.shared.global [%0], [%1], 16;" :: "r"(dst), "l"(src))
#define CP_COMMIT() asm volatile("cp.async.commit_group;" ::: "memory")
#define CP_WAIT0()  asm volatile("cp.async.wait_group 0;" ::: "memory")
#define CP_WAIT1()  asm volatile("cp.async.wait_group 1;" ::: "memory")

__device__ __forceinline__ uint32_t packh(float a, float b) {
    __half2 t = __floats2half2_rn(a, b);
    return *(uint32_t*)&t;
}

// ---------------------------------------------------------------------------
// Convert fp32 -> fp16 (single source)
// ---------------------------------------------------------------------------
__global__ __launch_bounds__(256) void cvt_kernel(
    const float* __restrict__ in, __half* __restrict__ out, int n4)
{
    int i = blockIdx.x * blockDim.x + threadIdx.x;
    if (i >= n4) return;
    float4 x = ((const float4*)in)[i];
    __half2* op = (__half2*)out;
    op[2 * i + 0] = __floats2half2_rn(x.x, x.y);
    op[2 * i + 1] = __floats2half2_rn(x.z, x.w);
}

// ---------------------------------------------------------------------------
// Weight prep for ALL layers in one launch (blockIdx.y = layer)
// ---------------------------------------------------------------------------
#define RQ ((D_ * D_) >> 2)
#define RW ((DFF_ * D_) >> 2)
#define PREP_B0 (3 * RQ)
#define PREP_B1 (PREP_B0 + RQ)
#define PREP_B2 (PREP_B1 + RW)
#define PREP_B3 (PREP_B2 + RW)
#define PREP_TOTAL (PREP_B3 + NQKV)

__global__ __launch_bounds__(256) void prep_kernel(
    const float* __restrict__ qw, const float* __restrict__ kw,
    const float* __restrict__ vw, const float* __restrict__ qb,
    const float* __restrict__ kb, const float* __restrict__ vb,
    const float* __restrict__ ow, const float* __restrict__ w1,
    const float* __restrict__ w2,
    __half* __restrict__ wqkv, float* __restrict__ bq,
    __half* __restrict__ wo, __half* __restrict__ w1c, __half* __restrict__ w2c)
{
    const int l = blockIdx.y;
    const int i = blockIdx.x * 256 + threadIdx.x;
    if (i >= PREP_TOTAL) return;

    const float* qwl = qw + (size_t)l * D_ * D_;
    const float* kwl = kw + (size_t)l * D_ * D_;
    const float* vwl = vw + (size_t)l * D_ * D_;
    const float* owl = ow + (size_t)l * D_ * D_;
    const float* w1l = w1 + (size_t)l * DFF_ * D_;
    const float* w2l = w2 + (size_t)l * D_ * DFF_;
    __half* wqkvl = wqkv + (size_t)l * NQKV * D_;
    __half* wol   = wo   + (size_t)l * D_ * D_;
    __half* w1cl  = w1c  + (size_t)l * DFF_ * D_;
    __half* w2cl  = w2c  + (size_t)l * D_ * DFF_;

    if (i >= PREP_B3) {
        const int j = i - PREP_B3;
        float v;
        if (j < D_)          v = qb[l * D_ + j];
        else if (j < 2 * D_) v = kb[l * D_ + j - D_];
        else                 v = vb[l * D_ + j - 2 * D_];
        bq[l * NQKV + j] = v;
        return;
    }
    const float* src;
    __half* dst;
    int j, oj;
    if (i < PREP_B0) {
        oj = i;
        src = (i < RQ) ? qwl : (i < 2 * RQ) ? kwl : vwl;
        j = (i < RQ) ? i : (i < 2 * RQ) ? i - RQ : i - 2 * RQ;
        dst = wqkvl;
    } else if (i < PREP_B1) {
        j = i - PREP_B0; oj = j; src = owl; dst = wol;
    } else if (i < PREP_B2) {
        j = i - PREP_B1; oj = j; src = w1l; dst = w1cl;
    } else {
        j = i - PREP_B2; oj = j; src = w2l; dst = w2cl;
    }
    float4 x = ((const float4*)src)[j];
    __half2* op = (__half2*)dst;
    op[2 * oj + 0] = __floats2half2_rn(x.x, x.y);
    op[2 * oj + 1] = __floats2half2_rn(x.z, x.w);
}

// ---------------------------------------------------------------------------
// fp16 mma.sync GEMM (R9 champion config): C = A[M,K] @ W[N,K]^T (+bias)
// EPI: 1 = fp16 out (+bias, Q cols x 0.125*log2e); 2 = relu + fp16 out (+bias);
//      3 = raw fp16 partial (no bias), at Hf + z*M*N
// ---------------------------------------------------------------------------
#define RS_B 144
#define TILE_B (128 * RS_B)
#define STAGE_B (2 * TILE_B)
#define GEMM_SMEM (2 * STAGE_B)

// 0.125 * log2(e): folds both the attention scale and the exp->exp2 change.
#define QSCALE 0.18033688011112042f

template <int EPI>
__global__ __launch_bounds__(256, 2) void gemm_mma_kernel(
    const __half* __restrict__ A, const __half* __restrict__ W,
    const float* __restrict__ bias,
    __half* __restrict__ Hf, int M, int N, int K, int klen)
{
    extern __shared__ char smem[];
    const uint32_t sb = smem_u32(smem);

    const int tid = threadIdx.x;
    const int wid = tid >> 5;
    const int lane = tid & 31;
    const int warp_m = wid >> 2;
    const int warp_n = wid & 3;
    const int bm = blockIdx.y * 128;
    const int bn = blockIdx.x * 128;
    const int kstart = blockIdx.z * klen;

    float acc[4][4][4];
#pragma unroll
    for (int mi = 0; mi < 4; mi++)
#pragma unroll
        for (int ni = 0; ni < 4; ni++)
#pragma unroll
            for (int r = 0; r < 4; r++) acc[mi][ni][r] = 0.f;

    auto load_chunk = [&](int kc, int stage) {
        const uint32_t base = sb + stage * STAGE_B;
#pragma unroll
        for (int t = 0; t < 4; t++) {
            const int idx = tid + t * 256;
            const int lr = idx >> 3, ls = idx & 7;
            CP16(base + lr * RS_B + ls * 16,
                 A + (size_t)(bm + lr) * K + kstart + kc + ls * 8);
        }
#pragma unroll
        for (int t = 0; t < 4; t++) {
            const int idx = tid + t * 256;
            const int lr = idx >> 3, ls = idx & 7;
            CP16(base + TILE_B + lr * RS_B + ls * 16,
                 W + (size_t)(bn + lr) * K + kstart + kc + ls * 8);
        }
    };

    const int arow = warp_m * 64 + (lane & 15);
    const int akb  = (lane >> 4) * 8;
    const int bg_ni = (lane >> 4);
    const int bg_kh = ((lane >> 3) & 1) * 8;
    const int brow_l = lane & 7;

    auto compute = [&](int stage) {
        const uint32_t base = sb + stage * STAGE_B;
        const uint32_t pA = base;
        const uint32_t pB = base + TILE_B;
#pragma unroll
        for (int ks = 0; ks < 4; ks++) {
            const int k0 = ks * 16;
            uint32_t af[4][4], bf[4][2];
#pragma unroll
            for (int mi = 0; mi < 4; mi++) {
                const uint32_t ro = (uint32_t)(arow + mi * 16) * RS_B + (k0 + akb) * 2;
                ldsm_x4(af[mi][0], af[mi][1], af[mi][2], af[mi][3], pA + ro);
            }
#pragma unroll
            for (int np = 0; np < 2; np++) {
                const int nrow = warp_n * 32 + (np * 2 + bg_ni) * 8 + brow_l;
                const uint32_t ro = (uint32_t)nrow * RS_B + (k0 + bg_kh) * 2;
                ldsm_x4(bf[np * 2][0], bf[np * 2][1], bf[np * 2 + 1][0], bf[np * 2 + 1][1], pB + ro);
            }
#pragma unroll
            for (int mi = 0; mi < 4; mi++)
#pragma unroll
                for (int ni = 0; ni < 4; ni++)
                    mma_f16(acc[mi][ni], af[mi], bf[ni]);
        }
    };

    const int nchunks = klen >> 6;
    load_chunk(0, 0);
    CP_COMMIT();

    for (int c = 0; c < nchunks; c++) {
        CP_WAIT0();
        __syncthreads();
        if (c + 1 < nchunks) {
            load_chunk((c + 1) << 6, (c + 1) & 1);
            CP_COMMIT();
        }
        compute(c & 1);
    }

    // epilogue
    __half* Hz = (EPI == 3) ? (Hf + (size_t)blockIdx.z * M * N) : Hf;
#pragma unroll
    for (int mi = 0; mi < 4; mi++) {
        const int m0 = bm + warp_m * 64 + mi * 16 + (lane >> 2);
#pragma unroll
        for (int ni = 0; ni < 4; ni++) {
            const int n0 = bn + warp_n * 32 + ni * 8 + (lane & 3) * 2;
            float v00 = acc[mi][ni][0], v01 = acc[mi][ni][1];
            float v10 = acc[mi][ni][2], v11 = acc[mi][ni][3];
            if (EPI != 3) {
                const float bx = bias[n0], by = bias[n0 + 1];
                v00 += bx; v01 += by; v10 += bx; v11 += by;
            }
            if (EPI == 1) {
                const float sc = (n0 < 768) ? QSCALE : 1.0f;
                v00 *= sc; v01 *= sc; v10 *= sc; v11 *= sc;
            }
            if (EPI == 2) {
                v00 = fmaxf(v00, 0.f); v01 = fmaxf(v01, 0.f);
                v10 = fmaxf(v10, 0.f); v11 = fmaxf(v11, 0.f);
            }
            *(uint32_t*)(Hz + (size_t)m0 * N + n0) = packh(v00, v01);
            *(uint32_t*)(Hz + (size_t)(m0 + 8) * N + n0) = packh(v10, v11);
        }
    }
}

// ---------------------------------------------------------------------------
// Tensor-core banded flash attention, fp16, 64-key tiles, exp2 softmax.
// 2 CTAs/SM (smem 54KB, regs capped at 128). Band |i-j| <= 256.
// Q arrives pre-scaled by 0.125*log2e -> softmax uses exp2f.
// ---------------------------------------------------------------------------
#define ATT_RSB 144
#define ATT_QTILE_B (128 * ATT_RSB)       // 18432
#define ATT_KTILE_B (64 * ATT_RSB)        // 9216
#define ATT_SMEM (ATT_QTILE_B + 4 * ATT_KTILE_B)  // 55296

__global__ __launch_bounds__(256, 2) void attn_mma_kernel(
    const __half* __restrict__ Qf, const __half* __restrict__ Kf,
    const __half* __restrict__ Vf, int ldq, __half* __restrict__ Of)
{
    extern __shared__ char smem[];
    const uint32_t sb = smem_u32(smem);
    const int b = blockIdx.z;
    const int h = blockIdx.y;
    const int qt = blockIdx.x;
    const int q0 = qt * 128;
    const int tid = threadIdx.x;
    const int wid = tid >> 5;
    const int lane = tid & 31;
    const int g = lane >> 2;
    const int tq = lane & 3;

    const uint32_t sQ = sb;
    const uint32_t sKV0 = sb + ATT_QTILE_B;   // stage s: K at s*2*KT, V at +KT

    // stage Q (128 rows x 64 halves)
    {
        const int row = tid >> 1, seg = tid & 1;
#pragma unroll
        for (int t = 0; t < 4; t++) {
            const size_t go = (size_t)(b * S_ + q0 + row) * ldq + h * 64 + (seg * 4 + t) * 8;
            CP16(sQ + (uint32_t)row * ATT_RSB + (seg * 4 + t) * 16, Qf + go);
        }
    }
    CP_COMMIT();

    // 64-key tile range
    const int ktmax = S_ / 64 - 1;
    int kt_lo = (q0 - 256) >> 6; if (kt_lo < 0) kt_lo = 0;
    int kt_hi = (q0 + 127 + 256) >> 6; if (kt_hi > ktmax) kt_hi = ktmax;

    auto load_kv = [&](int kt, int stg) {
        const uint32_t base = sKV0 + stg * 2 * ATT_KTILE_B;
        const int row = tid >> 2;              // 0..63
        const int s0  = (tid & 3) * 2;         // seg pairs
#pragma unroll
        for (int t = 0; t < 2; t++) {
            const int seg = s0 + t;
            const size_t go = (size_t)(b * S_ + kt * 64 + row) * ldq + h * 64 + seg * 8;
            const uint32_t so = (uint32_t)row * ATT_RSB + seg * 16;
            CP16(base + so,               Kf + go);
            CP16(base + ATT_KTILE_B + so, Vf + go);
        }
    };
    load_kv(kt_lo, 0);
    CP_COMMIT();

    CP_WAIT1();   // Q ready
    __syncthreads();

    uint32_t qf[4][4];
    {
        const int arow = wid * 16 + (lane & 15);
        const int akb = (lane >> 4) * 8;
#pragma unroll
        for (int ks = 0; ks < 4; ks++) {
            const uint32_t ro = (uint32_t)arow * ATT_RSB + (ks * 16 + akb) * 2;
            ldsm_x4(qf[ks][0], qf[ks][1], qf[ks][2], qf[ks][3], sQ + ro);
        }
    }

    float m0 = -1e30f, m1 = -1e30f, l0 = 0.f, l1 = 0.f;
    float o[8][4];
#pragma unroll
    for (int nd = 0; nd < 8; nd++)
#pragma unroll
        for (int r = 0; r < 4; r++) o[nd][r] = 0.f;

    const int rlo = q0 + wid * 16;
    const int row0 = rlo + g;
    const int brow0 = lane & 7;
    const int bkb = ((lane >> 3) & 1) * 8;
    const int vrow = lane & 15;

    for (int kt = kt_lo; kt <= kt_hi; kt++) {
        const int stg = (kt - kt_lo) & 1;
        if (kt < kt_hi) {
            load_kv(kt + 1, stg ^ 1);
            CP_COMMIT();
            CP_WAIT1();
        } else {
            CP_WAIT0();
        }
        __syncthreads();

        const uint32_t base = sKV0 + stg * 2 * ATT_KTILE_B;
        const uint32_t pK = base, pV = base + ATT_KTILE_B;

        const int cbase = kt * 64;
        const int T1 = rlo - 256 - cbase;
        const int T2 = rlo + 15 + 256 - cbase;
        int ntlo = (T1 > 0) ? (T1 >> 3) : 0;
        int nthi = (T2 < 0) ? -1 : (T2 >> 3);
        if (nthi > 7) nthi = 7;

        float s[8][4];
#pragma unroll
        for (int nt = 0; nt < 8; nt++)
#pragma unroll
            for (int r = 0; r < 4; r++) s[nt][r] = 0.f;
#pragma unroll
        for (int ks = 0; ks < 4; ks++) {
#pragma unroll
            for (int nt = 0; nt < 8; nt++) {
                if (nt < ntlo || nt > nthi) continue;
                uint32_t bk[2];
                const uint32_t ro = (uint32_t)(nt * 8 + brow0) * ATT_RSB + (ks * 16 + bkb) * 2;
                ldsm_x2(bk[0], bk[1], pK + ro);
                mma_f16(s[nt], qf[ks], bk);
            }
        }

        float rmax0 = -1e30f, rmax1 = -1e30f;
#pragma unroll
        for (int nt = 0; nt < 8; nt++) {
            if (nt < ntlo || nt > nthi) continue;
            const int col = cbase + nt * 8 + tq * 2;
            const bool i00 = (unsigned)(row0 - col + 256) <= 512u;
            const bool i01 = (unsigned)(row0 - col - 1 + 256) <= 512u;
            const bool i10 = (unsigned)(row0 + 8 - col + 256) <= 512u;
            const bool i11 = (unsigned)(row0 + 8 - col - 1 + 256) <= 512u;
            s[nt][0] = i00 ? s[nt][0] : -1e30f;
            s[nt][1] = i01 ? s[nt][1] : -1e30f;
            s[nt][2] = i10 ? s[nt][2] : -1e30f;
            s[nt][3] = i11 ? s[nt][3] : -1e30f;
            rmax0 = fmaxf(rmax0, fmaxf(s[nt][0], s[nt][1]));
            rmax1 = fmaxf(rmax1, fmaxf(s[nt][2], s[nt][3]));
        }
        rmax0 = fmaxf(rmax0, __shfl_xor_sync(0xffffffffu, rmax0, 1));
        rmax0 = fmaxf(rmax0, __shfl_xor_sync(0xffffffffu, rmax0, 2));
        rmax1 = fmaxf(rmax1, __shfl_xor_sync(0xffffffffu, rmax1, 1));
        rmax1 = fmaxf(rmax1, __shfl_xor_sync(0xffffffffu, rmax1, 2));

        const float nm0 = fmaxf(m0, rmax0);
        const float nm1 = fmaxf(m1, rmax1);
        const float c0 = exp2f(m0 - nm0);
        const float c1 = exp2f(m1 - nm1);
        m0 = nm0; m1 = nm1;

        float add0 = 0.f, add1 = 0.f;
        uint32_t p[8][2];
#pragma unroll
        for (int nt = 0; nt < 8; nt++) {
            if (nt < ntlo || nt > nthi) { p[nt][0] = 0; p[nt][1] = 0; continue; }
            const float p00 = exp2f(s[nt][0] - nm0);
            const float p01 = exp2f(s[nt][1] - nm0);
            const float p10 = exp2f(s[nt][2] - nm1);
            const float p11 = exp2f(s[nt][3] - nm1);
            add0 += p00 + p01;
            add1 += p10 + p11;
            p[nt][0] = packh(p00, p01);
            p[nt][1] = packh(p10, p11);
        }
        add0 += __shfl_xor_sync(0xffffffffu, add0, 1);
        add0 += __shfl_xor_sync(0xffffffffu, add0, 2);
        add1 += __shfl_xor_sync(0xffffffffu, add1, 1);
        add1 += __shfl_xor_sync(0xffffffffu, add1, 2);
        l0 = l0 * c0 + add0;
        l1 = l1 * c1 + add1;
#pragma unroll
        for (int nd = 0; nd < 8; nd++) {
            o[nd][0] *= c0; o[nd][1] *= c0;
            o[nd][2] *= c1; o[nd][3] *= c1;
        }

        // O += P · V  over 64-key tile (4 a-pairs of 16 keys)
#pragma unroll
        for (int ks = 0; ks < 4; ks++) {
            if (2 * ks + 1 < ntlo || 2 * ks > nthi) continue;
            uint32_t a[4] = {p[2 * ks][0], p[2 * ks][1], p[2 * ks + 1][0], p[2 * ks + 1][1]};
#pragma unroll
            for (int nd = 0; nd < 8; nd++) {
                uint32_t bv[2];
                const uint32_t ro = (uint32_t)(ks * 16 + vrow) * ATT_RSB + nd * 16;
                ldsm_x2t(bv[0], bv[1], pV + ro);
                mma_f16(o[nd], a, bv);
            }
        }
        __syncthreads();
    }

    const float inv0 = 1.f / l0;
    const float inv1 = 1.f / l1;
#pragma unroll
    for (int nd = 0; nd < 8; nd++) {
        const int d = nd * 8 + tq * 2;
        const size_t o0 = (size_t)(b * S_ + row0) * D_ + h * 64 + d;
        const size_t o1 = (size_t)(b * S_ + row0 + 8) * D_ + h * 64 + d;
        *(uint32_t*)(Of + o0) = packh(o[nd][0] * inv0, o[nd][1] * inv0);
        *(uint32_t*)(Of + o1) = packh(o[nd][2] * inv1, o[nd][3] * inv1);
    }
}

// ---------------------------------------------------------------------------
// Fused split-K reduce (fp16 partials) + bias + residual add + LayerNorm.
// ---------------------------------------------------------------------------
__global__ __launch_bounds__(256) void add_ln3_kernel(
    const float* __restrict__ res, const __half* __restrict__ parts,
    const float* __restrict__ bias,
    const float* __restrict__ g, const float* __restrict__ be,
    float* __restrict__ xout, __half* __restrict__ xf)
{
    const int row = blockIdx.x;
    const int tid = threadIdx.x;
    const float* xp = res + (size_t)row * D_;
    const __half* p0 = parts + (size_t)row * D_;
    const __half* p1 = parts + (size_t)MROWS * D_ + (size_t)row * D_;
    const __half* p2 = parts + 2 * (size_t)MROWS * D_ + (size_t)row * D_;

    float v[3];
    float s1 = 0.f, s2 = 0.f;
#pragma unroll
    for (int i = 0; i < 3; i++) {
        const int c = tid + 256 * i;
        const float ps = (__half2float(p0[c]) + __half2float(p1[c])) + __half2float(p2[c]);
        v[i] = xp[c] + ps + bias[c];
        s1 += v[i];
        s2 += v[i] * v[i];
    }
#pragma unroll
    for (int off = 16; off; off >>= 1) {
        s1 += __shfl_xor_sync(0xffffffffu, s1, off);
        s2 += __shfl_xor_sync(0xffffffffu, s2, off);
    }
    __shared__ float r1[8], r2[8];
    if ((tid & 31) == 0) { r1[tid >> 5] = s1; r2[tid >> 5] = s2; }
    __syncthreads();
    s1 = 0.f; s2 = 0.f;
#pragma unroll
    for (int i = 0; i < 8; i++) { s1 += r1[i]; s2 += r2[i]; }

    const float mean = s1 * (1.f / 768.f);
    const float var  = s2 * (1.f / 768.f) - mean * mean;
    const float rstd = rsqrtf(var + 1e-5f);
#pragma unroll
    for (int i = 0; i < 3; i++) {
        const int c = tid + 256 * i;
        const float val = (v[i] - mean) * rstd * g[c] + be[c];
        xout[(size_t)row * D_ + c] = val;
        xf[(size_t)row * D_ + c] = __float2half_rn(val);
    }
}

// ---------------------------------------------------------------------------
// Host orchestration
// ---------------------------------------------------------------------------
template <int EPI>
static void run_gemm(const __half* A, const __half* W, const float* bias,
                     __half* Hf, int M, int N, int K)
{
    dim3 grid(N / 128, M / 128, 1);
    gemm_mma_kernel<EPI><<<grid, 256, GEMM_SMEM>>>(A, W, bias, Hf, M, N, K, K);
}

static void run_gemm_sk(const __half* A, const __half* W, __half* Pf,
                        int M, int N, int K)
{
    dim3 grid(N / 128, M / 128, KSPLIT);
    gemm_mma_kernel<3><<<grid, 256, GEMM_SMEM>>>(A, W, nullptr, Pf,
                                                 M, N, K, K / KSPLIT);
}

extern "C" void kernel_launch(void* const* d_in, const int* in_sizes, int n_in,
                              void* d_out, int out_size)
{
    const float* src = (const float*)d_in[0];
    const float* qw  = (const float*)d_in[1];
    const float* qb  = (const float*)d_in[2];
    const float* kw  = (const float*)d_in[3];
    const float* kb  = (const float*)d_in[4];
    const float* vw  = (const float*)d_in[5];
    const float* vb  = (const float*)d_in[6];
    const float* ow  = (const float*)d_in[7];
    const float* ob  = (const float*)d_in[8];
    const float* w1  = (const float*)d_in[9];
    const float* b1  = (const float*)d_in[10];
    const float* w2  = (const float*)d_in[11];
    const float* b2  = (const float*)d_in[12];
    const float* g1  = (const float*)d_in[13];
    const float* be1 = (const float*)d_in[14];
    const float* g2  = (const float*)d_in[15];
    const float* be2 = (const float*)d_in[16];

    cudaFuncSetAttribute((const void*)gemm_mma_kernel<1>, cudaFuncAttributeMaxDynamicSharedMemorySize, GEMM_SMEM);
    cudaFuncSetAttribute((const void*)gemm_mma_kernel<2>, cudaFuncAttributeMaxDynamicSharedMemorySize, GEMM_SMEM);
    cudaFuncSetAttribute((const void*)gemm_mma_kernel<3>, cudaFuncAttributeMaxDynamicSharedMemorySize, GEMM_SMEM);
    cudaFuncSetAttribute((const void*)attn_mma_kernel, cudaFuncAttributeMaxDynamicSharedMemorySize, ATT_SMEM);

    float *x, *bq2;
    __half *pf, *xf, *of, *fff, *wqkv, *wo, *w1c, *w2c;
    cudaGetSymbolAddress((void**)&x,    g_x);
    cudaGetSymbolAddress((void**)&bq2,  g_bq2);
    cudaGetSymbolAddress((void**)&pf,   g_pf);
    cudaGetSymbolAddress((void**)&xf,   g_xf);
    cudaGetSymbolAddress((void**)&of,   g_of);
    cudaGetSymbolAddress((void**)&fff,  g_fff);
    cudaGetSymbolAddress((void**)&wqkv, g_wqkv);
    cudaGetSymbolAddress((void**)&wo,   g_wo);
    cudaGetSymbolAddress((void**)&w1c,  g_w1c);
    cudaGetSymbolAddress((void**)&w2c,  g_w2c);

    // all weight conversions + bias packs in ONE launch (grid.y = layer)
    {
        dim3 grid((PREP_TOTAL + 255) / 256, L_);
        prep_kernel<<<grid, 256>>>(qw, kw, vw, qb, kb, vb, ow, w1, w2,
                                   wqkv, bq2, wo, w1c, w2c);
    }

    // src -> fp16 activations
    {
        const int n4 = (MROWS * D_) >> 2;
        cvt_kernel<<<(n4 + 255) / 256, 256>>>(src, xf, n4);
    }

    for (int l = 0; l < L_; l++) {
        const __half* wqkv_l = wqkv + (size_t)l * NQKV * D_;
        const __half* wo_l   = wo   + (size_t)l * D_ * D_;
        const __half* w1_l   = w1c  + (size_t)l * DFF_ * D_;
        const __half* w2_l   = w2c  + (size_t)l * D_ * DFF_;

        // fused QKV projection (Q pre-scaled by 0.125*log2e in epilogue)
        run_gemm<1>(xf, wqkv_l, bq2 + l * NQKV, fff, MROWS, NQKV, D_);

        // banded attention on packed QKV (exp2 softmax)
        {
            dim3 grid(S_ / 128, H_, B_);
            attn_mma_kernel<<<grid, 256, ATT_SMEM>>>(
                fff, fff + D_, fff + 2 * D_, NQKV, of);
        }

        // output projection: split-K=3 fp16 partials, reduced inside add_ln3
        run_gemm_sk(of, wo_l, pf, MROWS, D_, D_);
        const float* res0 = (l == 0) ? src : x;
        add_ln3_kernel<<<MROWS, 256>>>(res0, pf, ob + l * D_, g1 + l * D_, be1 + l * D_, x, xf);

        // FFN
        run_gemm<2>(xf, w1_l, b1 + l * DFF_, fff, MROWS, DFF_, D_);
        run_gemm_sk(fff, w2_l, pf, MROWS, D_, DFF_);
        float* xout = (l == L_ - 1) ? (float*)d_out : x;
        add_ln3_kernel<<<MROWS, 256>>>(x, pf, b2 + l * D_, g2 + l * D_, be2 + l * D_, xout, xf);
    }
}

// round 15
// speedup vs baseline: 1.1740x; 1.0323x over previous
#include <cuda_runtime.h>
#include <cuda_bf16.h>
#include <cuda_fp16.h>
#include <cstdint>

// Problem constants
#define B_ 2
#define S_ 2048
#define D_ 768
#define H_ 12
#define DH_ 64
#define L_ 2
#define DFF_ 3072
#define MROWS (B_ * S_)   // 4096
#define NQKV 2304
#define KSPLIT 3

// ---------------------------------------------------------------------------
// Scratch (static device globals — no allocation allowed)
// ---------------------------------------------------------------------------
__device__ float g_x  [MROWS * D_];
__device__ float g_bq2[L_ * NQKV];
__device__ __half g_pf [KSPLIT * MROWS * D_];  // split-K fp16 partials
__device__ __half g_xf [MROWS * D_];
__device__ __half g_of [MROWS * D_];
__device__ __half g_fff[MROWS * DFF_];         // QKV (M x 2304) / FFN1 (M x 3072)
__device__ __half g_wqkv[L_ * NQKV * D_];
__device__ __half g_wo  [L_ * D_ * D_];
__device__ __half g_w1c [L_ * DFF_ * D_];
__device__ __half g_w2c [L_ * D_ * DFF_];

// ---------------------------------------------------------------------------
// Baseline-PTX tensor-core helpers
// ---------------------------------------------------------------------------
__device__ __forceinline__ uint32_t smem_u32(const void* p) {
    uint32_t a;
    asm("{ .reg .u64 t; cvta.to.shared.u64 t, %1; cvt.u32.u64 %0, t; }"
        : "=r"(a) : "l"(p));
    return a;
}
__device__ __forceinline__ void ldsm_x4(uint32_t& r0, uint32_t& r1,
                                        uint32_t& r2, uint32_t& r3, uint32_t a) {
    asm volatile("ldmatrix.sync.aligned.m8n8.x4.shared.b16 {%0,%1,%2,%3}, [%4];"
                 : "=r"(r0), "=r"(r1), "=r"(r2), "=r"(r3) : "r"(a));
}
__device__ __forceinline__ void ldsm_x2(uint32_t& r0, uint32_t& r1, uint32_t a) {
    asm volatile("ldmatrix.sync.aligned.m8n8.x2.shared.b16 {%0,%1}, [%2];"
                 : "=r"(r0), "=r"(r1) : "r"(a));
}
__device__ __forceinline__ void ldsm_x2t(uint32_t& r0, uint32_t& r1, uint32_t a) {
    asm volatile("ldmatrix.sync.aligned.m8n8.x2.trans.shared.b16 {%0,%1}, [%2];"
                 : "=r"(r0), "=r"(r1) : "r"(a));
}
__device__ __forceinline__ void mma_f16(float* d, const uint32_t* a, const uint32_t* b) {
    asm volatile(
        "mma.sync.aligned.m16n8k16.row.col.f32.f16.f16.f32 "
        "{%0,%1,%2,%3}, {%4,%5,%6,%7}, {%8,%9}, {%0,%1,%2,%3};"
        : "+f"(d[0]), "+f"(d[1]), "+f"(d[2]), "+f"(d[3])
        : "r"(a[0]), "r"(a[1]), "r"(a[2]), "r"(a[3]), "r"(b[0]), "r"(b[1]));
}
#define CP16(dst, src) \
    asm volatile("cp.async.cg.shared.global [%0], [%1], 16;" :: "r"(dst), "l"(src))
#define CP_COMMIT() asm volatile("cp.async.commit_group;" ::: "memory")
#define CP_WAIT0()  asm volatile("cp.async.wait_group 0;" ::: "memory")
#define CP_WAIT1()  asm volatile("cp.async.wait_group 1;" ::: "memory")

__device__ __forceinline__ uint32_t packh(float a, float b) {
    __half2 t = __floats2half2_rn(a, b);
    return *(uint32_t*)&t;
}

// ---------------------------------------------------------------------------
// Convert fp32 -> fp16 (single source)
// ---------------------------------------------------------------------------
__global__ __launch_bounds__(256) void cvt_kernel(
    const float* __restrict__ in, __half* __restrict__ out, int n4)
{
    int i = blockIdx.x * blockDim.x + threadIdx.x;
    if (i >= n4) return;
    float4 x = ((const float4*)in)[i];
    __half2* op = (__half2*)out;
    op[2 * i + 0] = __floats2half2_rn(x.x, x.y);
    op[2 * i + 1] = __floats2half2_rn(x.z, x.w);
}

// ---------------------------------------------------------------------------
// Weight prep for ALL layers in one launch (blockIdx.y = layer)
// ---------------------------------------------------------------------------
#define RQ ((D_ * D_) >> 2)
#define RW ((DFF_ * D_) >> 2)
#define PREP_B0 (3 * RQ)
#define PREP_B1 (PREP_B0 + RQ)
#define PREP_B2 (PREP_B1 + RW)
#define PREP_B3 (PREP_B2 + RW)
#define PREP_TOTAL (PREP_B3 + NQKV)

__global__ __launch_bounds__(256) void prep_kernel(
    const float* __restrict__ qw, const float* __restrict__ kw,
    const float* __restrict__ vw, const float* __restrict__ qb,
    const float* __restrict__ kb, const float* __restrict__ vb,
    const float* __restrict__ ow, const float* __restrict__ w1,
    const float* __restrict__ w2,
    __half* __restrict__ wqkv, float* __restrict__ bq,
    __half* __restrict__ wo, __half* __restrict__ w1c, __half* __restrict__ w2c)
{
    const int l = blockIdx.y;
    const int i = blockIdx.x * 256 + threadIdx.x;
    if (i >= PREP_TOTAL) return;

    const float* qwl = qw + (size_t)l * D_ * D_;
    const float* kwl = kw + (size_t)l * D_ * D_;
    const float* vwl = vw + (size_t)l * D_ * D_;
    const float* owl = ow + (size_t)l * D_ * D_;
    const float* w1l = w1 + (size_t)l * DFF_ * D_;
    const float* w2l = w2 + (size_t)l * D_ * DFF_;
    __half* wqkvl = wqkv + (size_t)l * NQKV * D_;
    __half* wol   = wo   + (size_t)l * D_ * D_;
    __half* w1cl  = w1c  + (size_t)l * DFF_ * D_;
    __half* w2cl  = w2c  + (size_t)l * D_ * DFF_;

    if (i >= PREP_B3) {
        const int j = i - PREP_B3;
        float v;
        if (j < D_)          v = qb[l * D_ + j];
        else if (j < 2 * D_) v = kb[l * D_ + j - D_];
        else                 v = vb[l * D_ + j - 2 * D_];
        bq[l * NQKV + j] = v;
        return;
    }
    const float* src;
    __half* dst;
    int j, oj;
    if (i < PREP_B0) {
        oj = i;
        src = (i < RQ) ? qwl : (i < 2 * RQ) ? kwl : vwl;
        j = (i < RQ) ? i : (i < 2 * RQ) ? i - RQ : i - 2 * RQ;
        dst = wqkvl;
    } else if (i < PREP_B1) {
        j = i - PREP_B0; oj = j; src = owl; dst = wol;
    } else if (i < PREP_B2) {
        j = i - PREP_B1; oj = j; src = w1l; dst = w1cl;
    } else {
        j = i - PREP_B2; oj = j; src = w2l; dst = w2cl;
    }
    float4 x = ((const float4*)src)[j];
    __half2* op = (__half2*)dst;
    op[2 * oj + 0] = __floats2half2_rn(x.x, x.y);
    op[2 * oj + 1] = __floats2half2_rn(x.z, x.w);
}

// ---------------------------------------------------------------------------
// fp16 mma.sync GEMM (R9 champion config): C = A[M,K] @ W[N,K]^T (+bias)
// EPI: 1 = fp16 out (+bias, Q cols x 0.125*log2e); 2 = relu + fp16 out (+bias);
//      3 = raw fp16 partial (no bias), at Hf + z*M*N
// ---------------------------------------------------------------------------
#define RS_B 144
#define TILE_B (128 * RS_B)
#define STAGE_B (2 * TILE_B)
#define GEMM_SMEM (2 * STAGE_B)

// 0.125 * log2(e): folds the attention scale and exp->exp2.
#define QSCALE 0.18033688011112042f

template <int EPI>
__global__ __launch_bounds__(256, 2) void gemm_mma_kernel(
    const __half* __restrict__ A, const __half* __restrict__ W,
    const float* __restrict__ bias,
    __half* __restrict__ Hf, int M, int N, int K, int klen)
{
    extern __shared__ char smem[];
    const uint32_t sb = smem_u32(smem);

    const int tid = threadIdx.x;
    const int wid = tid >> 5;
    const int lane = tid & 31;
    const int warp_m = wid >> 2;
    const int warp_n = wid & 3;
    const int bm = blockIdx.y * 128;
    const int bn = blockIdx.x * 128;
    const int kstart = blockIdx.z * klen;

    float acc[4][4][4];
#pragma unroll
    for (int mi = 0; mi < 4; mi++)
#pragma unroll
        for (int ni = 0; ni < 4; ni++)
#pragma unroll
            for (int r = 0; r < 4; r++) acc[mi][ni][r] = 0.f;

    auto load_chunk = [&](int kc, int stage) {
        const uint32_t base = sb + stage * STAGE_B;
#pragma unroll
        for (int t = 0; t < 4; t++) {
            const int idx = tid + t * 256;
            const int lr = idx >> 3, ls = idx & 7;
            CP16(base + lr * RS_B + ls * 16,
                 A + (size_t)(bm + lr) * K + kstart + kc + ls * 8);
        }
#pragma unroll
        for (int t = 0; t < 4; t++) {
            const int idx = tid + t * 256;
            const int lr = idx >> 3, ls = idx & 7;
            CP16(base + TILE_B + lr * RS_B + ls * 16,
                 W + (size_t)(bn + lr) * K + kstart + kc + ls * 8);
        }
    };

    const int arow = warp_m * 64 + (lane & 15);
    const int akb  = (lane >> 4) * 8;
    const int bg_ni = (lane >> 4);
    const int bg_kh = ((lane >> 3) & 1) * 8;
    const int brow_l = lane & 7;

    auto compute = [&](int stage) {
        const uint32_t base = sb + stage * STAGE_B;
        const uint32_t pA = base;
        const uint32_t pB = base + TILE_B;
#pragma unroll
        for (int ks = 0; ks < 4; ks++) {
            const int k0 = ks * 16;
            uint32_t af[4][4], bf[4][2];
#pragma unroll
            for (int mi = 0; mi < 4; mi++) {
                const uint32_t ro = (uint32_t)(arow + mi * 16) * RS_B + (k0 + akb) * 2;
                ldsm_x4(af[mi][0], af[mi][1], af[mi][2], af[mi][3], pA + ro);
            }
#pragma unroll
            for (int np = 0; np < 2; np++) {
                const int nrow = warp_n * 32 + (np * 2 + bg_ni) * 8 + brow_l;
                const uint32_t ro = (uint32_t)nrow * RS_B + (k0 + bg_kh) * 2;
                ldsm_x4(bf[np * 2][0], bf[np * 2][1], bf[np * 2 + 1][0], bf[np * 2 + 1][1], pB + ro);
            }
#pragma unroll
            for (int mi = 0; mi < 4; mi++)
#pragma unroll
                for (int ni = 0; ni < 4; ni++)
                    mma_f16(acc[mi][ni], af[mi], bf[ni]);
        }
    };

    const int nchunks = klen >> 6;
    load_chunk(0, 0);
    CP_COMMIT();

    for (int c = 0; c < nchunks; c++) {
        CP_WAIT0();
        __syncthreads();
        if (c + 1 < nchunks) {
            load_chunk((c + 1) << 6, (c + 1) & 1);
            CP_COMMIT();
        }
        compute(c & 1);
    }

    // epilogue
    __half* Hz = (EPI == 3) ? (Hf + (size_t)blockIdx.z * M * N) : Hf;
#pragma unroll
    for (int mi = 0; mi < 4; mi++) {
        const int m0 = bm + warp_m * 64 + mi * 16 + (lane >> 2);
#pragma unroll
        for (int ni = 0; ni < 4; ni++) {
            const int n0 = bn + warp_n * 32 + ni * 8 + (lane & 3) * 2;
            float v00 = acc[mi][ni][0], v01 = acc[mi][ni][1];
            float v10 = acc[mi][ni][2], v11 = acc[mi][ni][3];
            if (EPI != 3) {
                const float bx = bias[n0], by = bias[n0 + 1];
                v00 += bx; v01 += by; v10 += bx; v11 += by;
            }
            if (EPI == 1) {
                const float sc = (n0 < 768) ? QSCALE : 1.0f;
                v00 *= sc; v01 *= sc; v10 *= sc; v11 *= sc;
            }
            if (EPI == 2) {
                v00 = fmaxf(v00, 0.f); v01 = fmaxf(v01, 0.f);
                v10 = fmaxf(v10, 0.f); v11 = fmaxf(v11, 0.f);
            }
            *(uint32_t*)(Hz + (size_t)m0 * N + n0) = packh(v00, v01);
            *(uint32_t*)(Hz + (size_t)(m0 + 8) * N + n0) = packh(v10, v11);
        }
    }
}

// ---------------------------------------------------------------------------
// Tensor-core banded flash attention, fp16, 64-key tiles, exp2 softmax,
// interior-tile fast path (no masking when the whole warp-tile is in-band).
// 2 CTAs/SM. Band |i-j| <= 256. Q pre-scaled by 0.125*log2e.
// ---------------------------------------------------------------------------
#define ATT_RSB 144
#define ATT_QTILE_B (128 * ATT_RSB)
#define ATT_KTILE_B (64 * ATT_RSB)
#define ATT_SMEM (ATT_QTILE_B + 4 * ATT_KTILE_B)  // 55296

__global__ __launch_bounds__(256, 2) void attn_mma_kernel(
    const __half* __restrict__ Qf, const __half* __restrict__ Kf,
    const __half* __restrict__ Vf, int ldq, __half* __restrict__ Of)
{
    extern __shared__ char smem[];
    const uint32_t sb = smem_u32(smem);
    const int b = blockIdx.z;
    const int h = blockIdx.y;
    const int qt = blockIdx.x;
    const int q0 = qt * 128;
    const int tid = threadIdx.x;
    const int wid = tid >> 5;
    const int lane = tid & 31;
    const int g = lane >> 2;
    const int tq = lane & 3;

    const uint32_t sQ = sb;
    const uint32_t sKV0 = sb + ATT_QTILE_B;

    {
        const int row = tid >> 1, seg = tid & 1;
#pragma unroll
        for (int t = 0; t < 4; t++) {
            const size_t go = (size_t)(b * S_ + q0 + row) * ldq + h * 64 + (seg * 4 + t) * 8;
            CP16(sQ + (uint32_t)row * ATT_RSB + (seg * 4 + t) * 16, Qf + go);
        }
    }
    CP_COMMIT();

    const int ktmax = S_ / 64 - 1;
    int kt_lo = (q0 - 256) >> 6; if (kt_lo < 0) kt_lo = 0;
    int kt_hi = (q0 + 127 + 256) >> 6; if (kt_hi > ktmax) kt_hi = ktmax;

    auto load_kv = [&](int kt, int stg) {
        const uint32_t base = sKV0 + stg * 2 * ATT_KTILE_B;
        const int row = tid >> 2;
        const int s0  = (tid & 3) * 2;
#pragma unroll
        for (int t = 0; t < 2; t++) {
            const int seg = s0 + t;
            const size_t go = (size_t)(b * S_ + kt * 64 + row) * ldq + h * 64 + seg * 8;
            const uint32_t so = (uint32_t)row * ATT_RSB + seg * 16;
            CP16(base + so,               Kf + go);
            CP16(base + ATT_KTILE_B + so, Vf + go);
        }
    };
    load_kv(kt_lo, 0);
    CP_COMMIT();

    CP_WAIT1();
    __syncthreads();

    uint32_t qf[4][4];
    {
        const int arow = wid * 16 + (lane & 15);
        const int akb = (lane >> 4) * 8;
#pragma unroll
        for (int ks = 0; ks < 4; ks++) {
            const uint32_t ro = (uint32_t)arow * ATT_RSB + (ks * 16 + akb) * 2;
            ldsm_x4(qf[ks][0], qf[ks][1], qf[ks][2], qf[ks][3], sQ + ro);
        }
    }

    float m0 = -1e30f, m1 = -1e30f, l0 = 0.f, l1 = 0.f;
    float o[8][4];
#pragma unroll
    for (int nd = 0; nd < 8; nd++)
#pragma unroll
        for (int r = 0; r < 4; r++) o[nd][r] = 0.f;

    const int rlo = q0 + wid * 16;
    const int row0 = rlo + g;
    const int brow0 = lane & 7;
    const int bkb = ((lane >> 3) & 1) * 8;
    const int vrow = lane & 15;

    for (int kt = kt_lo; kt <= kt_hi; kt++) {
        const int stg = (kt - kt_lo) & 1;
        if (kt < kt_hi) {
            load_kv(kt + 1, stg ^ 1);
            CP_COMMIT();
            CP_WAIT1();
        } else {
            CP_WAIT0();
        }
        __syncthreads();

        const uint32_t base = sKV0 + stg * 2 * ATT_KTILE_B;
        const uint32_t pK = base, pV = base + ATT_KTILE_B;

        const int cbase = kt * 64;
        // warp-uniform: is this key tile fully inside the band for all 16 q-rows?
        const bool interior = (cbase >= rlo - 241) && (cbase <= rlo + 193);

        int ntlo, nthi;
        if (interior) { ntlo = 0; nthi = 7; }
        else {
            const int T1 = rlo - 256 - cbase;
            const int T2 = rlo + 15 + 256 - cbase;
            ntlo = (T1 > 0) ? (T1 >> 3) : 0;
            nthi = (T2 < 0) ? -1 : (T2 >> 3);
            if (nthi > 7) nthi = 7;
        }

        float s[8][4];
#pragma unroll
        for (int nt = 0; nt < 8; nt++)
#pragma unroll
            for (int r = 0; r < 4; r++) s[nt][r] = 0.f;

        float rmax0 = -1e30f, rmax1 = -1e30f;

        if (interior) {
            // full tile, no masking
#pragma unroll
            for (int ks = 0; ks < 4; ks++) {
#pragma unroll
                for (int nt = 0; nt < 8; nt++) {
                    uint32_t bk[2];
                    const uint32_t ro = (uint32_t)(nt * 8 + brow0) * ATT_RSB + (ks * 16 + bkb) * 2;
                    ldsm_x2(bk[0], bk[1], pK + ro);
                    mma_f16(s[nt], qf[ks], bk);
                }
            }
#pragma unroll
            for (int nt = 0; nt < 8; nt++) {
                rmax0 = fmaxf(rmax0, fmaxf(s[nt][0], s[nt][1]));
                rmax1 = fmaxf(rmax1, fmaxf(s[nt][2], s[nt][3]));
            }
        } else {
#pragma unroll
            for (int ks = 0; ks < 4; ks++) {
#pragma unroll
                for (int nt = 0; nt < 8; nt++) {
                    if (nt < ntlo || nt > nthi) continue;
                    uint32_t bk[2];
                    const uint32_t ro = (uint32_t)(nt * 8 + brow0) * ATT_RSB + (ks * 16 + bkb) * 2;
                    ldsm_x2(bk[0], bk[1], pK + ro);
                    mma_f16(s[nt], qf[ks], bk);
                }
            }
#pragma unroll
            for (int nt = 0; nt < 8; nt++) {
                if (nt < ntlo || nt > nthi) continue;
                const int col = cbase + nt * 8 + tq * 2;
                const bool i00 = (unsigned)(row0 - col + 256) <= 512u;
                const bool i01 = (unsigned)(row0 - col - 1 + 256) <= 512u;
                const bool i10 = (unsigned)(row0 + 8 - col + 256) <= 512u;
                const bool i11 = (unsigned)(row0 + 8 - col - 1 + 256) <= 512u;
                s[nt][0] = i00 ? s[nt][0] : -1e30f;
                s[nt][1] = i01 ? s[nt][1] : -1e30f;
                s[nt][2] = i10 ? s[nt][2] : -1e30f;
                s[nt][3] = i11 ? s[nt][3] : -1e30f;
                rmax0 = fmaxf(rmax0, fmaxf(s[nt][0], s[nt][1]));
                rmax1 = fmaxf(rmax1, fmaxf(s[nt][2], s[nt][3]));
            }
        }
        rmax0 = fmaxf(rmax0, __shfl_xor_sync(0xffffffffu, rmax0, 1));
        rmax0 = fmaxf(rmax0, __shfl_xor_sync(0xffffffffu, rmax0, 2));
        rmax1 = fmaxf(rmax1, __shfl_xor_sync(0xffffffffu, rmax1, 1));
        rmax1 = fmaxf(rmax1, __shfl_xor_sync(0xffffffffu, rmax1, 2));

        const float nm0 = fmaxf(m0, rmax0);
        const float nm1 = fmaxf(m1, rmax1);
        const float c0 = exp2f(m0 - nm0);
        const float c1 = exp2f(m1 - nm1);
        m0 = nm0; m1 = nm1;

        float add0 = 0.f, add1 = 0.f;
        uint32_t p[8][2];
        if (interior) {
#pragma unroll
            for (int nt = 0; nt < 8; nt++) {
                const float p00 = exp2f(s[nt][0] - nm0);
                const float p01 = exp2f(s[nt][1] - nm0);
                const float p10 = exp2f(s[nt][2] - nm1);
                const float p11 = exp2f(s[nt][3] - nm1);
                add0 += p00 + p01;
                add1 += p10 + p11;
                p[nt][0] = packh(p00, p01);
                p[nt][1] = packh(p10, p11);
            }
        } else {
#pragma unroll
            for (int nt = 0; nt < 8; nt++) {
                if (nt < ntlo || nt > nthi) { p[nt][0] = 0; p[nt][1] = 0; continue; }
                const float p00 = exp2f(s[nt][0] - nm0);
                const float p01 = exp2f(s[nt][1] - nm0);
                const float p10 = exp2f(s[nt][2] - nm1);
                const float p11 = exp2f(s[nt][3] - nm1);
                add0 += p00 + p01;
                add1 += p10 + p11;
                p[nt][0] = packh(p00, p01);
                p[nt][1] = packh(p10, p11);
            }
        }
        add0 += __shfl_xor_sync(0xffffffffu, add0, 1);
        add0 += __shfl_xor_sync(0xffffffffu, add0, 2);
        add1 += __shfl_xor_sync(0xffffffffu, add1, 1);
        add1 += __shfl_xor_sync(0xffffffffu, add1, 2);
        l0 = l0 * c0 + add0;
        l1 = l1 * c1 + add1;
#pragma unroll
        for (int nd = 0; nd < 8; nd++) {
            o[nd][0] *= c0; o[nd][1] *= c0;
            o[nd][2] *= c1; o[nd][3] *= c1;
        }

        // O += P · V
#pragma unroll
        for (int ks = 0; ks < 4; ks++) {
            if (!interior && (2 * ks + 1 < ntlo || 2 * ks > nthi)) continue;
            uint32_t a[4] = {p[2 * ks][0], p[2 * ks][1], p[2 * ks + 1][0], p[2 * ks + 1][1]};
#pragma unroll
            for (int nd = 0; nd < 8; nd++) {
                uint32_t bv[2];
                const uint32_t ro = (uint32_t)(ks * 16 + vrow) * ATT_RSB + nd * 16;
                ldsm_x2t(bv[0], bv[1], pV + ro);
                mma_f16(o[nd], a, bv);
            }
        }
        __syncthreads();
    }

    const float inv0 = 1.f / l0;
    const float inv1 = 1.f / l1;
#pragma unroll
    for (int nd = 0; nd < 8; nd++) {
        const int d = nd * 8 + tq * 2;
        const size_t o0 = (size_t)(b * S_ + row0) * D_ + h * 64 + d;
        const size_t o1 = (size_t)(b * S_ + row0 + 8) * D_ + h * 64 + d;
        *(uint32_t*)(Of + o0) = packh(o[nd][0] * inv0, o[nd][1] * inv0);
        *(uint32_t*)(Of + o1) = packh(o[nd][2] * inv1, o[nd][3] * inv1);
    }
}

// ---------------------------------------------------------------------------
// Fused split-K reduce (fp16 partials) + bias + residual add + LayerNorm.
// ---------------------------------------------------------------------------
__global__ __launch_bounds__(256) void add_ln3_kernel(
    const float* __restrict__ res, const __half* __restrict__ parts,
    const float* __restrict__ bias,
    const float* __restrict__ g, const float* __restrict__ be,
    float* __restrict__ xout, __half* __restrict__ xf)
{
    const int row = blockIdx.x;
    const int tid = threadIdx.x;
    const float* xp = res + (size_t)row * D_;
    const __half* p0 = parts + (size_t)row * D_;
    const __half* p1 = parts + (size_t)MROWS * D_ + (size_t)row * D_;
    const __half* p2 = parts + 2 * (size_t)MROWS * D_ + (size_t)row * D_;

    float v[3];
    float s1 = 0.f, s2 = 0.f;
#pragma unroll
    for (int i = 0; i < 3; i++) {
        const int c = tid + 256 * i;
        const float ps = (__half2float(p0[c]) + __half2float(p1[c])) + __half2float(p2[c]);
        v[i] = xp[c] + ps + bias[c];
        s1 += v[i];
        s2 += v[i] * v[i];
    }
#pragma unroll
    for (int off = 16; off; off >>= 1) {
        s1 += __shfl_xor_sync(0xffffffffu, s1, off);
        s2 += __shfl_xor_sync(0xffffffffu, s2, off);
    }
    __shared__ float r1[8], r2[8];
    if ((tid & 31) == 0) { r1[tid >> 5] = s1; r2[tid >> 5] = s2; }
    __syncthreads();
    s1 = 0.f; s2 = 0.f;
#pragma unroll
    for (int i = 0; i < 8; i++) { s1 += r1[i]; s2 += r2[i]; }

    const float mean = s1 * (1.f / 768.f);
    const float var  = s2 * (1.f / 768.f) - mean * mean;
    const float rstd = rsqrtf(var + 1e-5f);
#pragma unroll
    for (int i = 0; i < 3; i++) {
        const int c = tid + 256 * i;
        const float val = (v[i] - mean) * rstd * g[c] + be[c];
        xout[(size_t)row * D_ + c] = val;
        xf[(size_t)row * D_ + c] = __float2half_rn(val);
    }
}

// ---------------------------------------------------------------------------
// Host orchestration
// ---------------------------------------------------------------------------
template <int EPI>
static void run_gemm(const __half* A, const __half* W, const float* bias,
                     __half* Hf, int M, int N, int K)
{
    dim3 grid(N / 128, M / 128, 1);
    gemm_mma_kernel<EPI><<<grid, 256, GEMM_SMEM>>>(A, W, bias, Hf, M, N, K, K);
}

static void run_gemm_sk(const __half* A, const __half* W, __half* Pf,
                        int M, int N, int K)
{
    dim3 grid(N / 128, M / 128, KSPLIT);
    gemm_mma_kernel<3><<<grid, 256, GEMM_SMEM>>>(A, W, nullptr, Pf,
                                                 M, N, K, K / KSPLIT);
}

extern "C" void kernel_launch(void* const* d_in, const int* in_sizes, int n_in,
                              void* d_out, int out_size)
{
    const float* src = (const float*)d_in[0];
    const float* qw  = (const float*)d_in[1];
    const float* qb  = (const float*)d_in[2];
    const float* kw  = (const float*)d_in[3];
    const float* kb  = (const float*)d_in[4];
    const float* vw  = (const float*)d_in[5];
    const float* vb  = (const float*)d_in[6];
    const float* ow  = (const float*)d_in[7];
    const float* ob  = (const float*)d_in[8];
    const float* w1  = (const float*)d_in[9];
    const float* b1  = (const float*)d_in[10];
    const float* w2  = (const float*)d_in[11];
    const float* b2  = (const float*)d_in[12];
    const float* g1  = (const float*)d_in[13];
    const float* be1 = (const float*)d_in[14];
    const float* g2  = (const float*)d_in[15];
    const float* be2 = (const float*)d_in[16];

    cudaFuncSetAttribute((const void*)gemm_mma_kernel<1>, cudaFuncAttributeMaxDynamicSharedMemorySize, GEMM_SMEM);
    cudaFuncSetAttribute((const void*)gemm_mma_kernel<2>, cudaFuncAttributeMaxDynamicSharedMemorySize, GEMM_SMEM);
    cudaFuncSetAttribute((const void*)gemm_mma_kernel<3>, cudaFuncAttributeMaxDynamicSharedMemorySize, GEMM_SMEM);
    cudaFuncSetAttribute((const void*)attn_mma_kernel, cudaFuncAttributeMaxDynamicSharedMemorySize, ATT_SMEM);

    float *x, *bq2;
    __half *pf, *xf, *of, *fff, *wqkv, *wo, *w1c, *w2c;
    cudaGetSymbolAddress((void**)&x,    g_x);
    cudaGetSymbolAddress((void**)&bq2,  g_bq2);
    cudaGetSymbolAddress((void**)&pf,   g_pf);
    cudaGetSymbolAddress((void**)&xf,   g_xf);
    cudaGetSymbolAddress((void**)&of,   g_of);
    cudaGetSymbolAddress((void**)&fff,  g_fff);
    cudaGetSymbolAddress((void**)&wqkv, g_wqkv);
    cudaGetSymbolAddress((void**)&wo,   g_wo);
    cudaGetSymbolAddress((void**)&w1c,  g_w1c);
    cudaGetSymbolAddress((void**)&w2c,  g_w2c);

    // all weight conversions + bias packs in ONE launch (grid.y = layer)
    {
        dim3 grid((PREP_TOTAL + 255) / 256, L_);
        prep_kernel<<<grid, 256>>>(qw, kw, vw, qb, kb, vb, ow, w1, w2,
                                   wqkv, bq2, wo, w1c, w2c);
    }

    // src -> fp16 activations
    {
        const int n4 = (MROWS * D_) >> 2;
        cvt_kernel<<<(n4 + 255) / 256, 256>>>(src, xf, n4);
    }

    for (int l = 0; l < L_; l++) {
        const __half* wqkv_l = wqkv + (size_t)l * NQKV * D_;
        const __half* wo_l   = wo   + (size_t)l * D_ * D_;
        const __half* w1_l   = w1c  + (size_t)l * DFF_ * D_;
        const __half* w2_l   = w2c  + (size_t)l * D_ * DFF_;

        // fused QKV projection (Q pre-scaled by 0.125*log2e in epilogue)
        run_gemm<1>(xf, wqkv_l, bq2 + l * NQKV, fff, MROWS, NQKV, D_);

        // banded attention on packed QKV (exp2 softmax, interior fast path)
        {
            dim3 grid(S_ / 128, H_, B_);
            attn_mma_kernel<<<grid, 256, ATT_SMEM>>>(
                fff, fff + D_, fff + 2 * D_, NQKV, of);
        }

        // output projection: split-K=3 fp16 partials, reduced inside add_ln3
        run_gemm_sk(of, wo_l, pf, MROWS, D_, D_);
        const float* res0 = (l == 0) ? src : x;
        add_ln3_kernel<<<MROWS, 256>>>(res0, pf, ob + l * D_, g1 + l * D_, be1 + l * D_, x, xf);

        // FFN
        run_gemm<2>(xf, w1_l, b1 + l * DFF_, fff, MROWS, DFF_, D_);
        run_gemm_sk(fff, w2_l, pf, MROWS, D_, DFF_);
        float* xout = (l == L_ - 1) ? (float*)d_out : x;
        add_ln3_kernel<<<MROWS, 256>>>(x, pf, b2 + l * D_, g2 + l * D_, be2 + l * D_, xout, xf);
    }
}

// round 16
// speedup vs baseline: 1.1787x; 1.0040x over previous
#include <cuda_runtime.h>
#include <cuda_bf16.h>
#include <cuda_fp16.h>
#include <cstdint>

// Problem constants
#define B_ 2
#define S_ 2048
#define D_ 768
#define H_ 12
#define DH_ 64
#define L_ 2
#define DFF_ 3072
#define MROWS (B_ * S_)   // 4096
#define NQKV 2304
#define KSPLIT 3

// ---------------------------------------------------------------------------
// Scratch (static device globals — no allocation allowed)
// ---------------------------------------------------------------------------
__device__ float g_x  [MROWS * D_];
__device__ float g_bq2[L_ * NQKV];
__device__ __half g_pf [KSPLIT * MROWS * D_];  // split-K fp16 partials
__device__ __half g_xf [MROWS * D_];
__device__ __half g_of [MROWS * D_];
__device__ __half g_fff[MROWS * DFF_];         // QKV (M x 2304) / FFN1 (M x 3072)
__device__ __half g_wqkv[L_ * NQKV * D_];
__device__ __half g_wo  [L_ * D_ * D_];
__device__ __half g_w1c [L_ * DFF_ * D_];
__device__ __half g_w2c [L_ * D_ * DFF_];

// ---------------------------------------------------------------------------
// Baseline-PTX tensor-core helpers
// ---------------------------------------------------------------------------
__device__ __forceinline__ uint32_t smem_u32(const void* p) {
    uint32_t a;
    asm("{ .reg .u64 t; cvta.to.shared.u64 t, %1; cvt.u32.u64 %0, t; }"
        : "=r"(a) : "l"(p));
    return a;
}
__device__ __forceinline__ void ldsm_x4(uint32_t& r0, uint32_t& r1,
                                        uint32_t& r2, uint32_t& r3, uint32_t a) {
    asm volatile("ldmatrix.sync.aligned.m8n8.x4.shared.b16 {%0,%1,%2,%3}, [%4];"
                 : "=r"(r0), "=r"(r1), "=r"(r2), "=r"(r3) : "r"(a));
}
__device__ __forceinline__ void ldsm_x4t(uint32_t& r0, uint32_t& r1,
                                         uint32_t& r2, uint32_t& r3, uint32_t a) {
    asm volatile("ldmatrix.sync.aligned.m8n8.x4.trans.shared.b16 {%0,%1,%2,%3}, [%4];"
                 : "=r"(r0), "=r"(r1), "=r"(r2), "=r"(r3) : "r"(a));
}
__device__ __forceinline__ void ldsm_x2(uint32_t& r0, uint32_t& r1, uint32_t a) {
    asm volatile("ldmatrix.sync.aligned.m8n8.x2.shared.b16 {%0,%1}, [%2];"
                 : "=r"(r0), "=r"(r1) : "r"(a));
}
__device__ __forceinline__ void ldsm_x2t(uint32_t& r0, uint32_t& r1, uint32_t a) {
    asm volatile("ldmatrix.sync.aligned.m8n8.x2.trans.shared.b16 {%0,%1}, [%2];"
                 : "=r"(r0), "=r"(r1) : "r"(a));
}
__device__ __forceinline__ void mma_f16(float* d, const uint32_t* a, const uint32_t* b) {
    asm volatile(
        "mma.sync.aligned.m16n8k16.row.col.f32.f16.f16.f32 "
        "{%0,%1,%2,%3}, {%4,%5,%6,%7}, {%8,%9}, {%0,%1,%2,%3};"
        : "+f"(d[0]), "+f"(d[1]), "+f"(d[2]), "+f"(d[3])
        : "r"(a[0]), "r"(a[1]), "r"(a[2]), "r"(a[3]), "r"(b[0]), "r"(b[1]));
}
#define CP16(dst, src) \
    asm volatile("cp.async.cg.shared.global [%0], [%1], 16;" :: "r"(dst), "l"(src))
#define CP_COMMIT() asm volatile("cp.async.commit_group;" ::: "memory")
#define CP_WAIT0()  asm volatile("cp.async.wait_group 0;" ::: "memory")
#define CP_WAIT1()  asm volatile("cp.async.wait_group 1;" ::: "memory")

__device__ __forceinline__ uint32_t packh(float a, float b) {
    __half2 t = __floats2half2_rn(a, b);
    return *(uint32_t*)&t;
}

// ---------------------------------------------------------------------------
// Convert fp32 -> fp16 (single source)
// ---------------------------------------------------------------------------
__global__ __launch_bounds__(256) void cvt_kernel(
    const float* __restrict__ in, __half* __restrict__ out, int n4)
{
    int i = blockIdx.x * blockDim.x + threadIdx.x;
    if (i >= n4) return;
    float4 x = ((const float4*)in)[i];
    __half2* op = (__half2*)out;
    op[2 * i + 0] = __floats2half2_rn(x.x, x.y);
    op[2 * i + 1] = __floats2half2_rn(x.z, x.w);
}

// ---------------------------------------------------------------------------
// Weight prep for ALL layers in one launch (blockIdx.y = layer)
// ---------------------------------------------------------------------------
#define RQ ((D_ * D_) >> 2)
#define RW ((DFF_ * D_) >> 2)
#define PREP_B0 (3 * RQ)
#define PREP_B1 (PREP_B0 + RQ)
#define PREP_B2 (PREP_B1 + RW)
#define PREP_B3 (PREP_B2 + RW)
#define PREP_TOTAL (PREP_B3 + NQKV)

__global__ __launch_bounds__(256) void prep_kernel(
    const float* __restrict__ qw, const float* __restrict__ kw,
    const float* __restrict__ vw, const float* __restrict__ qb,
    const float* __restrict__ kb, const float* __restrict__ vb,
    const float* __restrict__ ow, const float* __restrict__ w1,
    const float* __restrict__ w2,
    __half* __restrict__ wqkv, float* __restrict__ bq,
    __half* __restrict__ wo, __half* __restrict__ w1c, __half* __restrict__ w2c)
{
    const int l = blockIdx.y;
    const int i = blockIdx.x * 256 + threadIdx.x;
    if (i >= PREP_TOTAL) return;

    const float* qwl = qw + (size_t)l * D_ * D_;
    const float* kwl = kw + (size_t)l * D_ * D_;
    const float* vwl = vw + (size_t)l * D_ * D_;
    const float* owl = ow + (size_t)l * D_ * D_;
    const float* w1l = w1 + (size_t)l * DFF_ * D_;
    const float* w2l = w2 + (size_t)l * D_ * DFF_;
    __half* wqkvl = wqkv + (size_t)l * NQKV * D_;
    __half* wol   = wo   + (size_t)l * D_ * D_;
    __half* w1cl  = w1c  + (size_t)l * DFF_ * D_;
    __half* w2cl  = w2c  + (size_t)l * D_ * DFF_;

    if (i >= PREP_B3) {
        const int j = i - PREP_B3;
        float v;
        if (j < D_)          v = qb[l * D_ + j];
        else if (j < 2 * D_) v = kb[l * D_ + j - D_];
        else                 v = vb[l * D_ + j - 2 * D_];
        bq[l * NQKV + j] = v;
        return;
    }
    const float* src;
    __half* dst;
    int j, oj;
    if (i < PREP_B0) {
        oj = i;
        src = (i < RQ) ? qwl : (i < 2 * RQ) ? kwl : vwl;
        j = (i < RQ) ? i : (i < 2 * RQ) ? i - RQ : i - 2 * RQ;
        dst = wqkvl;
    } else if (i < PREP_B1) {
        j = i - PREP_B0; oj = j; src = owl; dst = wol;
    } else if (i < PREP_B2) {
        j = i - PREP_B1; oj = j; src = w1l; dst = w1cl;
    } else {
        j = i - PREP_B2; oj = j; src = w2l; dst = w2cl;
    }
    float4 x = ((const float4*)src)[j];
    __half2* op = (__half2*)dst;
    op[2 * oj + 0] = __floats2half2_rn(x.x, x.y);
    op[2 * oj + 1] = __floats2half2_rn(x.z, x.w);
}

// ---------------------------------------------------------------------------
// fp16 mma.sync GEMM (R9 champion config): C = A[M,K] @ W[N,K]^T (+bias)
// EPI: 1 = fp16 out (+bias, Q cols x 0.125*log2e); 2 = relu + fp16 out (+bias);
//      3 = raw fp16 partial (no bias), at Hf + z*M*N
// ---------------------------------------------------------------------------
#define RS_B 144
#define TILE_B (128 * RS_B)
#define STAGE_B (2 * TILE_B)
#define GEMM_SMEM (2 * STAGE_B)

// 0.125 * log2(e): folds the attention scale and exp->exp2.
#define QSCALE 0.18033688011112042f

template <int EPI>
__global__ __launch_bounds__(256, 2) void gemm_mma_kernel(
    const __half* __restrict__ A, const __half* __restrict__ W,
    const float* __restrict__ bias,
    __half* __restrict__ Hf, int M, int N, int K, int klen)
{
    extern __shared__ char smem[];
    const uint32_t sb = smem_u32(smem);

    const int tid = threadIdx.x;
    const int wid = tid >> 5;
    const int lane = tid & 31;
    const int warp_m = wid >> 2;
    const int warp_n = wid & 3;
    const int bm = blockIdx.y * 128;
    const int bn = blockIdx.x * 128;
    const int kstart = blockIdx.z * klen;

    float acc[4][4][4];
#pragma unroll
    for (int mi = 0; mi < 4; mi++)
#pragma unroll
        for (int ni = 0; ni < 4; ni++)
#pragma unroll
            for (int r = 0; r < 4; r++) acc[mi][ni][r] = 0.f;

    auto load_chunk = [&](int kc, int stage) {
        const uint32_t base = sb + stage * STAGE_B;
#pragma unroll
        for (int t = 0; t < 4; t++) {
            const int idx = tid + t * 256;
            const int lr = idx >> 3, ls = idx & 7;
            CP16(base + lr * RS_B + ls * 16,
                 A + (size_t)(bm + lr) * K + kstart + kc + ls * 8);
        }
#pragma unroll
        for (int t = 0; t < 4; t++) {
            const int idx = tid + t * 256;
            const int lr = idx >> 3, ls = idx & 7;
            CP16(base + TILE_B + lr * RS_B + ls * 16,
                 W + (size_t)(bn + lr) * K + kstart + kc + ls * 8);
        }
    };

    const int arow = warp_m * 64 + (lane & 15);
    const int akb  = (lane >> 4) * 8;
    const int bg_ni = (lane >> 4);
    const int bg_kh = ((lane >> 3) & 1) * 8;
    const int brow_l = lane & 7;

    auto compute = [&](int stage) {
        const uint32_t base = sb + stage * STAGE_B;
        const uint32_t pA = base;
        const uint32_t pB = base + TILE_B;
#pragma unroll
        for (int ks = 0; ks < 4; ks++) {
            const int k0 = ks * 16;
            uint32_t af[4][4], bf[4][2];
#pragma unroll
            for (int mi = 0; mi < 4; mi++) {
                const uint32_t ro = (uint32_t)(arow + mi * 16) * RS_B + (k0 + akb) * 2;
                ldsm_x4(af[mi][0], af[mi][1], af[mi][2], af[mi][3], pA + ro);
            }
#pragma unroll
            for (int np = 0; np < 2; np++) {
                const int nrow = warp_n * 32 + (np * 2 + bg_ni) * 8 + brow_l;
                const uint32_t ro = (uint32_t)nrow * RS_B + (k0 + bg_kh) * 2;
                ldsm_x4(bf[np * 2][0], bf[np * 2][1], bf[np * 2 + 1][0], bf[np * 2 + 1][1], pB + ro);
            }
#pragma unroll
            for (int mi = 0; mi < 4; mi++)
#pragma unroll
                for (int ni = 0; ni < 4; ni++)
                    mma_f16(acc[mi][ni], af[mi], bf[ni]);
        }
    };

    const int nchunks = klen >> 6;
    load_chunk(0, 0);
    CP_COMMIT();

    for (int c = 0; c < nchunks; c++) {
        CP_WAIT0();
        __syncthreads();
        if (c + 1 < nchunks) {
            load_chunk((c + 1) << 6, (c + 1) & 1);
            CP_COMMIT();
        }
        compute(c & 1);
    }

    // epilogue
    __half* Hz = (EPI == 3) ? (Hf + (size_t)blockIdx.z * M * N) : Hf;
#pragma unroll
    for (int mi = 0; mi < 4; mi++) {
        const int m0 = bm + warp_m * 64 + mi * 16 + (lane >> 2);
#pragma unroll
        for (int ni = 0; ni < 4; ni++) {
            const int n0 = bn + warp_n * 32 + ni * 8 + (lane & 3) * 2;
            float v00 = acc[mi][ni][0], v01 = acc[mi][ni][1];
            float v10 = acc[mi][ni][2], v11 = acc[mi][ni][3];
            if (EPI != 3) {
                const float bx = bias[n0], by = bias[n0 + 1];
                v00 += bx; v01 += by; v10 += bx; v11 += by;
            }
            if (EPI == 1) {
                const float sc = (n0 < 768) ? QSCALE : 1.0f;
                v00 *= sc; v01 *= sc; v10 *= sc; v11 *= sc;
            }
            if (EPI == 2) {
                v00 = fmaxf(v00, 0.f); v01 = fmaxf(v01, 0.f);
                v10 = fmaxf(v10, 0.f); v11 = fmaxf(v11, 0.f);
            }
            *(uint32_t*)(Hz + (size_t)m0 * N + n0) = packh(v00, v01);
            *(uint32_t*)(Hz + (size_t)(m0 + 8) * N + n0) = packh(v10, v11);
        }
    }
}

// ---------------------------------------------------------------------------
// Tensor-core banded flash attention, fp16, 64-key tiles, exp2 softmax,
// interior fast path with x4 ldmatrix batching + empty-warp-tile skip.
// 2 CTAs/SM. Band |i-j| <= 256. Q pre-scaled by 0.125*log2e.
// ---------------------------------------------------------------------------
#define ATT_RSB 144
#define ATT_QTILE_B (128 * ATT_RSB)
#define ATT_KTILE_B (64 * ATT_RSB)
#define ATT_SMEM (ATT_QTILE_B + 4 * ATT_KTILE_B)  // 55296

__global__ __launch_bounds__(256, 2) void attn_mma_kernel(
    const __half* __restrict__ Qf, const __half* __restrict__ Kf,
    const __half* __restrict__ Vf, int ldq, __half* __restrict__ Of)
{
    extern __shared__ char smem[];
    const uint32_t sb = smem_u32(smem);
    const int b = blockIdx.z;
    const int h = blockIdx.y;
    const int qt = blockIdx.x;
    const int q0 = qt * 128;
    const int tid = threadIdx.x;
    const int wid = tid >> 5;
    const int lane = tid & 31;
    const int g = lane >> 2;
    const int tq = lane & 3;

    const uint32_t sQ = sb;
    const uint32_t sKV0 = sb + ATT_QTILE_B;

    {
        const int row = tid >> 1, seg = tid & 1;
#pragma unroll
        for (int t = 0; t < 4; t++) {
            const size_t go = (size_t)(b * S_ + q0 + row) * ldq + h * 64 + (seg * 4 + t) * 8;
            CP16(sQ + (uint32_t)row * ATT_RSB + (seg * 4 + t) * 16, Qf + go);
        }
    }
    CP_COMMIT();

    const int ktmax = S_ / 64 - 1;
    int kt_lo = (q0 - 256) >> 6; if (kt_lo < 0) kt_lo = 0;
    int kt_hi = (q0 + 127 + 256) >> 6; if (kt_hi > ktmax) kt_hi = ktmax;

    auto load_kv = [&](int kt, int stg) {
        const uint32_t base = sKV0 + stg * 2 * ATT_KTILE_B;
        const int row = tid >> 2;
        const int s0  = (tid & 3) * 2;
#pragma unroll
        for (int t = 0; t < 2; t++) {
            const int seg = s0 + t;
            const size_t go = (size_t)(b * S_ + kt * 64 + row) * ldq + h * 64 + seg * 8;
            const uint32_t so = (uint32_t)row * ATT_RSB + seg * 16;
            CP16(base + so,               Kf + go);
            CP16(base + ATT_KTILE_B + so, Vf + go);
        }
    };
    load_kv(kt_lo, 0);
    CP_COMMIT();

    CP_WAIT1();
    __syncthreads();

    uint32_t qf[4][4];
    {
        const int arow = wid * 16 + (lane & 15);
        const int akb = (lane >> 4) * 8;
#pragma unroll
        for (int ks = 0; ks < 4; ks++) {
            const uint32_t ro = (uint32_t)arow * ATT_RSB + (ks * 16 + akb) * 2;
            ldsm_x4(qf[ks][0], qf[ks][1], qf[ks][2], qf[ks][3], sQ + ro);
        }
    }

    float m0 = -1e30f, m1 = -1e30f, l0 = 0.f, l1 = 0.f;
    float o[8][4];
#pragma unroll
    for (int nd = 0; nd < 8; nd++)
#pragma unroll
        for (int r = 0; r < 4; r++) o[nd][r] = 0.f;

    const int rlo = q0 + wid * 16;
    const int row0 = rlo + g;
    const int brow0 = lane & 7;
    const int bkb = ((lane >> 3) & 1) * 8;
    const int bg_ni = (lane >> 4);          // x4 K-load pairing
    const int vrow = lane & 15;
    const int vhalf = (lane >> 4);          // x4 V-load pairing

    for (int kt = kt_lo; kt <= kt_hi; kt++) {
        const int stg = (kt - kt_lo) & 1;
        if (kt < kt_hi) {
            load_kv(kt + 1, stg ^ 1);
            CP_COMMIT();
            CP_WAIT1();
        } else {
            CP_WAIT0();
        }
        __syncthreads();

        const uint32_t base = sKV0 + stg * 2 * ATT_KTILE_B;
        const uint32_t pK = base, pV = base + ATT_KTILE_B;

        const int cbase = kt * 64;
        const bool interior = (cbase >= rlo - 241) && (cbase <= rlo + 193);

        int ntlo, nthi;
        if (interior) { ntlo = 0; nthi = 7; }
        else {
            const int T1 = rlo - 256 - cbase;
            const int T2 = rlo + 15 + 256 - cbase;
            ntlo = (T1 > 0) ? (T1 >> 3) : 0;
            nthi = (T2 < 0) ? -1 : (T2 >> 3);
            if (nthi > 7) nthi = 7;
        }

        if (nthi >= ntlo) {   // warp has work in this tile
            float s[8][4];
#pragma unroll
            for (int nt = 0; nt < 8; nt++)
#pragma unroll
                for (int r = 0; r < 4; r++) s[nt][r] = 0.f;

            float rmax0 = -1e30f, rmax1 = -1e30f;

            if (interior) {
                // full tile: x4-batched K loads (GEMM B-frag lane mapping)
#pragma unroll
                for (int ks = 0; ks < 4; ks++) {
#pragma unroll
                    for (int np = 0; np < 4; np++) {
                        uint32_t b0, b1, b2, b3;
                        const int nrow = (np * 2 + bg_ni) * 8 + brow0;
                        const uint32_t ro = (uint32_t)nrow * ATT_RSB + (ks * 16 + bkb) * 2;
                        ldsm_x4(b0, b1, b2, b3, pK + ro);
                        uint32_t bl[2] = {b0, b1};
                        uint32_t bh[2] = {b2, b3};
                        mma_f16(s[np * 2],     qf[ks], bl);
                        mma_f16(s[np * 2 + 1], qf[ks], bh);
                    }
                }
#pragma unroll
                for (int nt = 0; nt < 8; nt++) {
                    rmax0 = fmaxf(rmax0, fmaxf(s[nt][0], s[nt][1]));
                    rmax1 = fmaxf(rmax1, fmaxf(s[nt][2], s[nt][3]));
                }
            } else {
#pragma unroll
                for (int ks = 0; ks < 4; ks++) {
#pragma unroll
                    for (int nt = 0; nt < 8; nt++) {
                        if (nt < ntlo || nt > nthi) continue;
                        uint32_t bk[2];
                        const uint32_t ro = (uint32_t)(nt * 8 + brow0) * ATT_RSB + (ks * 16 + bkb) * 2;
                        ldsm_x2(bk[0], bk[1], pK + ro);
                        mma_f16(s[nt], qf[ks], bk);
                    }
                }
#pragma unroll
                for (int nt = 0; nt < 8; nt++) {
                    if (nt < ntlo || nt > nthi) continue;
                    const int col = cbase + nt * 8 + tq * 2;
                    const bool i00 = (unsigned)(row0 - col + 256) <= 512u;
                    const bool i01 = (unsigned)(row0 - col - 1 + 256) <= 512u;
                    const bool i10 = (unsigned)(row0 + 8 - col + 256) <= 512u;
                    const bool i11 = (unsigned)(row0 + 8 - col - 1 + 256) <= 512u;
                    s[nt][0] = i00 ? s[nt][0] : -1e30f;
                    s[nt][1] = i01 ? s[nt][1] : -1e30f;
                    s[nt][2] = i10 ? s[nt][2] : -1e30f;
                    s[nt][3] = i11 ? s[nt][3] : -1e30f;
                    rmax0 = fmaxf(rmax0, fmaxf(s[nt][0], s[nt][1]));
                    rmax1 = fmaxf(rmax1, fmaxf(s[nt][2], s[nt][3]));
                }
            }
            rmax0 = fmaxf(rmax0, __shfl_xor_sync(0xffffffffu, rmax0, 1));
            rmax0 = fmaxf(rmax0, __shfl_xor_sync(0xffffffffu, rmax0, 2));
            rmax1 = fmaxf(rmax1, __shfl_xor_sync(0xffffffffu, rmax1, 1));
            rmax1 = fmaxf(rmax1, __shfl_xor_sync(0xffffffffu, rmax1, 2));

            const float nm0 = fmaxf(m0, rmax0);
            const float nm1 = fmaxf(m1, rmax1);
            const float c0 = exp2f(m0 - nm0);
            const float c1 = exp2f(m1 - nm1);
            m0 = nm0; m1 = nm1;

            float add0 = 0.f, add1 = 0.f;
            uint32_t p[8][2];
            if (interior) {
#pragma unroll
                for (int nt = 0; nt < 8; nt++) {
                    const float p00 = exp2f(s[nt][0] - nm0);
                    const float p01 = exp2f(s[nt][1] - nm0);
                    const float p10 = exp2f(s[nt][2] - nm1);
                    const float p11 = exp2f(s[nt][3] - nm1);
                    add0 += p00 + p01;
                    add1 += p10 + p11;
                    p[nt][0] = packh(p00, p01);
                    p[nt][1] = packh(p10, p11);
                }
            } else {
#pragma unroll
                for (int nt = 0; nt < 8; nt++) {
                    if (nt < ntlo || nt > nthi) { p[nt][0] = 0; p[nt][1] = 0; continue; }
                    const float p00 = exp2f(s[nt][0] - nm0);
                    const float p01 = exp2f(s[nt][1] - nm0);
                    const float p10 = exp2f(s[nt][2] - nm1);
                    const float p11 = exp2f(s[nt][3] - nm1);
                    add0 += p00 + p01;
                    add1 += p10 + p11;
                    p[nt][0] = packh(p00, p01);
                    p[nt][1] = packh(p10, p11);
                }
            }
            add0 += __shfl_xor_sync(0xffffffffu, add0, 1);
            add0 += __shfl_xor_sync(0xffffffffu, add0, 2);
            add1 += __shfl_xor_sync(0xffffffffu, add1, 1);
            add1 += __shfl_xor_sync(0xffffffffu, add1, 2);
            l0 = l0 * c0 + add0;
            l1 = l1 * c1 + add1;
#pragma unroll
            for (int nd = 0; nd < 8; nd++) {
                o[nd][0] *= c0; o[nd][1] *= c0;
                o[nd][2] *= c1; o[nd][3] *= c1;
            }

            // O += P · V  (x4.trans batched V loads)
#pragma unroll
            for (int ks = 0; ks < 4; ks++) {
                if (!interior && (2 * ks + 1 < ntlo || 2 * ks > nthi)) continue;
                uint32_t a[4] = {p[2 * ks][0], p[2 * ks][1], p[2 * ks + 1][0], p[2 * ks + 1][1]};
#pragma unroll
                for (int ndp = 0; ndp < 4; ndp++) {
                    uint32_t b0, b1, b2, b3;
                    const uint32_t ro = (uint32_t)(ks * 16 + vrow) * ATT_RSB
                                      + (2 * ndp + vhalf) * 16;
                    ldsm_x4t(b0, b1, b2, b3, pV + ro);
                    uint32_t bl[2] = {b0, b1};
                    uint32_t bh[2] = {b2, b3};
                    mma_f16(o[2 * ndp],     a, bl);
                    mma_f16(o[2 * ndp + 1], a, bh);
                }
            }
        }
        __syncthreads();
    }

    const float inv0 = 1.f / l0;
    const float inv1 = 1.f / l1;
#pragma unroll
    for (int nd = 0; nd < 8; nd++) {
        const int d = nd * 8 + tq * 2;
        const size_t o0 = (size_t)(b * S_ + row0) * D_ + h * 64 + d;
        const size_t o1 = (size_t)(b * S_ + row0 + 8) * D_ + h * 64 + d;
        *(uint32_t*)(Of + o0) = packh(o[nd][0] * inv0, o[nd][1] * inv0);
        *(uint32_t*)(Of + o1) = packh(o[nd][2] * inv1, o[nd][3] * inv1);
    }
}

// ---------------------------------------------------------------------------
// Fused split-K reduce (fp16 partials) + bias + residual add + LayerNorm.
// ---------------------------------------------------------------------------
__global__ __launch_bounds__(256) void add_ln3_kernel(
    const float* __restrict__ res, const __half* __restrict__ parts,
    const float* __restrict__ bias,
    const float* __restrict__ g, const float* __restrict__ be,
    float* __restrict__ xout, __half* __restrict__ xf)
{
    const int row = blockIdx.x;
    const int tid = threadIdx.x;
    const float* xp = res + (size_t)row * D_;
    const __half* p0 = parts + (size_t)row * D_;
    const __half* p1 = parts + (size_t)MROWS * D_ + (size_t)row * D_;
    const __half* p2 = parts + 2 * (size_t)MROWS * D_ + (size_t)row * D_;

    float v[3];
    float s1 = 0.f, s2 = 0.f;
#pragma unroll
    for (int i = 0; i < 3; i++) {
        const int c = tid + 256 * i;
        const float ps = (__half2float(p0[c]) + __half2float(p1[c])) + __half2float(p2[c]);
        v[i] = xp[c] + ps + bias[c];
        s1 += v[i];
        s2 += v[i] * v[i];
    }
#pragma unroll
    for (int off = 16; off; off >>= 1) {
        s1 += __shfl_xor_sync(0xffffffffu, s1, off);
        s2 += __shfl_xor_sync(0xffffffffu, s2, off);
    }
    __shared__ float r1[8], r2[8];
    if ((tid & 31) == 0) { r1[tid >> 5] = s1; r2[tid >> 5] = s2; }
    __syncthreads();
    s1 = 0.f; s2 = 0.f;
#pragma unroll
    for (int i = 0; i < 8; i++) { s1 += r1[i]; s2 += r2[i]; }

    const float mean = s1 * (1.f / 768.f);
    const float var  = s2 * (1.f / 768.f) - mean * mean;
    const float rstd = rsqrtf(var + 1e-5f);
#pragma unroll
    for (int i = 0; i < 3; i++) {
        const int c = tid + 256 * i;
        const float val = (v[i] - mean) * rstd * g[c] + be[c];
        xout[(size_t)row * D_ + c] = val;
        xf[(size_t)row * D_ + c] = __float2half_rn(val);
    }
}

// ---------------------------------------------------------------------------
// Host orchestration
// ---------------------------------------------------------------------------
template <int EPI>
static void run_gemm(const __half* A, const __half* W, const float* bias,
                     __half* Hf, int M, int N, int K)
{
    dim3 grid(N / 128, M / 128, 1);
    gemm_mma_kernel<EPI><<<grid, 256, GEMM_SMEM>>>(A, W, bias, Hf, M, N, K, K);
}

static void run_gemm_sk(const __half* A, const __half* W, __half* Pf,
                        int M, int N, int K)
{
    dim3 grid(N / 128, M / 128, KSPLIT);
    gemm_mma_kernel<3><<<grid, 256, GEMM_SMEM>>>(A, W, nullptr, Pf,
                                                 M, N, K, K / KSPLIT);
}

extern "C" void kernel_launch(void* const* d_in, const int* in_sizes, int n_in,
                              void* d_out, int out_size)
{
    const float* src = (const float*)d_in[0];
    const float* qw  = (const float*)d_in[1];
    const float* qb  = (const float*)d_in[2];
    const float* kw  = (const float*)d_in[3];
    const float* kb  = (const float*)d_in[4];
    const float* vw  = (const float*)d_in[5];
    const float* vb  = (const float*)d_in[6];
    const float* ow  = (const float*)d_in[7];
    const float* ob  = (const float*)d_in[8];
    const float* w1  = (const float*)d_in[9];
    const float* b1  = (const float*)d_in[10];
    const float* w2  = (const float*)d_in[11];
    const float* b2  = (const float*)d_in[12];
    const float* g1  = (const float*)d_in[13];
    const float* be1 = (const float*)d_in[14];
    const float* g2  = (const float*)d_in[15];
    const float* be2 = (const float*)d_in[16];

    cudaFuncSetAttribute((const void*)gemm_mma_kernel<1>, cudaFuncAttributeMaxDynamicSharedMemorySize, GEMM_SMEM);
    cudaFuncSetAttribute((const void*)gemm_mma_kernel<2>, cudaFuncAttributeMaxDynamicSharedMemorySize, GEMM_SMEM);
    cudaFuncSetAttribute((const void*)gemm_mma_kernel<3>, cudaFuncAttributeMaxDynamicSharedMemorySize, GEMM_SMEM);
    cudaFuncSetAttribute((const void*)attn_mma_kernel, cudaFuncAttributeMaxDynamicSharedMemorySize, ATT_SMEM);

    float *x, *bq2;
    __half *pf, *xf, *of, *fff, *wqkv, *wo, *w1c, *w2c;
    cudaGetSymbolAddress((void**)&x,    g_x);
    cudaGetSymbolAddress((void**)&bq2,  g_bq2);
    cudaGetSymbolAddress((void**)&pf,   g_pf);
    cudaGetSymbolAddress((void**)&xf,   g_xf);
    cudaGetSymbolAddress((void**)&of,   g_of);
    cudaGetSymbolAddress((void**)&fff,  g_fff);
    cudaGetSymbolAddress((void**)&wqkv, g_wqkv);
    cudaGetSymbolAddress((void**)&wo,   g_wo);
    cudaGetSymbolAddress((void**)&w1c,  g_w1c);
    cudaGetSymbolAddress((void**)&w2c,  g_w2c);

    // all weight conversions + bias packs in ONE launch (grid.y = layer)
    {
        dim3 grid((PREP_TOTAL + 255) / 256, L_);
        prep_kernel<<<grid, 256>>>(qw, kw, vw, qb, kb, vb, ow, w1, w2,
                                   wqkv, bq2, wo, w1c, w2c);
    }

    // src -> fp16 activations
    {
        const int n4 = (MROWS * D_) >> 2;
        cvt_kernel<<<(n4 + 255) / 256, 256>>>(src, xf, n4);
    }

    for (int l = 0; l < L_; l++) {
        const __half* wqkv_l = wqkv + (size_t)l * NQKV * D_;
        const __half* wo_l   = wo   + (size_t)l * D_ * D_;
        const __half* w1_l   = w1c  + (size_t)l * DFF_ * D_;
        const __half* w2_l   = w2c  + (size_t)l * D_ * DFF_;

        // fused QKV projection (Q pre-scaled by 0.125*log2e in epilogue)
        run_gemm<1>(xf, wqkv_l, bq2 + l * NQKV, fff, MROWS, NQKV, D_);

        // banded attention on packed QKV
        {
            dim3 grid(S_ / 128, H_, B_);
            attn_mma_kernel<<<grid, 256, ATT_SMEM>>>(
                fff, fff + D_, fff + 2 * D_, NQKV, of);
        }

        // output projection: split-K=3 fp16 partials, reduced inside add_ln3
        run_gemm_sk(of, wo_l, pf, MROWS, D_, D_);
        const float* res0 = (l == 0) ? src : x;
        add_ln3_kernel<<<MROWS, 256>>>(res0, pf, ob + l * D_, g1 + l * D_, be1 + l * D_, x, xf);

        // FFN
        run_gemm<2>(xf, w1_l, b1 + l * DFF_, fff, MROWS, DFF_, D_);
        run_gemm_sk(fff, w2_l, pf, MROWS, D_, DFF_);
        float* xout = (l == L_ - 1) ? (float*)d_out : x;
        add_ln3_kernel<<<MROWS, 256>>>(x, pf, b2 + l * D_, g2 + l * D_, be2 + l * D_, xout, xf);
    }
}

// round 17
// speedup vs baseline: 1.1874x; 1.0073x over previous
#include <cuda_runtime.h>
#include <cuda_bf16.h>
#include <cuda_fp16.h>
#include <cstdint>

// Problem constants
#define B_ 2
#define S_ 2048
#define D_ 768
#define H_ 12
#define DH_ 64
#define L_ 2
#define DFF_ 3072
#define MROWS (B_ * S_)   // 4096
#define NQKV 2304
#define KSPLIT 3

// ---------------------------------------------------------------------------
// Scratch (static device globals — no allocation allowed)
// ---------------------------------------------------------------------------
__device__ float g_x  [MROWS * D_];
__device__ float g_bq2[L_ * NQKV];
__device__ __half g_pf [KSPLIT * MROWS * D_];  // split-K fp16 partials
__device__ __half g_xf [MROWS * D_];
__device__ __half g_of [MROWS * D_];
__device__ __half g_fff[MROWS * DFF_];         // QKV (M x 2304) / FFN1 (M x 3072)
__device__ __half g_wqkv[L_ * NQKV * D_];
__device__ __half g_wo  [L_ * D_ * D_];
__device__ __half g_w1c [L_ * DFF_ * D_];
__device__ __half g_w2c [L_ * D_ * DFF_];

// ---------------------------------------------------------------------------
// Baseline-PTX tensor-core helpers
// ---------------------------------------------------------------------------
__device__ __forceinline__ uint32_t smem_u32(const void* p) {
    uint32_t a;
    asm("{ .reg .u64 t; cvta.to.shared.u64 t, %1; cvt.u32.u64 %0, t; }"
        : "=r"(a) : "l"(p));
    return a;
}
__device__ __forceinline__ void ldsm_x4(uint32_t& r0, uint32_t& r1,
                                        uint32_t& r2, uint32_t& r3, uint32_t a) {
    asm volatile("ldmatrix.sync.aligned.m8n8.x4.shared.b16 {%0,%1,%2,%3}, [%4];"
                 : "=r"(r0), "=r"(r1), "=r"(r2), "=r"(r3) : "r"(a));
}
__device__ __forceinline__ void ldsm_x4t(uint32_t& r0, uint32_t& r1,
                                         uint32_t& r2, uint32_t& r3, uint32_t a) {
    asm volatile("ldmatrix.sync.aligned.m8n8.x4.trans.shared.b16 {%0,%1,%2,%3}, [%4];"
                 : "=r"(r0), "=r"(r1), "=r"(r2), "=r"(r3) : "r"(a));
}
__device__ __forceinline__ void ldsm_x2(uint32_t& r0, uint32_t& r1, uint32_t a) {
    asm volatile("ldmatrix.sync.aligned.m8n8.x2.shared.b16 {%0,%1}, [%2];"
                 : "=r"(r0), "=r"(r1) : "r"(a));
}
__device__ __forceinline__ void mma_f16(float* d, const uint32_t* a, const uint32_t* b) {
    asm volatile(
        "mma.sync.aligned.m16n8k16.row.col.f32.f16.f16.f32 "
        "{%0,%1,%2,%3}, {%4,%5,%6,%7}, {%8,%9}, {%0,%1,%2,%3};"
        : "+f"(d[0]), "+f"(d[1]), "+f"(d[2]), "+f"(d[3])
        : "r"(a[0]), "r"(a[1]), "r"(a[2]), "r"(a[3]), "r"(b[0]), "r"(b[1]));
}
#define CP16(dst, src) \
    asm volatile("cp.async.cg.shared.global [%0], [%1], 16;" :: "r"(dst), "l"(src))
#define CP_COMMIT() asm volatile("cp.async.commit_group;" ::: "memory")
#define CP_WAIT0()  asm volatile("cp.async.wait_group 0;" ::: "memory")
#define CP_WAIT1()  asm volatile("cp.async.wait_group 1;" ::: "memory")

__device__ __forceinline__ uint32_t packh(float a, float b) {
    __half2 t = __floats2half2_rn(a, b);
    return *(uint32_t*)&t;
}

// ---------------------------------------------------------------------------
// Convert fp32 -> fp16 (single source)
// ---------------------------------------------------------------------------
__global__ __launch_bounds__(256) void cvt_kernel(
    const float* __restrict__ in, __half* __restrict__ out, int n4)
{
    int i = blockIdx.x * blockDim.x + threadIdx.x;
    if (i >= n4) return;
    float4 x = ((const float4*)in)[i];
    __half2* op = (__half2*)out;
    op[2 * i + 0] = __floats2half2_rn(x.x, x.y);
    op[2 * i + 1] = __floats2half2_rn(x.z, x.w);
}

// ---------------------------------------------------------------------------
// Weight prep for ALL layers in one launch (blockIdx.y = layer)
// ---------------------------------------------------------------------------
#define RQ ((D_ * D_) >> 2)
#define RW ((DFF_ * D_) >> 2)
#define PREP_B0 (3 * RQ)
#define PREP_B1 (PREP_B0 + RQ)
#define PREP_B2 (PREP_B1 + RW)
#define PREP_B3 (PREP_B2 + RW)
#define PREP_TOTAL (PREP_B3 + NQKV)

__global__ __launch_bounds__(256) void prep_kernel(
    const float* __restrict__ qw, const float* __restrict__ kw,
    const float* __restrict__ vw, const float* __restrict__ qb,
    const float* __restrict__ kb, const float* __restrict__ vb,
    const float* __restrict__ ow, const float* __restrict__ w1,
    const float* __restrict__ w2,
    __half* __restrict__ wqkv, float* __restrict__ bq,
    __half* __restrict__ wo, __half* __restrict__ w1c, __half* __restrict__ w2c)
{
    const int l = blockIdx.y;
    const int i = blockIdx.x * 256 + threadIdx.x;
    if (i >= PREP_TOTAL) return;

    const float* qwl = qw + (size_t)l * D_ * D_;
    const float* kwl = kw + (size_t)l * D_ * D_;
    const float* vwl = vw + (size_t)l * D_ * D_;
    const float* owl = ow + (size_t)l * D_ * D_;
    const float* w1l = w1 + (size_t)l * DFF_ * D_;
    const float* w2l = w2 + (size_t)l * D_ * DFF_;
    __half* wqkvl = wqkv + (size_t)l * NQKV * D_;
    __half* wol   = wo   + (size_t)l * D_ * D_;
    __half* w1cl  = w1c  + (size_t)l * DFF_ * D_;
    __half* w2cl  = w2c  + (size_t)l * D_ * DFF_;

    if (i >= PREP_B3) {
        const int j = i - PREP_B3;
        float v;
        if (j < D_)          v = qb[l * D_ + j];
        else if (j < 2 * D_) v = kb[l * D_ + j - D_];
        else                 v = vb[l * D_ + j - 2 * D_];
        bq[l * NQKV + j] = v;
        return;
    }
    const float* src;
    __half* dst;
    int j, oj;
    if (i < PREP_B0) {
        oj = i;
        src = (i < RQ) ? qwl : (i < 2 * RQ) ? kwl : vwl;
        j = (i < RQ) ? i : (i < 2 * RQ) ? i - RQ : i - 2 * RQ;
        dst = wqkvl;
    } else if (i < PREP_B1) {
        j = i - PREP_B0; oj = j; src = owl; dst = wol;
    } else if (i < PREP_B2) {
        j = i - PREP_B1; oj = j; src = w1l; dst = w1cl;
    } else {
        j = i - PREP_B2; oj = j; src = w2l; dst = w2cl;
    }
    float4 x = ((const float4*)src)[j];
    __half2* op = (__half2*)dst;
    op[2 * oj + 0] = __floats2half2_rn(x.x, x.y);
    op[2 * oj + 1] = __floats2half2_rn(x.z, x.w);
}

// ---------------------------------------------------------------------------
// fp16 mma.sync GEMM (R9 champion config): C = A[M,K] @ W[N,K]^T (+bias)
// EPI: 1 = fp16 out (+bias, Q cols x 0.125*log2e); 2 = relu + fp16 out (+bias);
//      3 = raw fp16 partial (no bias), at Hf + z*M*N
// ---------------------------------------------------------------------------
#define RS_B 144
#define TILE_B (128 * RS_B)
#define STAGE_B (2 * TILE_B)
#define GEMM_SMEM (2 * STAGE_B)

// 0.125 * log2(e): folds the attention scale and exp->exp2.
#define QSCALE 0.18033688011112042f

template <int EPI>
__global__ __launch_bounds__(256, 2) void gemm_mma_kernel(
    const __half* __restrict__ A, const __half* __restrict__ W,
    const float* __restrict__ bias,
    __half* __restrict__ Hf, int M, int N, int K, int klen)
{
    extern __shared__ char smem[];
    const uint32_t sb = smem_u32(smem);

    const int tid = threadIdx.x;
    const int wid = tid >> 5;
    const int lane = tid & 31;
    const int warp_m = wid >> 2;
    const int warp_n = wid & 3;
    const int bm = blockIdx.y * 128;
    const int bn = blockIdx.x * 128;
    const int kstart = blockIdx.z * klen;

    float acc[4][4][4];
#pragma unroll
    for (int mi = 0; mi < 4; mi++)
#pragma unroll
        for (int ni = 0; ni < 4; ni++)
#pragma unroll
            for (int r = 0; r < 4; r++) acc[mi][ni][r] = 0.f;

    auto load_chunk = [&](int kc, int stage) {
        const uint32_t base = sb + stage * STAGE_B;
#pragma unroll
        for (int t = 0; t < 4; t++) {
            const int idx = tid + t * 256;
            const int lr = idx >> 3, ls = idx & 7;
            CP16(base + lr * RS_B + ls * 16,
                 A + (size_t)(bm + lr) * K + kstart + kc + ls * 8);
        }
#pragma unroll
        for (int t = 0; t < 4; t++) {
            const int idx = tid + t * 256;
            const int lr = idx >> 3, ls = idx & 7;
            CP16(base + TILE_B + lr * RS_B + ls * 16,
                 W + (size_t)(bn + lr) * K + kstart + kc + ls * 8);
        }
    };

    const int arow = warp_m * 64 + (lane & 15);
    const int akb  = (lane >> 4) * 8;
    const int bg_ni = (lane >> 4);
    const int bg_kh = ((lane >> 3) & 1) * 8;
    const int brow_l = lane & 7;

    auto compute = [&](int stage) {
        const uint32_t base = sb + stage * STAGE_B;
        const uint32_t pA = base;
        const uint32_t pB = base + TILE_B;
#pragma unroll
        for (int ks = 0; ks < 4; ks++) {
            const int k0 = ks * 16;
            uint32_t af[4][4], bf[4][2];
#pragma unroll
            for (int mi = 0; mi < 4; mi++) {
                const uint32_t ro = (uint32_t)(arow + mi * 16) * RS_B + (k0 + akb) * 2;
                ldsm_x4(af[mi][0], af[mi][1], af[mi][2], af[mi][3], pA + ro);
            }
#pragma unroll
            for (int np = 0; np < 2; np++) {
                const int nrow = warp_n * 32 + (np * 2 + bg_ni) * 8 + brow_l;
                const uint32_t ro = (uint32_t)nrow * RS_B + (k0 + bg_kh) * 2;
                ldsm_x4(bf[np * 2][0], bf[np * 2][1], bf[np * 2 + 1][0], bf[np * 2 + 1][1], pB + ro);
            }
#pragma unroll
            for (int mi = 0; mi < 4; mi++)
#pragma unroll
                for (int ni = 0; ni < 4; ni++)
                    mma_f16(acc[mi][ni], af[mi], bf[ni]);
        }
    };

    const int nchunks = klen >> 6;
    load_chunk(0, 0);
    CP_COMMIT();

    for (int c = 0; c < nchunks; c++) {
        CP_WAIT0();
        __syncthreads();
        if (c + 1 < nchunks) {
            load_chunk((c + 1) << 6, (c + 1) & 1);
            CP_COMMIT();
        }
        compute(c & 1);
    }

    // epilogue
    __half* Hz = (EPI == 3) ? (Hf + (size_t)blockIdx.z * M * N) : Hf;
#pragma unroll
    for (int mi = 0; mi < 4; mi++) {
        const int m0 = bm + warp_m * 64 + mi * 16 + (lane >> 2);
#pragma unroll
        for (int ni = 0; ni < 4; ni++) {
            const int n0 = bn + warp_n * 32 + ni * 8 + (lane & 3) * 2;
            float v00 = acc[mi][ni][0], v01 = acc[mi][ni][1];
            float v10 = acc[mi][ni][2], v11 = acc[mi][ni][3];
            if (EPI != 3) {
                const float bx = bias[n0], by = bias[n0 + 1];
                v00 += bx; v01 += by; v10 += bx; v11 += by;
            }
            if (EPI == 1) {
                const float sc = (n0 < 768) ? QSCALE : 1.0f;
                v00 *= sc; v01 *= sc; v10 *= sc; v11 *= sc;
            }
            if (EPI == 2) {
                v00 = fmaxf(v00, 0.f); v01 = fmaxf(v01, 0.f);
                v10 = fmaxf(v10, 0.f); v11 = fmaxf(v11, 0.f);
            }
            *(uint32_t*)(Hz + (size_t)m0 * N + n0) = packh(v00, v01);
            *(uint32_t*)(Hz + (size_t)(m0 + 8) * N + n0) = packh(v10, v11);
        }
    }
}

// ---------------------------------------------------------------------------
// Tensor-core banded flash attention: 64-row Q tiles, 4 warps, 128 threads,
// 4 CTAs/SM. 64-key tiles, exp2 softmax, interior fast path, x4 batching.
// Band |i-j| <= 256. Q pre-scaled by 0.125*log2e.
// ---------------------------------------------------------------------------
#define ATT_RSB 144
#define ATT_QROWS 64
#define ATT_QTILE_B (ATT_QROWS * ATT_RSB)   // 9216
#define ATT_KTILE_B (64 * ATT_RSB)          // 9216
#define ATT_SMEM (ATT_QTILE_B + 4 * ATT_KTILE_B)  // 46080

__global__ __launch_bounds__(128, 4) void attn_mma_kernel(
    const __half* __restrict__ Qf, const __half* __restrict__ Kf,
    const __half* __restrict__ Vf, int ldq, __half* __restrict__ Of)
{
    extern __shared__ char smem[];
    const uint32_t sb = smem_u32(smem);
    const int b = blockIdx.z;
    const int h = blockIdx.y;
    const int qt = blockIdx.x;
    const int q0 = qt * ATT_QROWS;
    const int tid = threadIdx.x;
    const int wid = tid >> 5;      // 0..3
    const int lane = tid & 31;
    const int g = lane >> 2;
    const int tq = lane & 3;

    const uint32_t sQ = sb;
    const uint32_t sKV0 = sb + ATT_QTILE_B;

    // stage Q (64 rows x 64 halves): 128 threads, 4 CP16 each
    {
        const int row = tid >> 1, seg0 = (tid & 1) * 4;
#pragma unroll
        for (int t = 0; t < 4; t++) {
            const int seg = seg0 + t;
            const size_t go = (size_t)(b * S_ + q0 + row) * ldq + h * 64 + seg * 8;
            CP16(sQ + (uint32_t)row * ATT_RSB + seg * 16, Qf + go);
        }
    }
    CP_COMMIT();

    const int ktmax = S_ / 64 - 1;
    int kt_lo = (q0 - 256) >> 6; if (kt_lo < 0) kt_lo = 0;
    int kt_hi = (q0 + ATT_QROWS - 1 + 256) >> 6; if (kt_hi > ktmax) kt_hi = ktmax;

    // KV tile load: 64 rows x 8 segs x 2 tensors = 1024 CP16 / 128 thr = 8 each
    auto load_kv = [&](int kt, int stg) {
        const uint32_t base = sKV0 + stg * 2 * ATT_KTILE_B;
        const int row = tid >> 1, seg0 = (tid & 1) * 4;
#pragma unroll
        for (int t = 0; t < 4; t++) {
            const int seg = seg0 + t;
            const size_t go = (size_t)(b * S_ + kt * 64 + row) * ldq + h * 64 + seg * 8;
            const uint32_t so = (uint32_t)row * ATT_RSB + seg * 16;
            CP16(base + so,               Kf + go);
            CP16(base + ATT_KTILE_B + so, Vf + go);
        }
    };
    load_kv(kt_lo, 0);
    CP_COMMIT();

    CP_WAIT1();
    __syncthreads();

    uint32_t qf[4][4];
    {
        const int arow = wid * 16 + (lane & 15);
        const int akb = (lane >> 4) * 8;
#pragma unroll
        for (int ks = 0; ks < 4; ks++) {
            const uint32_t ro = (uint32_t)arow * ATT_RSB + (ks * 16 + akb) * 2;
            ldsm_x4(qf[ks][0], qf[ks][1], qf[ks][2], qf[ks][3], sQ + ro);
        }
    }

    float m0 = -1e30f, m1 = -1e30f, l0 = 0.f, l1 = 0.f;
    float o[8][4];
#pragma unroll
    for (int nd = 0; nd < 8; nd++)
#pragma unroll
        for (int r = 0; r < 4; r++) o[nd][r] = 0.f;

    const int rlo = q0 + wid * 16;
    const int row0 = rlo + g;
    const int brow0 = lane & 7;
    const int bkb = ((lane >> 3) & 1) * 8;
    const int bg_ni = (lane >> 4);
    const int vrow = lane & 15;
    const int vhalf = (lane >> 4);

    for (int kt = kt_lo; kt <= kt_hi; kt++) {
        const int stg = (kt - kt_lo) & 1;
        if (kt < kt_hi) {
            load_kv(kt + 1, stg ^ 1);
            CP_COMMIT();
            CP_WAIT1();
        } else {
            CP_WAIT0();
        }
        __syncthreads();

        const uint32_t base = sKV0 + stg * 2 * ATT_KTILE_B;
        const uint32_t pK = base, pV = base + ATT_KTILE_B;

        const int cbase = kt * 64;
        const bool interior = (cbase >= rlo - 241) && (cbase <= rlo + 193);

        int ntlo, nthi;
        if (interior) { ntlo = 0; nthi = 7; }
        else {
            const int T1 = rlo - 256 - cbase;
            const int T2 = rlo + 15 + 256 - cbase;
            ntlo = (T1 > 0) ? (T1 >> 3) : 0;
            nthi = (T2 < 0) ? -1 : (T2 >> 3);
            if (nthi > 7) nthi = 7;
        }

        if (nthi >= ntlo) {
            float s[8][4];
#pragma unroll
            for (int nt = 0; nt < 8; nt++)
#pragma unroll
                for (int r = 0; r < 4; r++) s[nt][r] = 0.f;

            float rmax0 = -1e30f, rmax1 = -1e30f;

            if (interior) {
#pragma unroll
                for (int ks = 0; ks < 4; ks++) {
#pragma unroll
                    for (int np = 0; np < 4; np++) {
                        uint32_t b0, b1, b2, b3;
                        const int nrow = (np * 2 + bg_ni) * 8 + brow0;
                        const uint32_t ro = (uint32_t)nrow * ATT_RSB + (ks * 16 + bkb) * 2;
                        ldsm_x4(b0, b1, b2, b3, pK + ro);
                        uint32_t bl[2] = {b0, b1};
                        uint32_t bh[2] = {b2, b3};
                        mma_f16(s[np * 2],     qf[ks], bl);
                        mma_f16(s[np * 2 + 1], qf[ks], bh);
                    }
                }
#pragma unroll
                for (int nt = 0; nt < 8; nt++) {
                    rmax0 = fmaxf(rmax0, fmaxf(s[nt][0], s[nt][1]));
                    rmax1 = fmaxf(rmax1, fmaxf(s[nt][2], s[nt][3]));
                }
            } else {
#pragma unroll
                for (int ks = 0; ks < 4; ks++) {
#pragma unroll
                    for (int nt = 0; nt < 8; nt++) {
                        if (nt < ntlo || nt > nthi) continue;
                        uint32_t bk[2];
                        const uint32_t ro = (uint32_t)(nt * 8 + brow0) * ATT_RSB + (ks * 16 + bkb) * 2;
                        ldsm_x2(bk[0], bk[1], pK + ro);
                        mma_f16(s[nt], qf[ks], bk);
                    }
                }
#pragma unroll
                for (int nt = 0; nt < 8; nt++) {
                    if (nt < ntlo || nt > nthi) continue;
                    const int col = cbase + nt * 8 + tq * 2;
                    const bool i00 = (unsigned)(row0 - col + 256) <= 512u;
                    const bool i01 = (unsigned)(row0 - col - 1 + 256) <= 512u;
                    const bool i10 = (unsigned)(row0 + 8 - col + 256) <= 512u;
                    const bool i11 = (unsigned)(row0 + 8 - col - 1 + 256) <= 512u;
                    s[nt][0] = i00 ? s[nt][0] : -1e30f;
                    s[nt][1] = i01 ? s[nt][1] : -1e30f;
                    s[nt][2] = i10 ? s[nt][2] : -1e30f;
                    s[nt][3] = i11 ? s[nt][3] : -1e30f;
                    rmax0 = fmaxf(rmax0, fmaxf(s[nt][0], s[nt][1]));
                    rmax1 = fmaxf(rmax1, fmaxf(s[nt][2], s[nt][3]));
                }
            }
            rmax0 = fmaxf(rmax0, __shfl_xor_sync(0xffffffffu, rmax0, 1));
            rmax0 = fmaxf(rmax0, __shfl_xor_sync(0xffffffffu, rmax0, 2));
            rmax1 = fmaxf(rmax1, __shfl_xor_sync(0xffffffffu, rmax1, 1));
            rmax1 = fmaxf(rmax1, __shfl_xor_sync(0xffffffffu, rmax1, 2));

            const float nm0 = fmaxf(m0, rmax0);
            const float nm1 = fmaxf(m1, rmax1);
            const float c0 = exp2f(m0 - nm0);
            const float c1 = exp2f(m1 - nm1);
            m0 = nm0; m1 = nm1;

            float add0 = 0.f, add1 = 0.f;
            uint32_t p[8][2];
            if (interior) {
#pragma unroll
                for (int nt = 0; nt < 8; nt++) {
                    const float p00 = exp2f(s[nt][0] - nm0);
                    const float p01 = exp2f(s[nt][1] - nm0);
                    const float p10 = exp2f(s[nt][2] - nm1);
                    const float p11 = exp2f(s[nt][3] - nm1);
                    add0 += p00 + p01;
                    add1 += p10 + p11;
                    p[nt][0] = packh(p00, p01);
                    p[nt][1] = packh(p10, p11);
                }
            } else {
#pragma unroll
                for (int nt = 0; nt < 8; nt++) {
                    if (nt < ntlo || nt > nthi) { p[nt][0] = 0; p[nt][1] = 0; continue; }
                    const float p00 = exp2f(s[nt][0] - nm0);
                    const float p01 = exp2f(s[nt][1] - nm0);
                    const float p10 = exp2f(s[nt][2] - nm1);
                    const float p11 = exp2f(s[nt][3] - nm1);
                    add0 += p00 + p01;
                    add1 += p10 + p11;
                    p[nt][0] = packh(p00, p01);
                    p[nt][1] = packh(p10, p11);
                }
            }
            add0 += __shfl_xor_sync(0xffffffffu, add0, 1);
            add0 += __shfl_xor_sync(0xffffffffu, add0, 2);
            add1 += __shfl_xor_sync(0xffffffffu, add1, 1);
            add1 += __shfl_xor_sync(0xffffffffu, add1, 2);
            l0 = l0 * c0 + add0;
            l1 = l1 * c1 + add1;
#pragma unroll
            for (int nd = 0; nd < 8; nd++) {
                o[nd][0] *= c0; o[nd][1] *= c0;
                o[nd][2] *= c1; o[nd][3] *= c1;
            }

            // O += P · V  (x4.trans batched V loads)
#pragma unroll
            for (int ks = 0; ks < 4; ks++) {
                if (!interior && (2 * ks + 1 < ntlo || 2 * ks > nthi)) continue;
                uint32_t a[4] = {p[2 * ks][0], p[2 * ks][1], p[2 * ks + 1][0], p[2 * ks + 1][1]};
#pragma unroll
                for (int ndp = 0; ndp < 4; ndp++) {
                    uint32_t b0, b1, b2, b3;
                    const uint32_t ro = (uint32_t)(ks * 16 + vrow) * ATT_RSB
                                      + (2 * ndp + vhalf) * 16;
                    ldsm_x4t(b0, b1, b2, b3, pV + ro);
                    uint32_t bl[2] = {b0, b1};
                    uint32_t bh[2] = {b2, b3};
                    mma_f16(o[2 * ndp],     a, bl);
                    mma_f16(o[2 * ndp + 1], a, bh);
                }
            }
        }
        __syncthreads();
    }

    const float inv0 = 1.f / l0;
    const float inv1 = 1.f / l1;
#pragma unroll
    for (int nd = 0; nd < 8; nd++) {
        const int d = nd * 8 + tq * 2;
        const size_t o0 = (size_t)(b * S_ + row0) * D_ + h * 64 + d;
        const size_t o1 = (size_t)(b * S_ + row0 + 8) * D_ + h * 64 + d;
        *(uint32_t*)(Of + o0) = packh(o[nd][0] * inv0, o[nd][1] * inv0);
        *(uint32_t*)(Of + o1) = packh(o[nd][2] * inv1, o[nd][3] * inv1);
    }
}

// ---------------------------------------------------------------------------
// Fused split-K reduce (fp16 partials) + bias + residual add + LayerNorm.
// ---------------------------------------------------------------------------
__global__ __launch_bounds__(256) void add_ln3_kernel(
    const float* __restrict__ res, const __half* __restrict__ parts,
    const float* __restrict__ bias,
    const float* __restrict__ g, const float* __restrict__ be,
    float* __restrict__ xout, __half* __restrict__ xf)
{
    const int row = blockIdx.x;
    const int tid = threadIdx.x;
    const float* xp = res + (size_t)row * D_;
    const __half* p0 = parts + (size_t)row * D_;
    const __half* p1 = parts + (size_t)MROWS * D_ + (size_t)row * D_;
    const __half* p2 = parts + 2 * (size_t)MROWS * D_ + (size_t)row * D_;

    float v[3];
    float s1 = 0.f, s2 = 0.f;
#pragma unroll
    for (int i = 0; i < 3; i++) {
        const int c = tid + 256 * i;
        const float ps = (__half2float(p0[c]) + __half2float(p1[c])) + __half2float(p2[c]);
        v[i] = xp[c] + ps + bias[c];
        s1 += v[i];
        s2 += v[i] * v[i];
    }
#pragma unroll
    for (int off = 16; off; off >>= 1) {
        s1 += __shfl_xor_sync(0xffffffffu, s1, off);
        s2 += __shfl_xor_sync(0xffffffffu, s2, off);
    }
    __shared__ float r1[8], r2[8];
    if ((tid & 31) == 0) { r1[tid >> 5] = s1; r2[tid >> 5] = s2; }
    __syncthreads();
    s1 = 0.f; s2 = 0.f;
#pragma unroll
    for (int i = 0; i < 8; i++) { s1 += r1[i]; s2 += r2[i]; }

    const float mean = s1 * (1.f / 768.f);
    const float var  = s2 * (1.f / 768.f) - mean * mean;
    const float rstd = rsqrtf(var + 1e-5f);
#pragma unroll
    for (int i = 0; i < 3; i++) {
        const int c = tid + 256 * i;
        const float val = (v[i] - mean) * rstd * g[c] + be[c];
        xout[(size_t)row * D_ + c] = val;
        xf[(size_t)row * D_ + c] = __float2half_rn(val);
    }
}

// ---------------------------------------------------------------------------
// Host orchestration
// ---------------------------------------------------------------------------
template <int EPI>
static void run_gemm(const __half* A, const __half* W, const float* bias,
                     __half* Hf, int M, int N, int K)
{
    dim3 grid(N / 128, M / 128, 1);
    gemm_mma_kernel<EPI><<<grid, 256, GEMM_SMEM>>>(A, W, bias, Hf, M, N, K, K);
}

static void run_gemm_sk(const __half* A, const __half* W, __half* Pf,
                        int M, int N, int K)
{
    dim3 grid(N / 128, M / 128, KSPLIT);
    gemm_mma_kernel<3><<<grid, 256, GEMM_SMEM>>>(A, W, nullptr, Pf,
                                                 M, N, K, K / KSPLIT);
}

extern "C" void kernel_launch(void* const* d_in, const int* in_sizes, int n_in,
                              void* d_out, int out_size)
{
    const float* src = (const float*)d_in[0];
    const float* qw  = (const float*)d_in[1];
    const float* qb  = (const float*)d_in[2];
    const float* kw  = (const float*)d_in[3];
    const float* kb  = (const float*)d_in[4];
    const float* vw  = (const float*)d_in[5];
    const float* vb  = (const float*)d_in[6];
    const float* ow  = (const float*)d_in[7];
    const float* ob  = (const float*)d_in[8];
    const float* w1  = (const float*)d_in[9];
    const float* b1  = (const float*)d_in[10];
    const float* w2  = (const float*)d_in[11];
    const float* b2  = (const float*)d_in[12];
    const float* g1  = (const float*)d_in[13];
    const float* be1 = (const float*)d_in[14];
    const float* g2  = (const float*)d_in[15];
    const float* be2 = (const float*)d_in[16];

    cudaFuncSetAttribute((const void*)gemm_mma_kernel<1>, cudaFuncAttributeMaxDynamicSharedMemorySize, GEMM_SMEM);
    cudaFuncSetAttribute((const void*)gemm_mma_kernel<2>, cudaFuncAttributeMaxDynamicSharedMemorySize, GEMM_SMEM);
    cudaFuncSetAttribute((const void*)gemm_mma_kernel<3>, cudaFuncAttributeMaxDynamicSharedMemorySize, GEMM_SMEM);
    cudaFuncSetAttribute((const void*)attn_mma_kernel, cudaFuncAttributeMaxDynamicSharedMemorySize, ATT_SMEM);

    float *x, *bq2;
    __half *pf, *xf, *of, *fff, *wqkv, *wo, *w1c, *w2c;
    cudaGetSymbolAddress((void**)&x,    g_x);
    cudaGetSymbolAddress((void**)&bq2,  g_bq2);
    cudaGetSymbolAddress((void**)&pf,   g_pf);
    cudaGetSymbolAddress((void**)&xf,   g_xf);
    cudaGetSymbolAddress((void**)&of,   g_of);
    cudaGetSymbolAddress((void**)&fff,  g_fff);
    cudaGetSymbolAddress((void**)&wqkv, g_wqkv);
    cudaGetSymbolAddress((void**)&wo,   g_wo);
    cudaGetSymbolAddress((void**)&w1c,  g_w1c);
    cudaGetSymbolAddress((void**)&w2c,  g_w2c);

    // all weight conversions + bias packs in ONE launch (grid.y = layer)
    {
        dim3 grid((PREP_TOTAL + 255) / 256, L_);
        prep_kernel<<<grid, 256>>>(qw, kw, vw, qb, kb, vb, ow, w1, w2,
                                   wqkv, bq2, wo, w1c, w2c);
    }

    // src -> fp16 activations
    {
        const int n4 = (MROWS * D_) >> 2;
        cvt_kernel<<<(n4 + 255) / 256, 256>>>(src, xf, n4);
    }

    for (int l = 0; l < L_; l++) {
        const __half* wqkv_l = wqkv + (size_t)l * NQKV * D_;
        const __half* wo_l   = wo   + (size_t)l * D_ * D_;
        const __half* w1_l   = w1c  + (size_t)l * DFF_ * D_;
        const __half* w2_l   = w2c  + (size_t)l * D_ * DFF_;

        // fused QKV projection (Q pre-scaled by 0.125*log2e in epilogue)
        run_gemm<1>(xf, wqkv_l, bq2 + l * NQKV, fff, MROWS, NQKV, D_);

        // banded attention on packed QKV (64-row CTAs, 4 CTAs/SM)
        {
            dim3 grid(S_ / ATT_QROWS, H_, B_);
            attn_mma_kernel<<<grid, 128, ATT_SMEM>>>(
                fff, fff + D_, fff + 2 * D_, NQKV, of);
        }

        // output projection: split-K=3 fp16 partials, reduced inside add_ln3
        run_gemm_sk(of, wo_l, pf, MROWS, D_, D_);
        const float* res0 = (l == 0) ? src : x;
        add_ln3_kernel<<<MROWS, 256>>>(res0, pf, ob + l * D_, g1 + l * D_, be1 + l * D_, x, xf);

        // FFN
        run_gemm<2>(xf, w1_l, b1 + l * DFF_, fff, MROWS, DFF_, D_);
        run_gemm_sk(fff, w2_l, pf, MROWS, D_, DFF_);
        float* xout = (l == L_ - 1) ? (float*)d_out : x;
        add_ln3_kernel<<<MROWS, 256>>>(x, pf, b2 + l * D_, g2 + l * D_, be2 + l * D_, xout, xf);
    }
}